// round 12
// baseline (speedup 1.0000x reference)
#include <cuda_runtime.h>
#include <cuda_bf16.h>
#include <cuda_fp16.h>
#include <cstdint>

#define BB 2
#define CC 1024
#define TT 2048
#define HH 16
#define DH 64
#define LN_EPS 1e-6f
#define LOG2E 1.44269504088896340736f

// ---- dense GEMM tiling (KC=32, 2-stage, 2 CTAs/SM) ----
#define GM_MT 128
#define GM_NT 128
#define GM_KC 32
#define NCHUNK (CC / GM_KC)            // 32
#define PITCH 40
#define A_BYTES (GM_MT * PITCH * 2)     // 10240
#define B_BYTES (GM_NT * PITCH * 2)     // 10240
#define STAGE0_BYTES (2 * A_BYTES + 2 * B_BYTES)  // 40960
#define GEMM_SMEM0 (2 * STAGE0_BYTES)             // 81920
#define STAGE2_BYTES (2 * A_BYTES + B_BYTES)      // 30720
#define GEMM_SMEM2 (2 * STAGE2_BYTES)             // 61440

// ---- attention: 512 threads, 2 kt-groups x 8 warps, 2 stages per group ----
#define QPITCH 72
#define KT 64
#define NKT (TT / KT)                   // 32 tiles, 16 per group
#define AQ_B (128 * QPITCH * 2)         // 18432
#define AK_B (KT * QPITCH * 2)          // 9216
#define ASTAGE_B (3 * AK_B)             // 27648 (K hi/lo + V single)
#define ATTN_SMEM (2 * AQ_B + 4 * ASTAGE_B)      // 147456
#define MERGE_OFF (2 * AQ_B + 2 * ASTAGE_B)      // group-B buffer region, 55296B

// ---- scratch ----
__device__ float g_y[(size_t)BB * CC * TT];
__device__ float g_lnsum[(size_t)BB * TT];
__device__ float g_lnsq[(size_t)BB * TT];
__device__ __nv_bfloat16 g_wqk_hi[2 * CC * CC], g_wqk_lo[2 * CC * CC];
__device__ __half g_wv_hi[CC * CC], g_wv_lo[CC * CC];
__device__ __half g_wfc_hi[CC * CC], g_wfc_lo[CC * CC];
__device__ __nv_bfloat16 g_xT_hi[(size_t)BB * TT * CC], g_xT_lo[(size_t)BB * TT * CC];
__device__ __half g_xT_h16[(size_t)BB * TT * CC];
__device__ __half g_cT[(size_t)BB * TT * CC];
__device__ __nv_bfloat16 g_qT_hi[(size_t)BB * HH * TT * DH], g_qT_lo[(size_t)BB * HH * TT * DH];
__device__ __nv_bfloat16 g_kT_hi[(size_t)BB * HH * TT * DH], g_kT_lo[(size_t)BB * HH * TT * DH];
__device__ __half g_v[(size_t)BB * HH * DH * TT];

// ===========================================================================
__device__ __forceinline__ uint32_t smem_u32(const void* p) {
    return (uint32_t)__cvta_generic_to_shared(p);
}
__device__ __forceinline__ void cp16(uint32_t dst, const void* src) {
    asm volatile("cp.async.cg.shared.global [%0], [%1], 16;\n" :: "r"(dst), "l"(src));
}
__device__ __forceinline__ void cp_commit() {
    asm volatile("cp.async.commit_group;\n" ::: "memory");
}
__device__ __forceinline__ void bar_named(int id, int cnt) {
    asm volatile("bar.sync %0, %1;" :: "r"(id), "r"(cnt) : "memory");
}
__device__ __forceinline__ void ldmatrix_x4(uint32_t& a0, uint32_t& a1, uint32_t& a2,
                                            uint32_t& a3, uint32_t addr) {
    asm volatile("ldmatrix.sync.aligned.m8n8.x4.shared.b16 {%0,%1,%2,%3}, [%4];"
                 : "=r"(a0), "=r"(a1), "=r"(a2), "=r"(a3) : "r"(addr));
}
__device__ __forceinline__ void mma_bf16(float* c,
                                         uint32_t a0, uint32_t a1, uint32_t a2, uint32_t a3,
                                         uint32_t b0, uint32_t b1) {
    asm volatile(
        "mma.sync.aligned.m16n8k16.row.col.f32.bf16.bf16.f32 "
        "{%0,%1,%2,%3}, {%4,%5,%6,%7}, {%8,%9}, {%0,%1,%2,%3};"
        : "+f"(c[0]), "+f"(c[1]), "+f"(c[2]), "+f"(c[3])
        : "r"(a0), "r"(a1), "r"(a2), "r"(a3), "r"(b0), "r"(b1));
}
__device__ __forceinline__ void mma_f16(float* c,
                                        uint32_t a0, uint32_t a1, uint32_t a2, uint32_t a3,
                                        uint32_t b0, uint32_t b1) {
    asm volatile(
        "mma.sync.aligned.m16n8k16.row.col.f32.f16.f16.f32 "
        "{%0,%1,%2,%3}, {%4,%5,%6,%7}, {%8,%9}, {%0,%1,%2,%3};"
        : "+f"(c[0]), "+f"(c[1]), "+f"(c[2]), "+f"(c[3])
        : "r"(a0), "r"(a1), "r"(a2), "r"(a3), "r"(b0), "r"(b1));
}
__device__ __forceinline__ uint32_t cvt2(float f0, float f1) {  // bf16x2
    uint32_t r;
    asm("cvt.rn.bf16x2.f32 %0, %1, %2;" : "=r"(r) : "f"(f1), "f"(f0));
    return r;
}
__device__ __forceinline__ void split2(float f0, float f1, uint32_t& hi, uint32_t& lo) {
    hi = cvt2(f0, f1);
    const float h0 = __uint_as_float(hi << 16);
    const float h1 = __uint_as_float(hi & 0xffff0000u);
    lo = cvt2(f0 - h0, f1 - h1);
}
__device__ __forceinline__ uint32_t cvt2h(float f0, float f1) {  // f16x2
    uint32_t r;
    asm("cvt.rn.f16x2.f32 %0, %1, %2;" : "=r"(r) : "f"(f1), "f"(f0));
    return r;
}

// ===========================================================================
// conversions
// ===========================================================================
__global__ void __launch_bounds__(256) split_kernel(
    const float* __restrict__ in, __nv_bfloat16* __restrict__ hi,
    __nv_bfloat16* __restrict__ lo, int n)
{
    int i = blockIdx.x * 256 + threadIdx.x;
    if (i < n) {
        const float v = in[i];
        const __nv_bfloat16 h = __float2bfloat16(v);
        hi[i] = h;
        lo[i] = __float2bfloat16(v - __bfloat162float(h));
    }
}

__global__ void __launch_bounds__(256) splith_kernel(
    const float* __restrict__ in, __half* __restrict__ hi,
    __half* __restrict__ lo, int n)
{
    int i = blockIdx.x * 256 + threadIdx.x;
    if (i < n) {
        const float v = in[i];
        const __half h = __float2half_rn(v);
        hi[i] = h;
        lo[i] = __float2half_rn(v - __half2float(h));
    }
}

__global__ void __launch_bounds__(256) lnzero_kernel()
{
    int i = blockIdx.x * 256 + threadIdx.x;
    if (i < BB * TT) { g_lnsum[i] = 0.0f; g_lnsq[i] = 0.0f; }
}

__global__ void __launch_bounds__(256) tsplit_kernel(
    const float* __restrict__ in, __nv_bfloat16* __restrict__ hi,
    __nv_bfloat16* __restrict__ lo, __half* __restrict__ h16)
{
    __shared__ float tile[32][33];
    const int b = blockIdx.z;
    const int t0 = blockIdx.x * 32, c0 = blockIdx.y * 32;
    const float* ib = in + (size_t)b * CC * TT;
    for (int j = threadIdx.y; j < 32; j += 8)
        tile[j][threadIdx.x] = ib[(size_t)(c0 + j) * TT + t0 + threadIdx.x];
    __syncthreads();
    __nv_bfloat16* hb = hi + (size_t)b * TT * CC;
    __nv_bfloat16* lb = lo + (size_t)b * TT * CC;
    __half* sb = h16 + (size_t)b * TT * CC;
    for (int j = threadIdx.y; j < 32; j += 8) {
        const float v = tile[threadIdx.x][j];
        const __nv_bfloat16 h = __float2bfloat16(v);
        const size_t o = (size_t)(t0 + j) * CC + c0 + threadIdx.x;
        hb[o] = h;
        lb[o] = __float2bfloat16(v - __bfloat162float(h));
        sb[o] = __float2half_rn(v);
    }
}

// ===========================================================================
// mma.sync split GEMM (unchanged from round 11)
// ===========================================================================
template <int MODE>
__device__ __forceinline__ void g_load_stage(
    uint32_t st, int kc,
    const uint16_t* __restrict__ Ahi, const uint16_t* __restrict__ Alo,
    const uint16_t* __restrict__ Bhi, const uint16_t* __restrict__ Blo,
    int m0, int n0, int tid)
{
    for (int i = tid; i < GM_MT * 4; i += 256) {
        const int r = i >> 2, c = i & 3;
        const uint32_t dst = st + (uint32_t)(r * PITCH + c * 8) * 2;
        const size_t g = (size_t)(m0 + r) * CC + kc + c * 8;
        cp16(dst, Ahi + g);
        cp16(dst + A_BYTES, Alo + g);
    }
    for (int i = tid; i < GM_NT * 4; i += 256) {
        const int r = i >> 2, c = i & 3;
        const uint32_t dst = st + 2 * A_BYTES + (uint32_t)(r * PITCH + c * 8) * 2;
        const size_t g = (size_t)(n0 + r) * CC + kc + c * 8;
        cp16(dst, Bhi + g);
        if (MODE == 0) cp16(dst + B_BYTES, Blo + g);
    }
    cp_commit();
}

template <int EPI, int MODE>
__global__ void __launch_bounds__(256) hgemm(
    const uint16_t* __restrict__ Ahi, const uint16_t* __restrict__ Alo,
    const uint16_t* __restrict__ BhiAll, const uint16_t* __restrict__ BloAll,
    const float* __restrict__ Res, float* __restrict__ Cout, long outBatchStride)
{
    extern __shared__ char smem[];
    const uint32_t sbase = smem_u32(smem);
    const uint32_t stageB = (MODE == 0) ? STAGE0_BYTES : STAGE2_BYTES;

    const int tid = threadIdx.x;
    const int wid = tid >> 5;
    const int lane = tid & 31;
    const int b = blockIdx.z;
    const int m0 = blockIdx.y * GM_MT;
    const int n0 = blockIdx.x * GM_NT;
    const int wm = (wid >> 2) * 64;
    const int wn = (wid & 3) * 32;

    const uint16_t* Bhi = BhiAll + (size_t)b * TT * CC;
    const uint16_t* Blo = (MODE == 0) ? (BloAll + (size_t)b * TT * CC) : nullptr;

    float acc[4][4][4];
#pragma unroll
    for (int i = 0; i < 4; i++)
#pragma unroll
        for (int j = 0; j < 4; j++)
#pragma unroll
            for (int r = 0; r < 4; r++) acc[i][j][r] = 0.0f;

    const int a_row = lane & 15;
    const int a_ksel = (lane >> 4) * 8;
    const int b4_row = lane & 7;
    const int b4_k = ((lane >> 3) & 1) * 8;
    const int b4_n = ((lane >> 4) & 1) * 8;

    g_load_stage<MODE>(sbase, 0, Ahi, Alo, Bhi, Blo, m0, n0, tid);

    for (int c = 0; c < NCHUNK; c++) {
        const uint32_t st = sbase + (uint32_t)(c & 1) * stageB;
        if (c + 1 < NCHUNK) {
            g_load_stage<MODE>(sbase + (uint32_t)((c + 1) & 1) * stageB,
                               (c + 1) * GM_KC, Ahi, Alo, Bhi, Blo, m0, n0, tid);
            asm volatile("cp.async.wait_group 1;\n" ::: "memory");
        } else {
            asm volatile("cp.async.wait_group 0;\n" ::: "memory");
        }
        __syncthreads();

        const uint32_t sAh = st;
        const uint32_t sAl = st + A_BYTES;
        const uint32_t sBh = st + 2 * A_BYTES;
        const uint32_t sBl = sBh + B_BYTES;

#pragma unroll
        for (int kk = 0; kk < GM_KC; kk += 16) {
            uint32_t ah[4][4], al[4][4], bh[4][2], bl[4][2];
#pragma unroll
            for (int mi = 0; mi < 4; mi++) {
                const uint32_t off =
                    (uint32_t)((wm + mi * 16 + a_row) * PITCH + kk + a_ksel) * 2;
                ldmatrix_x4(ah[mi][0], ah[mi][1], ah[mi][2], ah[mi][3], sAh + off);
                ldmatrix_x4(al[mi][0], al[mi][1], al[mi][2], al[mi][3], sAl + off);
            }
#pragma unroll
            for (int p = 0; p < 2; p++) {
                const uint32_t off =
                    (uint32_t)((wn + p * 16 + b4_n + b4_row) * PITCH + kk + b4_k) * 2;
                ldmatrix_x4(bh[2 * p][0], bh[2 * p][1], bh[2 * p + 1][0],
                            bh[2 * p + 1][1], sBh + off);
                if (MODE == 0)
                    ldmatrix_x4(bl[2 * p][0], bl[2 * p][1], bl[2 * p + 1][0],
                                bl[2 * p + 1][1], sBl + off);
            }
#pragma unroll
            for (int mi = 0; mi < 4; mi++)
#pragma unroll
                for (int nj = 0; nj < 4; nj++) {
                    float* a = acc[mi][nj];
                    if (MODE == 0) {
                        mma_bf16(a, ah[mi][0], ah[mi][1], ah[mi][2], ah[mi][3],
                                 bh[nj][0], bh[nj][1]);
                        mma_bf16(a, ah[mi][0], ah[mi][1], ah[mi][2], ah[mi][3],
                                 bl[nj][0], bl[nj][1]);
                        mma_bf16(a, al[mi][0], al[mi][1], al[mi][2], al[mi][3],
                                 bh[nj][0], bh[nj][1]);
                    } else {
                        mma_f16(a, ah[mi][0], ah[mi][1], ah[mi][2], ah[mi][3],
                                bh[nj][0], bh[nj][1]);
                        mma_f16(a, al[mi][0], al[mi][1], al[mi][2], al[mi][3],
                                bh[nj][0], bh[nj][1]);
                    }
                }
        }
        __syncthreads();
    }

    const int er = lane >> 2;
    const int ec = (lane & 3) * 2;

    if (EPI == 1) {
        float* lns = (float*)smem;
        float* lnq = lns + 128;
        if (tid < 128) { lns[tid] = 0.0f; lnq[tid] = 0.0f; }
        __syncthreads();

        float cs[8], cq[8];
#pragma unroll
        for (int i = 0; i < 8; i++) { cs[i] = 0.0f; cq[i] = 0.0f; }

        float* Cb = Cout + (size_t)b * outBatchStride;
        const float* Rb = Res + (size_t)b * CC * TT;
#pragma unroll
        for (int mi = 0; mi < 4; mi++)
#pragma unroll
            for (int nj = 0; nj < 4; nj++) {
                const int m = m0 + wm + mi * 16 + er;
                const int n = n0 + wn + nj * 8 + ec;
                float2 v0 = make_float2(acc[mi][nj][0], acc[mi][nj][1]);
                float2 v1 = make_float2(acc[mi][nj][2], acc[mi][nj][3]);
                const float2 r0 = *(const float2*)(Rb + (size_t)m * TT + n);
                const float2 r1 = *(const float2*)(Rb + (size_t)(m + 8) * TT + n);
                v0.x += r0.x; v0.y += r0.y;
                v1.x += r1.x; v1.y += r1.y;
                *(float2*)(Cb + (size_t)m * TT + n) = v0;
                *(float2*)(Cb + (size_t)(m + 8) * TT + n) = v1;
                cs[nj * 2 + 0] += v0.x + v1.x;
                cq[nj * 2 + 0] += v0.x * v0.x + v1.x * v1.x;
                cs[nj * 2 + 1] += v0.y + v1.y;
                cq[nj * 2 + 1] += v0.y * v0.y + v1.y * v1.y;
            }
#pragma unroll
        for (int ci = 0; ci < 8; ci++) {
            const int col = wn + (ci >> 1) * 8 + ec + (ci & 1);
            atomicAdd(&lns[col], cs[ci]);
            atomicAdd(&lnq[col], cq[ci]);
        }
        __syncthreads();
        if (tid < 128) {
            atomicAdd(&g_lnsum[(size_t)b * TT + n0 + tid], lns[tid]);
            atomicAdd(&g_lnsq[(size_t)b * TT + n0 + tid], lnq[tid]);
        }
    } else if (EPI == 3) {
        uint32_t* vv = (uint32_t*)g_v;
#pragma unroll
        for (int mi = 0; mi < 4; mi++)
#pragma unroll
            for (int nj = 0; nj < 4; nj++) {
                const int n = n0 + wn + nj * 8 + ec;
#pragma unroll
                for (int rr = 0; rr < 2; rr++) {
                    const int ch = m0 + wm + mi * 16 + er + rr * 8;
                    const int bh = b * HH + (ch >> 6);
                    const int d = ch & 63;
                    vv[(((size_t)bh * DH + d) * TT + n) >> 1] =
                        cvt2h(acc[mi][nj][2 * rr], acc[mi][nj][2 * rr + 1]);
                }
            }
    } else {
        const bool isK = (m0 >= CC);
        const float qscale = isK ? 1.0f : LOG2E;
        const int chBase = isK ? (m0 - CC) : m0;
        const int h0 = chBase >> 6;
        float* stg = (float*)smem;
#pragma unroll
        for (int mi = 0; mi < 4; mi++)
#pragma unroll
            for (int nj = 0; nj < 4; nj++) {
                const int m = wm + mi * 16 + er;
                const int n = wn + nj * 8 + ec;
                stg[n * 129 + m] = acc[mi][nj][0];
                stg[(n + 1) * 129 + m] = acc[mi][nj][1];
                stg[n * 129 + m + 8] = acc[mi][nj][2];
                stg[(n + 1) * 129 + m + 8] = acc[mi][nj][3];
            }
        __syncthreads();
        uint32_t* dh = (uint32_t*)(isK ? g_kT_hi : g_qT_hi);
        uint32_t* dl = (uint32_t*)(isK ? g_kT_lo : g_qT_lo);
#pragma unroll
        for (int i = 0; i < 16; i++) {
            const int t = wid * 16 + i;
            const float* row = stg + t * 129;
#pragma unroll
            for (int half = 0; half < 2; half++) {
                const float v0 = row[half * 64 + 2 * lane] * qscale;
                const float v1 = row[half * 64 + 2 * lane + 1] * qscale;
                uint32_t hi, lo;
                split2(v0, v1, hi, lo);
                const size_t idx =
                    ((size_t)(b * HH + h0 + half) * TT + n0 + t) * 32 + lane;
                dh[idx] = hi;
                dl[idx] = lo;
            }
        }
    }
}

// ===========================================================================
// Split-KT warp-specialized flash attention: 512 threads, two 8-warp groups.
// Group g processes kt tiles {g, g+2, ...} with private stages + named bars.
// Flash-decoding merge at the end. QK bf16 3-term, exp2 softmax, PV fp16.
// ===========================================================================
__device__ __forceinline__ void attn_load_stage2(uint32_t st, int bh, int k0, int gtid)
{
    const __nv_bfloat16* kh = g_kT_hi + ((size_t)bh * TT + k0) * DH;
    const __nv_bfloat16* kl = g_kT_lo + ((size_t)bh * TT + k0) * DH;
    for (int i = gtid; i < KT * 8; i += 256) {
        const int r = i >> 3, c = i & 7;
        const uint32_t d = st + (uint32_t)(r * QPITCH + c * 8) * 2;
        cp16(d, kh + (size_t)r * DH + c * 8);
        cp16(d + AK_B, kl + (size_t)r * DH + c * 8);
    }
    const __half* vp = g_v + (size_t)bh * DH * TT + k0;
    for (int i = gtid; i < 64 * (KT / 8); i += 256) {
        const int r = i >> 3, c = i & 7;
        const uint32_t d = st + 2 * AK_B + (uint32_t)(r * QPITCH + c * 8) * 2;
        cp16(d, vp + (size_t)r * TT + c * 8);
    }
}

__global__ void __launch_bounds__(512, 1) attn_mma()
{
    extern __shared__ char smem[];
    const uint32_t sb = smem_u32(smem);
    const uint32_t sQh = sb, sQl = sb + AQ_B;
    const uint32_t stage0 = sb + 2 * AQ_B;

    const int tid = threadIdx.x;
    const int g = tid >> 8;          // group 0 / 1
    const int gtid = tid & 255;
    const int wq = (tid >> 5) & 7;   // q-row block within group
    const int lane = tid & 31;
    const int b = blockIdx.z, h = blockIdx.y;
    const int bh = b * HH + h;
    const int q0 = blockIdx.x * 128;
    const uint32_t gstage = stage0 + (uint32_t)g * 2 * ASTAGE_B;

    // prologue: all threads load Q; group loads its first two tiles
    {
        const __nv_bfloat16* qh = g_qT_hi + ((size_t)bh * TT + q0) * DH;
        const __nv_bfloat16* ql = g_qT_lo + ((size_t)bh * TT + q0) * DH;
        for (int i = tid; i < 128 * 8; i += 512) {
            const int r = i >> 3, c = i & 7;
            const uint32_t d = sQh + (uint32_t)(r * QPITCH + c * 8) * 2;
            cp16(d, qh + (size_t)r * DH + c * 8);
            cp16(d + AQ_B, ql + (size_t)r * DH + c * 8);
        }
        attn_load_stage2(gstage, bh, g * KT, gtid);            // local tile 0
        cp_commit();                                            // commit #1 (Q + t0)
        attn_load_stage2(gstage + ASTAGE_B, bh, (2 + g) * KT, gtid);  // local tile 1
        cp_commit();                                            // commit #2
    }
    asm volatile("cp.async.wait_group 1;\n" ::: "memory");      // Q + tile0 done
    __syncthreads();                                            // Q visible CTA-wide

    const int a_row = lane & 15;
    const int a_ksel = (lane >> 4) * 8;
    const int b4_row = lane & 7;
    const int b4_k = ((lane >> 3) & 1) * 8;
    const int b4_n = ((lane >> 4) & 1) * 8;
    const int barid = 1 + g;

    uint32_t qfh[4][4], qfl[4][4];
#pragma unroll
    for (int ks = 0; ks < 4; ks++) {
        const uint32_t off =
            (uint32_t)((wq * 16 + a_row) * QPITCH + ks * 16 + a_ksel) * 2;
        ldmatrix_x4(qfh[ks][0], qfh[ks][1], qfh[ks][2], qfh[ks][3], sQh + off);
        ldmatrix_x4(qfl[ks][0], qfl[ks][1], qfl[ks][2], qfl[ks][3], sQl + off);
    }

    float O[8][4];
    float m0 = -__int_as_float(0x7f800000), m1 = m0;
    float l0 = 0.0f, l1 = 0.0f;
#pragma unroll
    for (int d = 0; d < 8; d++)
#pragma unroll
        for (int r = 0; r < 4; r++) O[d][r] = 0.0f;

    for (int i = 0; i < NKT / 2; i++) {
        const uint32_t stb = gstage + (uint32_t)(i & 1) * ASTAGE_B;
        // commits issued so far (group): 2 + i; tile i = commit #(i+1)
        asm volatile("cp.async.wait_group 1;\n" ::: "memory");
        bar_named(barid, 256);

        float S[8][4];
#pragma unroll
        for (int n = 0; n < 8; n++)
#pragma unroll
            for (int r = 0; r < 4; r++) S[n][r] = 0.0f;

        const uint32_t Kh = stb, Kl = stb + AK_B;
#pragma unroll
        for (int np = 0; np < 4; np++) {
#pragma unroll
            for (int ks = 0; ks < 4; ks++) {
                const uint32_t off =
                    (uint32_t)((np * 16 + b4_n + b4_row) * QPITCH + ks * 16 + b4_k) * 2;
                uint32_t kh0, kh1, kh2, kh3, kl0, kl1, kl2, kl3;
                ldmatrix_x4(kh0, kh1, kh2, kh3, Kh + off);
                ldmatrix_x4(kl0, kl1, kl2, kl3, Kl + off);
                mma_bf16(S[2 * np], qfh[ks][0], qfh[ks][1], qfh[ks][2], qfh[ks][3], kh0, kh1);
                mma_bf16(S[2 * np], qfh[ks][0], qfh[ks][1], qfh[ks][2], qfh[ks][3], kl0, kl1);
                mma_bf16(S[2 * np], qfl[ks][0], qfl[ks][1], qfl[ks][2], qfl[ks][3], kh0, kh1);
                mma_bf16(S[2 * np + 1], qfh[ks][0], qfh[ks][1], qfh[ks][2], qfh[ks][3], kh2, kh3);
                mma_bf16(S[2 * np + 1], qfh[ks][0], qfh[ks][1], qfh[ks][2], qfh[ks][3], kl2, kl3);
                mma_bf16(S[2 * np + 1], qfl[ks][0], qfl[ks][1], qfl[ks][2], qfl[ks][3], kh2, kh3);
            }
        }

        // online softmax (log2 domain)
        float mx0 = -__int_as_float(0x7f800000), mx1 = mx0;
#pragma unroll
        for (int n = 0; n < 8; n++) {
            mx0 = fmaxf(mx0, fmaxf(S[n][0], S[n][1]));
            mx1 = fmaxf(mx1, fmaxf(S[n][2], S[n][3]));
        }
        mx0 = fmaxf(mx0, __shfl_xor_sync(0xffffffffu, mx0, 1));
        mx0 = fmaxf(mx0, __shfl_xor_sync(0xffffffffu, mx0, 2));
        mx1 = fmaxf(mx1, __shfl_xor_sync(0xffffffffu, mx1, 1));
        mx1 = fmaxf(mx1, __shfl_xor_sync(0xffffffffu, mx1, 2));
        const float mn0 = fmaxf(m0, mx0), mn1 = fmaxf(m1, mx1);
        const float al0 = exp2f(m0 - mn0), al1 = exp2f(m1 - mn1);
        float s0 = 0.0f, s1 = 0.0f;
#pragma unroll
        for (int n = 0; n < 8; n++) {
            S[n][0] = exp2f(S[n][0] - mn0);
            S[n][1] = exp2f(S[n][1] - mn0);
            S[n][2] = exp2f(S[n][2] - mn1);
            S[n][3] = exp2f(S[n][3] - mn1);
            s0 += S[n][0] + S[n][1];
            s1 += S[n][2] + S[n][3];
        }
        s0 += __shfl_xor_sync(0xffffffffu, s0, 1);
        s0 += __shfl_xor_sync(0xffffffffu, s0, 2);
        s1 += __shfl_xor_sync(0xffffffffu, s1, 1);
        s1 += __shfl_xor_sync(0xffffffffu, s1, 2);
        l0 = l0 * al0 + s0;
        l1 = l1 * al1 + s1;
        m0 = mn0;
        m1 = mn1;
#pragma unroll
        for (int d = 0; d < 8; d++) {
            O[d][0] *= al0; O[d][1] *= al0;
            O[d][2] *= al1; O[d][3] *= al1;
        }

        // O += P V
        const uint32_t Vs = stb + 2 * AK_B;
#pragma unroll
        for (int u = 0; u < 4; u++) {
            uint32_t ph[4];
            ph[0] = cvt2h(S[2 * u][0], S[2 * u][1]);
            ph[1] = cvt2h(S[2 * u][2], S[2 * u][3]);
            ph[2] = cvt2h(S[2 * u + 1][0], S[2 * u + 1][1]);
            ph[3] = cvt2h(S[2 * u + 1][2], S[2 * u + 1][3]);
#pragma unroll
            for (int dp = 0; dp < 4; dp++) {
                const uint32_t off =
                    (uint32_t)((dp * 16 + b4_n + b4_row) * QPITCH + u * 16 + b4_k) * 2;
                uint32_t vh0, vh1, vh2, vh3;
                ldmatrix_x4(vh0, vh1, vh2, vh3, Vs + off);
                mma_f16(O[2 * dp], ph[0], ph[1], ph[2], ph[3], vh0, vh1);
                mma_f16(O[2 * dp + 1], ph[0], ph[1], ph[2], ph[3], vh2, vh3);
            }
        }

        bar_named(barid, 256);  // group done reading buf before refill
        if (i + 2 < NKT / 2)
            attn_load_stage2(stb, bh, (2 * (i + 2) + g) * KT, gtid);
        cp_commit();            // uniform commit keeps wait arithmetic constant
    }

    // ---- flash-decoding merge: group 1 -> smem, group 0 combines ----
    float* ms = (float*)(smem + MERGE_OFF);
    if (g == 1) {
        float* p = ms + gtid * 36;
#pragma unroll
        for (int d = 0; d < 8; d++) {
            p[d * 4 + 0] = O[d][0]; p[d * 4 + 1] = O[d][1];
            p[d * 4 + 2] = O[d][2]; p[d * 4 + 3] = O[d][3];
        }
        p[32] = m0; p[33] = m1; p[34] = l0; p[35] = l1;
    }
    __syncthreads();
    if (g == 0) {
        const float* p = ms + gtid * 36;
        const float mB0 = p[32], mB1 = p[33], lB0 = p[34], lB1 = p[35];
        const float M0 = fmaxf(m0, mB0), M1 = fmaxf(m1, mB1);
        const float wA0 = exp2f(m0 - M0), wB0 = exp2f(mB0 - M0);
        const float wA1 = exp2f(m1 - M1), wB1 = exp2f(mB1 - M1);
        const float r0 = 1.0f / (l0 * wA0 + lB0 * wB0);
        const float r1 = 1.0f / (l1 * wA1 + lB1 * wB1);

        const int row0 = q0 + wq * 16 + (lane >> 2);
        const size_t base0 = ((size_t)b * TT + row0) * CC + h * DH;
        const size_t base1 = base0 + (size_t)8 * CC;
#pragma unroll
        for (int dn = 0; dn < 8; dn++) {
            const int col = dn * 8 + 2 * (lane & 3);
            const float o0 = (O[dn][0] * wA0 + p[dn * 4 + 0] * wB0) * r0;
            const float o1 = (O[dn][1] * wA0 + p[dn * 4 + 1] * wB0) * r0;
            const float o2 = (O[dn][2] * wA1 + p[dn * 4 + 2] * wB1) * r1;
            const float o3 = (O[dn][3] * wA1 + p[dn * 4 + 3] * wB1) * r1;
            *(uint32_t*)&g_cT[base0 + col] = cvt2h(o0, o1);
            *(uint32_t*)&g_cT[base1 + col] = cvt2h(o2, o3);
        }
    }
}

// ===========================================================================
// LayerNorm: normalize-only
// ===========================================================================
__global__ void __launch_bounds__(256) ln_kernel(
    const float* __restrict__ gamma, const float* __restrict__ beta,
    float* __restrict__ out)
{
    const int tx = threadIdx.x, ty = threadIdx.y;
    const int b = blockIdx.y;
    const int t = blockIdx.x * 16 + tx;

    const float s = g_lnsum[(size_t)b * TT + t];
    const float q = g_lnsq[(size_t)b * TT + t];
    const float mu = s * (1.0f / CC);
    const float rstd = rsqrtf(q * (1.0f / CC) - mu * mu + LN_EPS);

    const float* yb = g_y + (size_t)b * CC * TT;
    float* ob = out + (size_t)b * CC * TT;
    for (int c = ty; c < CC; c += 16) {
        const float v = yb[(size_t)c * TT + t];
        ob[(size_t)c * TT + t] = (v - mu) * rstd * gamma[c] + beta[c];
    }
}

// ===========================================================================
extern "C" void kernel_launch(void* const* d_in, const int* in_sizes, int n_in,
                              void* d_out, int out_size)
{
    const float* x     = (const float*)d_in[0];
    const float* wqkv  = (const float*)d_in[1];
    const float* wfc   = (const float*)d_in[2];
    const float* gamma = (const float*)d_in[3];
    const float* beta  = (const float*)d_in[4];
    float* out = (float*)d_out;

    float* y;
    cudaGetSymbolAddress((void**)&y, g_y);
    __nv_bfloat16 *wqkh, *wqkl, *xth, *xtl;
    __half *wvh, *wvl, *wfh, *wfl, *xt16, *ct;
    cudaGetSymbolAddress((void**)&wqkh, g_wqk_hi);
    cudaGetSymbolAddress((void**)&wqkl, g_wqk_lo);
    cudaGetSymbolAddress((void**)&wvh, g_wv_hi);
    cudaGetSymbolAddress((void**)&wvl, g_wv_lo);
    cudaGetSymbolAddress((void**)&wfh, g_wfc_hi);
    cudaGetSymbolAddress((void**)&wfl, g_wfc_lo);
    cudaGetSymbolAddress((void**)&xth, g_xT_hi);
    cudaGetSymbolAddress((void**)&xtl, g_xT_lo);
    cudaGetSymbolAddress((void**)&xt16, g_xT_h16);
    cudaGetSymbolAddress((void**)&ct, g_cT);

    cudaFuncSetAttribute((const void*)hgemm<2, 0>, cudaFuncAttributeMaxDynamicSharedMemorySize, GEMM_SMEM0);
    cudaFuncSetAttribute((const void*)hgemm<3, 2>, cudaFuncAttributeMaxDynamicSharedMemorySize, GEMM_SMEM2);
    cudaFuncSetAttribute((const void*)hgemm<1, 2>, cudaFuncAttributeMaxDynamicSharedMemorySize, GEMM_SMEM2);
    cudaFuncSetAttribute((const void*)attn_mma, cudaFuncAttributeMaxDynamicSharedMemorySize, ATTN_SMEM);

    // 0) conversions + LN-stat zero
    split_kernel<<<(2 * CC * CC + 255) / 256, 256>>>(wqkv, wqkh, wqkl, 2 * CC * CC);
    splith_kernel<<<(CC * CC + 255) / 256, 256>>>(wqkv + 2 * CC * CC, wvh, wvl, CC * CC);
    splith_kernel<<<(CC * CC + 255) / 256, 256>>>(wfc, wfh, wfl, CC * CC);
    tsplit_kernel<<<dim3(TT / 32, CC / 32, BB), dim3(32, 8)>>>(x, xth, xtl, xt16);
    lnzero_kernel<<<(BB * TT + 255) / 256, 256>>>();

    // 1a) Q/K GEMM (bf16 3-term) with fused attention-layout epilogue
    hgemm<2, 0><<<dim3(TT / GM_NT, 2 * CC / GM_MT, BB), 256, GEMM_SMEM0>>>(
        (const uint16_t*)wqkh, (const uint16_t*)wqkl,
        (const uint16_t*)xth, (const uint16_t*)xtl, nullptr, nullptr, 0);

    // 1b) V GEMM (fp16 asym) -> g_v single fp16
    hgemm<3, 2><<<dim3(TT / GM_NT, CC / GM_MT, BB), 256, GEMM_SMEM2>>>(
        (const uint16_t*)wvh, (const uint16_t*)wvl,
        (const uint16_t*)xt16, nullptr, nullptr, nullptr, 0);

    // 2) split-KT warp-specialized flash attention -> g_cT
    attn_mma<<<dim3(TT / 128, HH, BB), 512, ATTN_SMEM>>>();

    // 3) y = w_fc @ ctx + x (fp16 asym) + fused LN stats
    hgemm<1, 2><<<dim3(TT / GM_NT, CC / GM_MT, BB), 256, GEMM_SMEM2>>>(
        (const uint16_t*)wfh, (const uint16_t*)wfl,
        (const uint16_t*)ct, nullptr, x, y, (long)CC * TT);

    // 4) LayerNorm normalize-only -> out
    ln_kernel<<<dim3(TT / 16, BB), dim3(16, 16)>>>(gamma, beta, out);
}

// round 13
// speedup vs baseline: 1.0212x; 1.0212x over previous
#include <cuda_runtime.h>
#include <cuda_bf16.h>
#include <cuda_fp16.h>
#include <cstdint>

#define BB 2
#define CC 1024
#define TT 2048
#define HH 16
#define DH 64
#define LN_EPS 1e-6f
#define LOG2E 1.44269504088896340736f

// ---- dense GEMM tiling (KC=32, 2-stage, 2 CTAs/SM) ----
#define GM_MT 128
#define GM_NT 128
#define GM_KC 32
#define NCHUNK (CC / GM_KC)            // 32
#define PITCH 40
#define A_BYTES (GM_MT * PITCH * 2)     // 10240
#define B_BYTES (GM_NT * PITCH * 2)     // 10240
#define STAGE0_BYTES (2 * A_BYTES + 2 * B_BYTES)  // 40960
#define GEMM_SMEM0 (2 * STAGE0_BYTES)             // 81920
#define STAGE2_BYTES (2 * A_BYTES + B_BYTES)      // 30720
#define GEMM_SMEM2 (2 * STAGE2_BYTES)             // 61440

// ---- attention: kt-tile 64, V rows 0..63 + ones-row block 64..71 ----
#define QPITCH 72
#define KT 64
#define NKT (TT / KT)                   // 32
#define AQ_B (128 * QPITCH * 2)         // 18432
#define AK_B (KT * QPITCH * 2)          // 9216
#define AV_ROWS 72
#define ASTAGE_B (2 * AK_B + AV_ROWS * QPITCH * 2)  // 28800
#define ATTN_SMEM (2 * AQ_B + 2 * ASTAGE_B)          // 94464 -> 2 CTAs/SM

// ---- scratch ----
__device__ float g_y[(size_t)BB * CC * TT];
__device__ float g_lnsum[(size_t)BB * TT];
__device__ float g_lnsq[(size_t)BB * TT];
__device__ __nv_bfloat16 g_wqk_hi[2 * CC * CC], g_wqk_lo[2 * CC * CC];
__device__ __half g_wv_hi[CC * CC], g_wv_lo[CC * CC];
__device__ __half g_wfc_hi[CC * CC], g_wfc_lo[CC * CC];
__device__ __nv_bfloat16 g_xT_hi[(size_t)BB * TT * CC], g_xT_lo[(size_t)BB * TT * CC];
__device__ __half g_xT_h16[(size_t)BB * TT * CC];
__device__ __half g_cT[(size_t)BB * TT * CC];
__device__ __nv_bfloat16 g_qT_hi[(size_t)BB * HH * TT * DH], g_qT_lo[(size_t)BB * HH * TT * DH];
__device__ __nv_bfloat16 g_kT_hi[(size_t)BB * HH * TT * DH], g_kT_lo[(size_t)BB * HH * TT * DH];
__device__ __half g_v[(size_t)BB * HH * DH * TT];

// ===========================================================================
__device__ __forceinline__ uint32_t smem_u32(const void* p) {
    return (uint32_t)__cvta_generic_to_shared(p);
}
__device__ __forceinline__ void cp16(uint32_t dst, const void* src) {
    asm volatile("cp.async.cg.shared.global [%0], [%1], 16;\n" :: "r"(dst), "l"(src));
}
__device__ __forceinline__ void cp_commit() {
    asm volatile("cp.async.commit_group;\n" ::: "memory");
}
__device__ __forceinline__ void ldmatrix_x4(uint32_t& a0, uint32_t& a1, uint32_t& a2,
                                            uint32_t& a3, uint32_t addr) {
    asm volatile("ldmatrix.sync.aligned.m8n8.x4.shared.b16 {%0,%1,%2,%3}, [%4];"
                 : "=r"(a0), "=r"(a1), "=r"(a2), "=r"(a3) : "r"(addr));
}
__device__ __forceinline__ void ldmatrix_x2(uint32_t& b0, uint32_t& b1, uint32_t addr) {
    asm volatile("ldmatrix.sync.aligned.m8n8.x2.shared.b16 {%0,%1}, [%2];"
                 : "=r"(b0), "=r"(b1) : "r"(addr));
}
__device__ __forceinline__ void mma_bf16(float* c,
                                         uint32_t a0, uint32_t a1, uint32_t a2, uint32_t a3,
                                         uint32_t b0, uint32_t b1) {
    asm volatile(
        "mma.sync.aligned.m16n8k16.row.col.f32.bf16.bf16.f32 "
        "{%0,%1,%2,%3}, {%4,%5,%6,%7}, {%8,%9}, {%0,%1,%2,%3};"
        : "+f"(c[0]), "+f"(c[1]), "+f"(c[2]), "+f"(c[3])
        : "r"(a0), "r"(a1), "r"(a2), "r"(a3), "r"(b0), "r"(b1));
}
__device__ __forceinline__ void mma_f16(float* c,
                                        uint32_t a0, uint32_t a1, uint32_t a2, uint32_t a3,
                                        uint32_t b0, uint32_t b1) {
    asm volatile(
        "mma.sync.aligned.m16n8k16.row.col.f32.f16.f16.f32 "
        "{%0,%1,%2,%3}, {%4,%5,%6,%7}, {%8,%9}, {%0,%1,%2,%3};"
        : "+f"(c[0]), "+f"(c[1]), "+f"(c[2]), "+f"(c[3])
        : "r"(a0), "r"(a1), "r"(a2), "r"(a3), "r"(b0), "r"(b1));
}
__device__ __forceinline__ uint32_t cvt2(float f0, float f1) {  // bf16x2
    uint32_t r;
    asm("cvt.rn.bf16x2.f32 %0, %1, %2;" : "=r"(r) : "f"(f1), "f"(f0));
    return r;
}
__device__ __forceinline__ void split2(float f0, float f1, uint32_t& hi, uint32_t& lo) {
    hi = cvt2(f0, f1);
    const float h0 = __uint_as_float(hi << 16);
    const float h1 = __uint_as_float(hi & 0xffff0000u);
    lo = cvt2(f0 - h0, f1 - h1);
}
__device__ __forceinline__ uint32_t cvt2h(float f0, float f1) {  // f16x2
    uint32_t r;
    asm("cvt.rn.f16x2.f32 %0, %1, %2;" : "=r"(r) : "f"(f1), "f"(f0));
    return r;
}

// ===========================================================================
// fused prologue conversions: wqk bf16 split | wv fp16 split | wfc fp16 split
// | LN stat zero — one launch, range-partitioned.
// ===========================================================================
__global__ void __launch_bounds__(256) conv_kernel(
    const float* __restrict__ wqkv, const float* __restrict__ wfc)
{
    const size_t N1 = (size_t)2 * CC * CC;
    const size_t N2 = (size_t)CC * CC;
    size_t i = (size_t)blockIdx.x * 256 + threadIdx.x;
    if (i < N1) {
        const float v = wqkv[i];
        const __nv_bfloat16 h = __float2bfloat16(v);
        g_wqk_hi[i] = h;
        g_wqk_lo[i] = __float2bfloat16(v - __bfloat162float(h));
    } else if (i < N1 + N2) {
        const float v = wqkv[i];  // wv region of wqkv
        const size_t j = i - N1;
        const __half h = __float2half_rn(v);
        g_wv_hi[j] = h;
        g_wv_lo[j] = __float2half_rn(v - __half2float(h));
    } else if (i < N1 + 2 * N2) {
        const size_t j = i - N1 - N2;
        const float v = wfc[j];
        const __half h = __float2half_rn(v);
        g_wfc_hi[j] = h;
        g_wfc_lo[j] = __float2half_rn(v - __half2float(h));
    } else if (i < N1 + 2 * N2 + (size_t)BB * TT) {
        const size_t j = i - N1 - 2 * N2;
        g_lnsum[j] = 0.0f;
        g_lnsq[j] = 0.0f;
    }
}

__global__ void __launch_bounds__(256) tsplit_kernel(
    const float* __restrict__ in, __nv_bfloat16* __restrict__ hi,
    __nv_bfloat16* __restrict__ lo, __half* __restrict__ h16)
{
    __shared__ float tile[32][33];
    const int b = blockIdx.z;
    const int t0 = blockIdx.x * 32, c0 = blockIdx.y * 32;
    const float* ib = in + (size_t)b * CC * TT;
    for (int j = threadIdx.y; j < 32; j += 8)
        tile[j][threadIdx.x] = ib[(size_t)(c0 + j) * TT + t0 + threadIdx.x];
    __syncthreads();
    __nv_bfloat16* hb = hi + (size_t)b * TT * CC;
    __nv_bfloat16* lb = lo + (size_t)b * TT * CC;
    __half* sb = h16 + (size_t)b * TT * CC;
    for (int j = threadIdx.y; j < 32; j += 8) {
        const float v = tile[threadIdx.x][j];
        const __nv_bfloat16 h = __float2bfloat16(v);
        const size_t o = (size_t)(t0 + j) * CC + c0 + threadIdx.x;
        hb[o] = h;
        lb[o] = __float2bfloat16(v - __bfloat162float(h));
        sb[o] = __float2half_rn(v);
    }
}

// ===========================================================================
// mma.sync split GEMM (round-11 config, unchanged)
// ===========================================================================
template <int MODE>
__device__ __forceinline__ void g_load_stage(
    uint32_t st, int kc,
    const uint16_t* __restrict__ Ahi, const uint16_t* __restrict__ Alo,
    const uint16_t* __restrict__ Bhi, const uint16_t* __restrict__ Blo,
    int m0, int n0, int tid)
{
    for (int i = tid; i < GM_MT * 4; i += 256) {
        const int r = i >> 2, c = i & 3;
        const uint32_t dst = st + (uint32_t)(r * PITCH + c * 8) * 2;
        const size_t g = (size_t)(m0 + r) * CC + kc + c * 8;
        cp16(dst, Ahi + g);
        cp16(dst + A_BYTES, Alo + g);
    }
    for (int i = tid; i < GM_NT * 4; i += 256) {
        const int r = i >> 2, c = i & 3;
        const uint32_t dst = st + 2 * A_BYTES + (uint32_t)(r * PITCH + c * 8) * 2;
        const size_t g = (size_t)(n0 + r) * CC + kc + c * 8;
        cp16(dst, Bhi + g);
        if (MODE == 0) cp16(dst + B_BYTES, Blo + g);
    }
    cp_commit();
}

template <int EPI, int MODE>
__global__ void __launch_bounds__(256) hgemm(
    const uint16_t* __restrict__ Ahi, const uint16_t* __restrict__ Alo,
    const uint16_t* __restrict__ BhiAll, const uint16_t* __restrict__ BloAll,
    const float* __restrict__ Res, float* __restrict__ Cout, long outBatchStride)
{
    extern __shared__ char smem[];
    const uint32_t sbase = smem_u32(smem);
    const uint32_t stageB = (MODE == 0) ? STAGE0_BYTES : STAGE2_BYTES;

    const int tid = threadIdx.x;
    const int wid = tid >> 5;
    const int lane = tid & 31;
    const int b = blockIdx.z;
    const int m0 = blockIdx.y * GM_MT;
    const int n0 = blockIdx.x * GM_NT;
    const int wm = (wid >> 2) * 64;
    const int wn = (wid & 3) * 32;

    const uint16_t* Bhi = BhiAll + (size_t)b * TT * CC;
    const uint16_t* Blo = (MODE == 0) ? (BloAll + (size_t)b * TT * CC) : nullptr;

    float acc[4][4][4];
#pragma unroll
    for (int i = 0; i < 4; i++)
#pragma unroll
        for (int j = 0; j < 4; j++)
#pragma unroll
            for (int r = 0; r < 4; r++) acc[i][j][r] = 0.0f;

    const int a_row = lane & 15;
    const int a_ksel = (lane >> 4) * 8;
    const int b4_row = lane & 7;
    const int b4_k = ((lane >> 3) & 1) * 8;
    const int b4_n = ((lane >> 4) & 1) * 8;

    g_load_stage<MODE>(sbase, 0, Ahi, Alo, Bhi, Blo, m0, n0, tid);

    for (int c = 0; c < NCHUNK; c++) {
        const uint32_t st = sbase + (uint32_t)(c & 1) * stageB;
        if (c + 1 < NCHUNK) {
            g_load_stage<MODE>(sbase + (uint32_t)((c + 1) & 1) * stageB,
                               (c + 1) * GM_KC, Ahi, Alo, Bhi, Blo, m0, n0, tid);
            asm volatile("cp.async.wait_group 1;\n" ::: "memory");
        } else {
            asm volatile("cp.async.wait_group 0;\n" ::: "memory");
        }
        __syncthreads();

        const uint32_t sAh = st;
        const uint32_t sAl = st + A_BYTES;
        const uint32_t sBh = st + 2 * A_BYTES;
        const uint32_t sBl = sBh + B_BYTES;

#pragma unroll
        for (int kk = 0; kk < GM_KC; kk += 16) {
            uint32_t ah[4][4], al[4][4], bh[4][2], bl[4][2];
#pragma unroll
            for (int mi = 0; mi < 4; mi++) {
                const uint32_t off =
                    (uint32_t)((wm + mi * 16 + a_row) * PITCH + kk + a_ksel) * 2;
                ldmatrix_x4(ah[mi][0], ah[mi][1], ah[mi][2], ah[mi][3], sAh + off);
                ldmatrix_x4(al[mi][0], al[mi][1], al[mi][2], al[mi][3], sAl + off);
            }
#pragma unroll
            for (int p = 0; p < 2; p++) {
                const uint32_t off =
                    (uint32_t)((wn + p * 16 + b4_n + b4_row) * PITCH + kk + b4_k) * 2;
                ldmatrix_x4(bh[2 * p][0], bh[2 * p][1], bh[2 * p + 1][0],
                            bh[2 * p + 1][1], sBh + off);
                if (MODE == 0)
                    ldmatrix_x4(bl[2 * p][0], bl[2 * p][1], bl[2 * p + 1][0],
                                bl[2 * p + 1][1], sBl + off);
            }
#pragma unroll
            for (int mi = 0; mi < 4; mi++)
#pragma unroll
                for (int nj = 0; nj < 4; nj++) {
                    float* a = acc[mi][nj];
                    if (MODE == 0) {
                        mma_bf16(a, ah[mi][0], ah[mi][1], ah[mi][2], ah[mi][3],
                                 bh[nj][0], bh[nj][1]);
                        mma_bf16(a, ah[mi][0], ah[mi][1], ah[mi][2], ah[mi][3],
                                 bl[nj][0], bl[nj][1]);
                        mma_bf16(a, al[mi][0], al[mi][1], al[mi][2], al[mi][3],
                                 bh[nj][0], bh[nj][1]);
                    } else {
                        mma_f16(a, ah[mi][0], ah[mi][1], ah[mi][2], ah[mi][3],
                                bh[nj][0], bh[nj][1]);
                        mma_f16(a, al[mi][0], al[mi][1], al[mi][2], al[mi][3],
                                bh[nj][0], bh[nj][1]);
                    }
                }
        }
        __syncthreads();
    }

    const int er = lane >> 2;
    const int ec = (lane & 3) * 2;

    if (EPI == 1) {
        float* lns = (float*)smem;
        float* lnq = lns + 128;
        if (tid < 128) { lns[tid] = 0.0f; lnq[tid] = 0.0f; }
        __syncthreads();

        float cs[8], cq[8];
#pragma unroll
        for (int i = 0; i < 8; i++) { cs[i] = 0.0f; cq[i] = 0.0f; }

        float* Cb = Cout + (size_t)b * outBatchStride;
        const float* Rb = Res + (size_t)b * CC * TT;
#pragma unroll
        for (int mi = 0; mi < 4; mi++)
#pragma unroll
            for (int nj = 0; nj < 4; nj++) {
                const int m = m0 + wm + mi * 16 + er;
                const int n = n0 + wn + nj * 8 + ec;
                float2 v0 = make_float2(acc[mi][nj][0], acc[mi][nj][1]);
                float2 v1 = make_float2(acc[mi][nj][2], acc[mi][nj][3]);
                const float2 r0 = *(const float2*)(Rb + (size_t)m * TT + n);
                const float2 r1 = *(const float2*)(Rb + (size_t)(m + 8) * TT + n);
                v0.x += r0.x; v0.y += r0.y;
                v1.x += r1.x; v1.y += r1.y;
                *(float2*)(Cb + (size_t)m * TT + n) = v0;
                *(float2*)(Cb + (size_t)(m + 8) * TT + n) = v1;
                cs[nj * 2 + 0] += v0.x + v1.x;
                cq[nj * 2 + 0] += v0.x * v0.x + v1.x * v1.x;
                cs[nj * 2 + 1] += v0.y + v1.y;
                cq[nj * 2 + 1] += v0.y * v0.y + v1.y * v1.y;
            }
#pragma unroll
        for (int ci = 0; ci < 8; ci++) {
            const int col = wn + (ci >> 1) * 8 + ec + (ci & 1);
            atomicAdd(&lns[col], cs[ci]);
            atomicAdd(&lnq[col], cq[ci]);
        }
        __syncthreads();
        if (tid < 128) {
            atomicAdd(&g_lnsum[(size_t)b * TT + n0 + tid], lns[tid]);
            atomicAdd(&g_lnsq[(size_t)b * TT + n0 + tid], lnq[tid]);
        }
    } else if (EPI == 3) {
        uint32_t* vv = (uint32_t*)g_v;
#pragma unroll
        for (int mi = 0; mi < 4; mi++)
#pragma unroll
            for (int nj = 0; nj < 4; nj++) {
                const int n = n0 + wn + nj * 8 + ec;
#pragma unroll
                for (int rr = 0; rr < 2; rr++) {
                    const int ch = m0 + wm + mi * 16 + er + rr * 8;
                    const int bh = b * HH + (ch >> 6);
                    const int d = ch & 63;
                    vv[(((size_t)bh * DH + d) * TT + n) >> 1] =
                        cvt2h(acc[mi][nj][2 * rr], acc[mi][nj][2 * rr + 1]);
                }
            }
    } else {
        const bool isK = (m0 >= CC);
        const float qscale = isK ? 1.0f : LOG2E;
        const int chBase = isK ? (m0 - CC) : m0;
        const int h0 = chBase >> 6;
        float* stg = (float*)smem;
#pragma unroll
        for (int mi = 0; mi < 4; mi++)
#pragma unroll
            for (int nj = 0; nj < 4; nj++) {
                const int m = wm + mi * 16 + er;
                const int n = wn + nj * 8 + ec;
                stg[n * 129 + m] = acc[mi][nj][0];
                stg[(n + 1) * 129 + m] = acc[mi][nj][1];
                stg[n * 129 + m + 8] = acc[mi][nj][2];
                stg[(n + 1) * 129 + m + 8] = acc[mi][nj][3];
            }
        __syncthreads();
        uint32_t* dh = (uint32_t*)(isK ? g_kT_hi : g_qT_hi);
        uint32_t* dl = (uint32_t*)(isK ? g_kT_lo : g_qT_lo);
#pragma unroll
        for (int i = 0; i < 16; i++) {
            const int t = wid * 16 + i;
            const float* row = stg + t * 129;
#pragma unroll
            for (int half = 0; half < 2; half++) {
                const float v0 = row[half * 64 + 2 * lane] * qscale;
                const float v1 = row[half * 64 + 2 * lane + 1] * qscale;
                uint32_t hi, lo;
                split2(v0, v1, hi, lo);
                const size_t idx =
                    ((size_t)(b * HH + h0 + half) * TT + n0 + t) * 32 + lane;
                dh[idx] = hi;
                dl[idx] = lo;
            }
        }
    }
}

// ===========================================================================
// Flash attention (round-11 structure) + ones-row l-accumulation.
// QK bf16 3-term, exp2 softmax, PV fp16 single x single; V row 64 = ones.
// ===========================================================================
__device__ __forceinline__ void attn_load_stage(uint32_t st, int bh, int k0, int tid)
{
    const __nv_bfloat16* kh = g_kT_hi + ((size_t)bh * TT + k0) * DH;
    const __nv_bfloat16* kl = g_kT_lo + ((size_t)bh * TT + k0) * DH;
    for (int i = tid; i < KT * 8; i += 256) {
        const int r = i >> 3, c = i & 7;
        const uint32_t d = st + (uint32_t)(r * QPITCH + c * 8) * 2;
        cp16(d, kh + (size_t)r * DH + c * 8);
        cp16(d + AK_B, kl + (size_t)r * DH + c * 8);
    }
    const __half* vp = g_v + (size_t)bh * DH * TT + k0;
    for (int i = tid; i < 64 * (KT / 8); i += 256) {
        const int r = i >> 3, c = i & 7;
        const uint32_t d = st + 2 * AK_B + (uint32_t)(r * QPITCH + c * 8) * 2;
        cp16(d, vp + (size_t)r * TT + c * 8);
    }
}

__global__ void __launch_bounds__(256, 2) attn_mma()
{
    extern __shared__ char smem[];
    const uint32_t sb = smem_u32(smem);
    const uint32_t sQh = sb, sQl = sb + AQ_B;
    const uint32_t stage0 = sb + 2 * AQ_B;

    const int tid = threadIdx.x;
    const int wq = tid >> 5;
    const int lane = tid & 31;
    const int b = blockIdx.z, h = blockIdx.y;
    const int bh = b * HH + h;
    const int q0 = blockIdx.x * 128;

    {
        const __nv_bfloat16* qh = g_qT_hi + ((size_t)bh * TT + q0) * DH;
        const __nv_bfloat16* ql = g_qT_lo + ((size_t)bh * TT + q0) * DH;
        for (int i = tid; i < 128 * 8; i += 256) {
            const int r = i >> 3, c = i & 7;
            const uint32_t d = sQh + (uint32_t)(r * QPITCH + c * 8) * 2;
            cp16(d, qh + (size_t)r * DH + c * 8);
            cp16(d + AQ_B, ql + (size_t)r * DH + c * 8);
        }
        attn_load_stage(stage0, bh, 0, tid);
        cp_commit();
    }

    // init V ones-row block (rows 64..71; row 64 = 1.0h, rest 0) in both stages
    for (int s = 0; s < 2; s++) {
        char* vbase = smem + (2 * AQ_B + s * ASTAGE_B + 2 * AK_B);
        for (int i = tid; i < 8 * 32; i += 256) {   // 8 rows x 64 halfs
            const int r = i >> 5, c = i & 31;
            *(uint32_t*)(vbase + (size_t)(64 + r) * QPITCH * 2 + c * 4) =
                (r == 0) ? 0x3C003C00u : 0u;
        }
    }

    const int a_row = lane & 15;
    const int a_ksel = (lane >> 4) * 8;
    const int b4_row = lane & 7;
    const int b4_k = ((lane >> 3) & 1) * 8;
    const int b4_n = ((lane >> 4) & 1) * 8;
    const int l2_row = lane & 7;               // ldmatrix.x2 addressing (lanes 0..15)
    const int l2_k = ((lane >> 3) & 1) * 8;

    uint32_t qfh[4][4], qfl[4][4];
    float O[8][4], Oext[4];
    float m0 = -__int_as_float(0x7f800000), m1 = m0;
#pragma unroll
    for (int d = 0; d < 8; d++)
#pragma unroll
        for (int r = 0; r < 4; r++) O[d][r] = 0.0f;
#pragma unroll
    for (int r = 0; r < 4; r++) Oext[r] = 0.0f;

    for (int kt = 0; kt < NKT; kt++) {
        const uint32_t stb = stage0 + (uint32_t)(kt & 1) * ASTAGE_B;
        if (kt + 1 < NKT) {
            attn_load_stage(stage0 + (uint32_t)((kt + 1) & 1) * ASTAGE_B,
                            bh, (kt + 1) * KT, tid);
            cp_commit();
            asm volatile("cp.async.wait_group 1;\n" ::: "memory");
        } else {
            asm volatile("cp.async.wait_group 0;\n" ::: "memory");
        }
        __syncthreads();

        if (kt == 0) {
#pragma unroll
            for (int ks = 0; ks < 4; ks++) {
                const uint32_t off =
                    (uint32_t)((wq * 16 + a_row) * QPITCH + ks * 16 + a_ksel) * 2;
                ldmatrix_x4(qfh[ks][0], qfh[ks][1], qfh[ks][2], qfh[ks][3], sQh + off);
                ldmatrix_x4(qfl[ks][0], qfl[ks][1], qfl[ks][2], qfl[ks][3], sQl + off);
            }
        }

        float S[8][4];
#pragma unroll
        for (int n = 0; n < 8; n++)
#pragma unroll
            for (int r = 0; r < 4; r++) S[n][r] = 0.0f;

        const uint32_t Kh = stb, Kl = stb + AK_B;
#pragma unroll
        for (int np = 0; np < 4; np++) {
#pragma unroll
            for (int ks = 0; ks < 4; ks++) {
                const uint32_t off =
                    (uint32_t)((np * 16 + b4_n + b4_row) * QPITCH + ks * 16 + b4_k) * 2;
                uint32_t kh0, kh1, kh2, kh3, kl0, kl1, kl2, kl3;
                ldmatrix_x4(kh0, kh1, kh2, kh3, Kh + off);
                ldmatrix_x4(kl0, kl1, kl2, kl3, Kl + off);
                mma_bf16(S[2 * np], qfh[ks][0], qfh[ks][1], qfh[ks][2], qfh[ks][3], kh0, kh1);
                mma_bf16(S[2 * np], qfh[ks][0], qfh[ks][1], qfh[ks][2], qfh[ks][3], kl0, kl1);
                mma_bf16(S[2 * np], qfl[ks][0], qfl[ks][1], qfl[ks][2], qfl[ks][3], kh0, kh1);
                mma_bf16(S[2 * np + 1], qfh[ks][0], qfh[ks][1], qfh[ks][2], qfh[ks][3], kh2, kh3);
                mma_bf16(S[2 * np + 1], qfh[ks][0], qfh[ks][1], qfh[ks][2], qfh[ks][3], kl2, kl3);
                mma_bf16(S[2 * np + 1], qfl[ks][0], qfl[ks][1], qfl[ks][2], qfl[ks][3], kh2, kh3);
            }
        }

        // online softmax (log2 domain); l tracked via ones-row mma
        float mx0 = -__int_as_float(0x7f800000), mx1 = mx0;
#pragma unroll
        for (int n = 0; n < 8; n++) {
            mx0 = fmaxf(mx0, fmaxf(S[n][0], S[n][1]));
            mx1 = fmaxf(mx1, fmaxf(S[n][2], S[n][3]));
        }
        mx0 = fmaxf(mx0, __shfl_xor_sync(0xffffffffu, mx0, 1));
        mx0 = fmaxf(mx0, __shfl_xor_sync(0xffffffffu, mx0, 2));
        mx1 = fmaxf(mx1, __shfl_xor_sync(0xffffffffu, mx1, 1));
        mx1 = fmaxf(mx1, __shfl_xor_sync(0xffffffffu, mx1, 2));
        const float mn0 = fmaxf(m0, mx0), mn1 = fmaxf(m1, mx1);
        const float al0 = exp2f(m0 - mn0), al1 = exp2f(m1 - mn1);
#pragma unroll
        for (int n = 0; n < 8; n++) {
            S[n][0] = exp2f(S[n][0] - mn0);
            S[n][1] = exp2f(S[n][1] - mn0);
            S[n][2] = exp2f(S[n][2] - mn1);
            S[n][3] = exp2f(S[n][3] - mn1);
        }
        m0 = mn0;
        m1 = mn1;
#pragma unroll
        for (int d = 0; d < 8; d++) {
            O[d][0] *= al0; O[d][1] *= al0;
            O[d][2] *= al1; O[d][3] *= al1;
        }
        Oext[0] *= al0; Oext[1] *= al0;
        Oext[2] *= al1; Oext[3] *= al1;

        // O += P V  (single fp16) + ones-row l accumulation
        const uint32_t Vs = stb + 2 * AK_B;
#pragma unroll
        for (int u = 0; u < 4; u++) {
            uint32_t ph[4];
            ph[0] = cvt2h(S[2 * u][0], S[2 * u][1]);
            ph[1] = cvt2h(S[2 * u][2], S[2 * u][3]);
            ph[2] = cvt2h(S[2 * u + 1][0], S[2 * u + 1][1]);
            ph[3] = cvt2h(S[2 * u + 1][2], S[2 * u + 1][3]);
#pragma unroll
            for (int dp = 0; dp < 4; dp++) {
                const uint32_t off =
                    (uint32_t)((dp * 16 + b4_n + b4_row) * QPITCH + u * 16 + b4_k) * 2;
                uint32_t vh0, vh1, vh2, vh3;
                ldmatrix_x4(vh0, vh1, vh2, vh3, Vs + off);
                mma_f16(O[2 * dp], ph[0], ph[1], ph[2], ph[3], vh0, vh1);
                mma_f16(O[2 * dp + 1], ph[0], ph[1], ph[2], ph[3], vh2, vh3);
            }
            {   // rows 64..71 (row 64 = ones): l into Oext
                uint32_t e0, e1;
                const uint32_t off =
                    (uint32_t)((64 + l2_row) * QPITCH + u * 16 + l2_k) * 2;
                ldmatrix_x2(e0, e1, Vs + off);
                mma_f16(Oext, ph[0], ph[1], ph[2], ph[3], e0, e1);
            }
        }
        __syncthreads();
    }

    // epilogue: l lives in quad-leader c0/c2 of Oext
    const float l0 = __shfl_sync(0xffffffffu, Oext[0], lane & 0x1c);
    const float l1 = __shfl_sync(0xffffffffu, Oext[2], lane & 0x1c);
    const float r0 = 1.0f / l0, r1 = 1.0f / l1;
    const int row0 = q0 + wq * 16 + (lane >> 2);
    const size_t base0 = ((size_t)b * TT + row0) * CC + h * DH;
    const size_t base1 = base0 + (size_t)8 * CC;
#pragma unroll
    for (int dn = 0; dn < 8; dn++) {
        const int col = dn * 8 + 2 * (lane & 3);
        *(uint32_t*)&g_cT[base0 + col] = cvt2h(O[dn][0] * r0, O[dn][1] * r0);
        *(uint32_t*)&g_cT[base1 + col] = cvt2h(O[dn][2] * r1, O[dn][3] * r1);
    }
}

// ===========================================================================
// LayerNorm: normalize-only
// ===========================================================================
__global__ void __launch_bounds__(256) ln_kernel(
    const float* __restrict__ gamma, const float* __restrict__ beta,
    float* __restrict__ out)
{
    const int tx = threadIdx.x, ty = threadIdx.y;
    const int b = blockIdx.y;
    const int t = blockIdx.x * 16 + tx;

    const float s = g_lnsum[(size_t)b * TT + t];
    const float q = g_lnsq[(size_t)b * TT + t];
    const float mu = s * (1.0f / CC);
    const float rstd = rsqrtf(q * (1.0f / CC) - mu * mu + LN_EPS);

    const float* yb = g_y + (size_t)b * CC * TT;
    float* ob = out + (size_t)b * CC * TT;
    for (int c = ty; c < CC; c += 16) {
        const float v = yb[(size_t)c * TT + t];
        ob[(size_t)c * TT + t] = (v - mu) * rstd * gamma[c] + beta[c];
    }
}

// ===========================================================================
extern "C" void kernel_launch(void* const* d_in, const int* in_sizes, int n_in,
                              void* d_out, int out_size)
{
    const float* x     = (const float*)d_in[0];
    const float* wqkv  = (const float*)d_in[1];
    const float* wfc   = (const float*)d_in[2];
    const float* gamma = (const float*)d_in[3];
    const float* beta  = (const float*)d_in[4];
    float* out = (float*)d_out;

    float* y;
    cudaGetSymbolAddress((void**)&y, g_y);
    __nv_bfloat16 *wqkh, *wqkl, *xth, *xtl;
    __half *wvh, *wvl, *wfh, *wfl, *xt16, *ct;
    cudaGetSymbolAddress((void**)&wqkh, g_wqk_hi);
    cudaGetSymbolAddress((void**)&wqkl, g_wqk_lo);
    cudaGetSymbolAddress((void**)&wvh, g_wv_hi);
    cudaGetSymbolAddress((void**)&wvl, g_wv_lo);
    cudaGetSymbolAddress((void**)&wfh, g_wfc_hi);
    cudaGetSymbolAddress((void**)&wfl, g_wfc_lo);
    cudaGetSymbolAddress((void**)&xth, g_xT_hi);
    cudaGetSymbolAddress((void**)&xtl, g_xT_lo);
    cudaGetSymbolAddress((void**)&xt16, g_xT_h16);
    cudaGetSymbolAddress((void**)&ct, g_cT);

    cudaFuncSetAttribute((const void*)hgemm<2, 0>, cudaFuncAttributeMaxDynamicSharedMemorySize, GEMM_SMEM0);
    cudaFuncSetAttribute((const void*)hgemm<3, 2>, cudaFuncAttributeMaxDynamicSharedMemorySize, GEMM_SMEM2);
    cudaFuncSetAttribute((const void*)hgemm<1, 2>, cudaFuncAttributeMaxDynamicSharedMemorySize, GEMM_SMEM2);
    cudaFuncSetAttribute((const void*)attn_mma, cudaFuncAttributeMaxDynamicSharedMemorySize, ATTN_SMEM);

    // 0) fused conversions + LN-stat zero, then x transpose-split
    {
        const size_t total = (size_t)4 * CC * CC + (size_t)BB * TT;
        conv_kernel<<<(unsigned)((total + 255) / 256), 256>>>(wqkv, wfc);
    }
    tsplit_kernel<<<dim3(TT / 32, CC / 32, BB), dim3(32, 8)>>>(x, xth, xtl, xt16);

    // 1a) Q/K GEMM (bf16 3-term) with fused attention-layout epilogue
    hgemm<2, 0><<<dim3(TT / GM_NT, 2 * CC / GM_MT, BB), 256, GEMM_SMEM0>>>(
        (const uint16_t*)wqkh, (const uint16_t*)wqkl,
        (const uint16_t*)xth, (const uint16_t*)xtl, nullptr, nullptr, 0);

    // 1b) V GEMM (fp16 asym) -> g_v single fp16
    hgemm<3, 2><<<dim3(TT / GM_NT, CC / GM_MT, BB), 256, GEMM_SMEM2>>>(
        (const uint16_t*)wvh, (const uint16_t*)wvl,
        (const uint16_t*)xt16, nullptr, nullptr, nullptr, 0);

    // 2) flash attention (ones-row l) -> g_cT
    attn_mma<<<dim3(TT / 128, HH, BB), 256, ATTN_SMEM>>>();

    // 3) y = w_fc @ ctx + x (fp16 asym) + fused LN stats
    hgemm<1, 2><<<dim3(TT / GM_NT, CC / GM_MT, BB), 256, GEMM_SMEM2>>>(
        (const uint16_t*)wfh, (const uint16_t*)wfl,
        (const uint16_t*)ct, nullptr, x, y, (long)CC * TT);

    // 4) LayerNorm normalize-only -> out
    ln_kernel<<<dim3(TT / 16, BB), dim3(16, 16)>>>(gamma, beta, out);
}

// round 14
// speedup vs baseline: 1.0436x; 1.0219x over previous
#include <cuda_runtime.h>
#include <cuda_bf16.h>
#include <cuda_fp16.h>
#include <cstdint>

#define BB 2
#define CC 1024
#define TT 2048
#define HH 16
#define DH 64
#define LN_EPS 1e-6f
#define LOG2E 1.44269504088896340736f

// ---- dense GEMM tiling (KC=32, 2-stage, 2 CTAs/SM) ----
#define GM_MT 128
#define GM_NT 128
#define GM_KC 32
#define NCHUNK (CC / GM_KC)            // 32
#define PITCH 40
#define A_BYTES (GM_MT * PITCH * 2)     // 10240
#define B_BYTES (GM_NT * PITCH * 2)     // 10240
#define STAGE0_BYTES (2 * A_BYTES + 2 * B_BYTES)  // 40960
#define GEMM_SMEM0 (2 * STAGE0_BYTES)             // 81920
#define STAGE2_BYTES (2 * A_BYTES + B_BYTES)      // 30720
#define GEMM_SMEM2 (2 * STAGE2_BYTES)             // 61440

// ---- attention: kt-tile 64, V rows 0..63 + ones-row block 64..71 ----
#define QPITCH 72
#define KT 64
#define NKT (TT / KT)                   // 32
#define AQ_B (128 * QPITCH * 2)         // 18432
#define AK_B (KT * QPITCH * 2)          // 9216
#define AV_ROWS 72
#define ASTAGE_B (2 * AK_B + AV_ROWS * QPITCH * 2)  // 28800
#define ATTN_SMEM (2 * AQ_B + 2 * ASTAGE_B)          // 94464 -> 2 CTAs/SM

// conv work folded into tsplit grid
#define CONV_TOTAL ((size_t)4 * CC * CC + (size_t)BB * TT)   // 4198400
#define CONVX 257                                            // ceil(16400/64)

// ---- scratch ----
__device__ float g_y[(size_t)BB * CC * TT];
__device__ float g_lnsum[(size_t)BB * TT];
__device__ float g_lnsq[(size_t)BB * TT];
__device__ __nv_bfloat16 g_wqk_hi[2 * CC * CC], g_wqk_lo[2 * CC * CC];
__device__ __half g_wv_hi[CC * CC], g_wv_lo[CC * CC];
__device__ __half g_wfc_hi[CC * CC], g_wfc_lo[CC * CC];
__device__ __nv_bfloat16 g_xT_hi[(size_t)BB * TT * CC], g_xT_lo[(size_t)BB * TT * CC];
__device__ __half g_xT_h16[(size_t)BB * TT * CC];
__device__ __half g_cT[(size_t)BB * TT * CC];
__device__ __nv_bfloat16 g_qT_hi[(size_t)BB * HH * TT * DH], g_qT_lo[(size_t)BB * HH * TT * DH];
__device__ __nv_bfloat16 g_kT_hi[(size_t)BB * HH * TT * DH], g_kT_lo[(size_t)BB * HH * TT * DH];
__device__ __half g_v[(size_t)BB * HH * DH * TT];

// ===========================================================================
__device__ __forceinline__ uint32_t smem_u32(const void* p) {
    return (uint32_t)__cvta_generic_to_shared(p);
}
__device__ __forceinline__ void cp16(uint32_t dst, const void* src) {
    asm volatile("cp.async.cg.shared.global [%0], [%1], 16;\n" :: "r"(dst), "l"(src));
}
__device__ __forceinline__ void cp_commit() {
    asm volatile("cp.async.commit_group;\n" ::: "memory");
}
__device__ __forceinline__ void ldmatrix_x4(uint32_t& a0, uint32_t& a1, uint32_t& a2,
                                            uint32_t& a3, uint32_t addr) {
    asm volatile("ldmatrix.sync.aligned.m8n8.x4.shared.b16 {%0,%1,%2,%3}, [%4];"
                 : "=r"(a0), "=r"(a1), "=r"(a2), "=r"(a3) : "r"(addr));
}
__device__ __forceinline__ void ldmatrix_x2(uint32_t& b0, uint32_t& b1, uint32_t addr) {
    asm volatile("ldmatrix.sync.aligned.m8n8.x2.shared.b16 {%0,%1}, [%2];"
                 : "=r"(b0), "=r"(b1) : "r"(addr));
}
__device__ __forceinline__ void mma_bf16(float* c,
                                         uint32_t a0, uint32_t a1, uint32_t a2, uint32_t a3,
                                         uint32_t b0, uint32_t b1) {
    asm volatile(
        "mma.sync.aligned.m16n8k16.row.col.f32.bf16.bf16.f32 "
        "{%0,%1,%2,%3}, {%4,%5,%6,%7}, {%8,%9}, {%0,%1,%2,%3};"
        : "+f"(c[0]), "+f"(c[1]), "+f"(c[2]), "+f"(c[3])
        : "r"(a0), "r"(a1), "r"(a2), "r"(a3), "r"(b0), "r"(b1));
}
__device__ __forceinline__ void mma_f16(float* c,
                                        uint32_t a0, uint32_t a1, uint32_t a2, uint32_t a3,
                                        uint32_t b0, uint32_t b1) {
    asm volatile(
        "mma.sync.aligned.m16n8k16.row.col.f32.f16.f16.f32 "
        "{%0,%1,%2,%3}, {%4,%5,%6,%7}, {%8,%9}, {%0,%1,%2,%3};"
        : "+f"(c[0]), "+f"(c[1]), "+f"(c[2]), "+f"(c[3])
        : "r"(a0), "r"(a1), "r"(a2), "r"(a3), "r"(b0), "r"(b1));
}
__device__ __forceinline__ uint32_t cvt2(float f0, float f1) {  // bf16x2
    uint32_t r;
    asm("cvt.rn.bf16x2.f32 %0, %1, %2;" : "=r"(r) : "f"(f1), "f"(f0));
    return r;
}
__device__ __forceinline__ void split2(float f0, float f1, uint32_t& hi, uint32_t& lo) {
    hi = cvt2(f0, f1);
    const float h0 = __uint_as_float(hi << 16);
    const float h1 = __uint_as_float(hi & 0xffff0000u);
    lo = cvt2(f0 - h0, f1 - h1);
}
__device__ __forceinline__ uint32_t cvt2h(float f0, float f1) {  // f16x2
    uint32_t r;
    asm("cvt.rn.f16x2.f32 %0, %1, %2;" : "=r"(r) : "f"(f1), "f"(f0));
    return r;
}

// ===========================================================================
// fused prologue: tsplit (blocks x<64) + weight conversions + lnzero (x>=64)
// ===========================================================================
__global__ void __launch_bounds__(256) prologue_kernel(
    const float* __restrict__ x, const float* __restrict__ wqkv,
    const float* __restrict__ wfc)
{
    if (blockIdx.x < TT / 32) {
        __shared__ float tile[32][33];
        const int b = blockIdx.z;
        const int t0 = blockIdx.x * 32, c0 = blockIdx.y * 32;
        const float* ib = x + (size_t)b * CC * TT;
        for (int j = threadIdx.y; j < 32; j += 8)
            tile[j][threadIdx.x] = ib[(size_t)(c0 + j) * TT + t0 + threadIdx.x];
        __syncthreads();
        __nv_bfloat16* hb = g_xT_hi + (size_t)b * TT * CC;
        __nv_bfloat16* lb = g_xT_lo + (size_t)b * TT * CC;
        __half* sb = g_xT_h16 + (size_t)b * TT * CC;
        for (int j = threadIdx.y; j < 32; j += 8) {
            const float v = tile[threadIdx.x][j];
            const __nv_bfloat16 h = __float2bfloat16(v);
            const size_t o = (size_t)(t0 + j) * CC + c0 + threadIdx.x;
            hb[o] = h;
            lb[o] = __float2bfloat16(v - __bfloat162float(h));
            sb[o] = __float2half_rn(v);
        }
    } else {
        const int tid = threadIdx.y * 32 + threadIdx.x;
        const size_t cid = (size_t)(blockIdx.x - TT / 32) +
                           (size_t)CONVX * (blockIdx.y + 32 * blockIdx.z);
        const size_t i = cid * 256 + tid;
        const size_t N1 = (size_t)2 * CC * CC;
        const size_t N2 = (size_t)CC * CC;
        if (i < N1) {
            const float v = wqkv[i];
            const __nv_bfloat16 h = __float2bfloat16(v);
            g_wqk_hi[i] = h;
            g_wqk_lo[i] = __float2bfloat16(v - __bfloat162float(h));
        } else if (i < N1 + N2) {
            const float v = wqkv[i];
            const size_t j = i - N1;
            const __half h = __float2half_rn(v);
            g_wv_hi[j] = h;
            g_wv_lo[j] = __float2half_rn(v - __half2float(h));
        } else if (i < N1 + 2 * N2) {
            const size_t j = i - N1 - N2;
            const float v = wfc[j];
            const __half h = __float2half_rn(v);
            g_wfc_hi[j] = h;
            g_wfc_lo[j] = __float2half_rn(v - __half2float(h));
        } else if (i < CONV_TOTAL) {
            const size_t j = i - N1 - 2 * N2;
            g_lnsum[j] = 0.0f;
            g_lnsq[j] = 0.0f;
        }
    }
}

// ===========================================================================
// shared GEMM core (templated), callers pass m-block index `by`
// ===========================================================================
template <int MODE>
__device__ __forceinline__ void g_load_stage(
    uint32_t st, int kc,
    const uint16_t* __restrict__ Ahi, const uint16_t* __restrict__ Alo,
    const uint16_t* __restrict__ Bhi, const uint16_t* __restrict__ Blo,
    int m0, int n0, int tid)
{
    for (int i = tid; i < GM_MT * 4; i += 256) {
        const int r = i >> 2, c = i & 3;
        const uint32_t dst = st + (uint32_t)(r * PITCH + c * 8) * 2;
        const size_t g = (size_t)(m0 + r) * CC + kc + c * 8;
        cp16(dst, Ahi + g);
        cp16(dst + A_BYTES, Alo + g);
    }
    for (int i = tid; i < GM_NT * 4; i += 256) {
        const int r = i >> 2, c = i & 3;
        const uint32_t dst = st + 2 * A_BYTES + (uint32_t)(r * PITCH + c * 8) * 2;
        const size_t g = (size_t)(n0 + r) * CC + kc + c * 8;
        cp16(dst, Bhi + g);
        if (MODE == 0) cp16(dst + B_BYTES, Blo + g);
    }
    cp_commit();
}

template <int EPI, int MODE>
__device__ __forceinline__ void gemm_core(
    char* smem,
    const uint16_t* __restrict__ Ahi, const uint16_t* __restrict__ Alo,
    const uint16_t* __restrict__ BhiAll, const uint16_t* __restrict__ BloAll,
    const float* __restrict__ Res, float* __restrict__ Cout,
    long outBatchStride, int by)
{
    const uint32_t sbase = smem_u32(smem);
    const uint32_t stageB = (MODE == 0) ? STAGE0_BYTES : STAGE2_BYTES;

    const int tid = threadIdx.x;
    const int wid = tid >> 5;
    const int lane = tid & 31;
    const int b = blockIdx.z;
    const int m0 = by * GM_MT;
    const int n0 = blockIdx.x * GM_NT;
    const int wm = (wid >> 2) * 64;
    const int wn = (wid & 3) * 32;

    const uint16_t* Bhi = BhiAll + (size_t)b * TT * CC;
    const uint16_t* Blo = (MODE == 0) ? (BloAll + (size_t)b * TT * CC) : nullptr;

    float acc[4][4][4];
#pragma unroll
    for (int i = 0; i < 4; i++)
#pragma unroll
        for (int j = 0; j < 4; j++)
#pragma unroll
            for (int r = 0; r < 4; r++) acc[i][j][r] = 0.0f;

    const int a_row = lane & 15;
    const int a_ksel = (lane >> 4) * 8;
    const int b4_row = lane & 7;
    const int b4_k = ((lane >> 3) & 1) * 8;
    const int b4_n = ((lane >> 4) & 1) * 8;

    g_load_stage<MODE>(sbase, 0, Ahi, Alo, Bhi, Blo, m0, n0, tid);

    for (int c = 0; c < NCHUNK; c++) {
        const uint32_t st = sbase + (uint32_t)(c & 1) * stageB;
        if (c + 1 < NCHUNK) {
            g_load_stage<MODE>(sbase + (uint32_t)((c + 1) & 1) * stageB,
                               (c + 1) * GM_KC, Ahi, Alo, Bhi, Blo, m0, n0, tid);
            asm volatile("cp.async.wait_group 1;\n" ::: "memory");
        } else {
            asm volatile("cp.async.wait_group 0;\n" ::: "memory");
        }
        __syncthreads();

        const uint32_t sAh = st;
        const uint32_t sAl = st + A_BYTES;
        const uint32_t sBh = st + 2 * A_BYTES;
        const uint32_t sBl = sBh + B_BYTES;

#pragma unroll
        for (int kk = 0; kk < GM_KC; kk += 16) {
            uint32_t ah[4][4], al[4][4], bh[4][2], bl[4][2];
#pragma unroll
            for (int mi = 0; mi < 4; mi++) {
                const uint32_t off =
                    (uint32_t)((wm + mi * 16 + a_row) * PITCH + kk + a_ksel) * 2;
                ldmatrix_x4(ah[mi][0], ah[mi][1], ah[mi][2], ah[mi][3], sAh + off);
                ldmatrix_x4(al[mi][0], al[mi][1], al[mi][2], al[mi][3], sAl + off);
            }
#pragma unroll
            for (int p = 0; p < 2; p++) {
                const uint32_t off =
                    (uint32_t)((wn + p * 16 + b4_n + b4_row) * PITCH + kk + b4_k) * 2;
                ldmatrix_x4(bh[2 * p][0], bh[2 * p][1], bh[2 * p + 1][0],
                            bh[2 * p + 1][1], sBh + off);
                if (MODE == 0)
                    ldmatrix_x4(bl[2 * p][0], bl[2 * p][1], bl[2 * p + 1][0],
                                bl[2 * p + 1][1], sBl + off);
            }
#pragma unroll
            for (int mi = 0; mi < 4; mi++)
#pragma unroll
                for (int nj = 0; nj < 4; nj++) {
                    float* a = acc[mi][nj];
                    if (MODE == 0) {
                        mma_bf16(a, ah[mi][0], ah[mi][1], ah[mi][2], ah[mi][3],
                                 bh[nj][0], bh[nj][1]);
                        mma_bf16(a, ah[mi][0], ah[mi][1], ah[mi][2], ah[mi][3],
                                 bl[nj][0], bl[nj][1]);
                        mma_bf16(a, al[mi][0], al[mi][1], al[mi][2], al[mi][3],
                                 bh[nj][0], bh[nj][1]);
                    } else {
                        mma_f16(a, ah[mi][0], ah[mi][1], ah[mi][2], ah[mi][3],
                                bh[nj][0], bh[nj][1]);
                        mma_f16(a, al[mi][0], al[mi][1], al[mi][2], al[mi][3],
                                bh[nj][0], bh[nj][1]);
                    }
                }
        }
        __syncthreads();
    }

    const int er = lane >> 2;
    const int ec = (lane & 3) * 2;

    if (EPI == 1) {
        float* lns = (float*)smem;
        float* lnq = lns + 128;
        const int tid2 = threadIdx.x;
        if (tid2 < 128) { lns[tid2] = 0.0f; lnq[tid2] = 0.0f; }
        __syncthreads();

        float cs[8], cq[8];
#pragma unroll
        for (int i = 0; i < 8; i++) { cs[i] = 0.0f; cq[i] = 0.0f; }

        float* Cb = Cout + (size_t)b * outBatchStride;
        const float* Rb = Res + (size_t)b * CC * TT;
#pragma unroll
        for (int mi = 0; mi < 4; mi++)
#pragma unroll
            for (int nj = 0; nj < 4; nj++) {
                const int m = m0 + wm + mi * 16 + er;
                const int n = n0 + wn + nj * 8 + ec;
                float2 v0 = make_float2(acc[mi][nj][0], acc[mi][nj][1]);
                float2 v1 = make_float2(acc[mi][nj][2], acc[mi][nj][3]);
                const float2 r0 = *(const float2*)(Rb + (size_t)m * TT + n);
                const float2 r1 = *(const float2*)(Rb + (size_t)(m + 8) * TT + n);
                v0.x += r0.x; v0.y += r0.y;
                v1.x += r1.x; v1.y += r1.y;
                *(float2*)(Cb + (size_t)m * TT + n) = v0;
                *(float2*)(Cb + (size_t)(m + 8) * TT + n) = v1;
                cs[nj * 2 + 0] += v0.x + v1.x;
                cq[nj * 2 + 0] += v0.x * v0.x + v1.x * v1.x;
                cs[nj * 2 + 1] += v0.y + v1.y;
                cq[nj * 2 + 1] += v0.y * v0.y + v1.y * v1.y;
            }
#pragma unroll
        for (int ci = 0; ci < 8; ci++) {
            const int col = wn + (ci >> 1) * 8 + ec + (ci & 1);
            atomicAdd(&lns[col], cs[ci]);
            atomicAdd(&lnq[col], cq[ci]);
        }
        __syncthreads();
        if (tid2 < 128) {
            atomicAdd(&g_lnsum[(size_t)b * TT + n0 + tid2], lns[tid2]);
            atomicAdd(&g_lnsq[(size_t)b * TT + n0 + tid2], lnq[tid2]);
        }
    } else if (EPI == 3) {
        uint32_t* vv = (uint32_t*)g_v;
#pragma unroll
        for (int mi = 0; mi < 4; mi++)
#pragma unroll
            for (int nj = 0; nj < 4; nj++) {
                const int n = n0 + wn + nj * 8 + ec;
#pragma unroll
                for (int rr = 0; rr < 2; rr++) {
                    const int ch = m0 + wm + mi * 16 + er + rr * 8;
                    const int bh = b * HH + (ch >> 6);
                    const int d = ch & 63;
                    vv[(((size_t)bh * DH + d) * TT + n) >> 1] =
                        cvt2h(acc[mi][nj][2 * rr], acc[mi][nj][2 * rr + 1]);
                }
            }
    } else {
        const bool isK = (m0 >= CC);
        const float qscale = isK ? 1.0f : LOG2E;
        const int chBase = isK ? (m0 - CC) : m0;
        const int h0 = chBase >> 6;
        float* stg = (float*)smem;
#pragma unroll
        for (int mi = 0; mi < 4; mi++)
#pragma unroll
            for (int nj = 0; nj < 4; nj++) {
                const int m = wm + mi * 16 + er;
                const int n = wn + nj * 8 + ec;
                stg[n * 129 + m] = acc[mi][nj][0];
                stg[(n + 1) * 129 + m] = acc[mi][nj][1];
                stg[n * 129 + m + 8] = acc[mi][nj][2];
                stg[(n + 1) * 129 + m + 8] = acc[mi][nj][3];
            }
        __syncthreads();
        uint32_t* dh = (uint32_t*)(isK ? g_kT_hi : g_qT_hi);
        uint32_t* dl = (uint32_t*)(isK ? g_kT_lo : g_qT_lo);
#pragma unroll
        for (int i = 0; i < 16; i++) {
            const int t = wid * 16 + i;
            const float* row = stg + t * 129;
#pragma unroll
            for (int half = 0; half < 2; half++) {
                const float v0 = row[half * 64 + 2 * lane] * qscale;
                const float v1 = row[half * 64 + 2 * lane + 1] * qscale;
                uint32_t hi, lo;
                split2(v0, v1, hi, lo);
                const size_t idx =
                    ((size_t)(b * HH + h0 + half) * TT + n0 + t) * 32 + lane;
                dh[idx] = hi;
                dl[idx] = lo;
            }
        }
    }
}

// merged QK + V projection launch (grid.y = 24)
__global__ void __launch_bounds__(256, 2) qkv_fused(
    const uint16_t* __restrict__ wqkh, const uint16_t* __restrict__ wqkl,
    const uint16_t* __restrict__ xth, const uint16_t* __restrict__ xtl,
    const uint16_t* __restrict__ wvh, const uint16_t* __restrict__ wvl,
    const uint16_t* __restrict__ xt16)
{
    extern __shared__ char smem[];
    if (blockIdx.y < 2 * CC / GM_MT) {
        gemm_core<2, 0>(smem, wqkh, wqkl, xth, xtl, nullptr, nullptr, 0,
                        blockIdx.y);
    } else {
        gemm_core<3, 2>(smem, wvh, wvl, xt16, nullptr, nullptr, nullptr, 0,
                        blockIdx.y - 2 * CC / GM_MT);
    }
}

// projection GEMM (+residual, +LN stats)
__global__ void __launch_bounds__(256, 2) proj_gemm(
    const uint16_t* __restrict__ Ahi, const uint16_t* __restrict__ Alo,
    const uint16_t* __restrict__ Bhi,
    const float* __restrict__ Res, float* __restrict__ Cout, long outBatchStride)
{
    extern __shared__ char smem[];
    gemm_core<1, 2>(smem, Ahi, Alo, Bhi, nullptr, Res, Cout, outBatchStride,
                    blockIdx.y);
}

// ===========================================================================
// Flash attention + ones-row l-accumulation (round-13, unchanged)
// ===========================================================================
__device__ __forceinline__ void attn_load_stage(uint32_t st, int bh, int k0, int tid)
{
    const __nv_bfloat16* kh = g_kT_hi + ((size_t)bh * TT + k0) * DH;
    const __nv_bfloat16* kl = g_kT_lo + ((size_t)bh * TT + k0) * DH;
    for (int i = tid; i < KT * 8; i += 256) {
        const int r = i >> 3, c = i & 7;
        const uint32_t d = st + (uint32_t)(r * QPITCH + c * 8) * 2;
        cp16(d, kh + (size_t)r * DH + c * 8);
        cp16(d + AK_B, kl + (size_t)r * DH + c * 8);
    }
    const __half* vp = g_v + (size_t)bh * DH * TT + k0;
    for (int i = tid; i < 64 * (KT / 8); i += 256) {
        const int r = i >> 3, c = i & 7;
        const uint32_t d = st + 2 * AK_B + (uint32_t)(r * QPITCH + c * 8) * 2;
        cp16(d, vp + (size_t)r * TT + c * 8);
    }
}

__global__ void __launch_bounds__(256, 2) attn_mma()
{
    extern __shared__ char smem[];
    const uint32_t sb = smem_u32(smem);
    const uint32_t sQh = sb, sQl = sb + AQ_B;
    const uint32_t stage0 = sb + 2 * AQ_B;

    const int tid = threadIdx.x;
    const int wq = tid >> 5;
    const int lane = tid & 31;
    const int b = blockIdx.z, h = blockIdx.y;
    const int bh = b * HH + h;
    const int q0 = blockIdx.x * 128;

    {
        const __nv_bfloat16* qh = g_qT_hi + ((size_t)bh * TT + q0) * DH;
        const __nv_bfloat16* ql = g_qT_lo + ((size_t)bh * TT + q0) * DH;
        for (int i = tid; i < 128 * 8; i += 256) {
            const int r = i >> 3, c = i & 7;
            const uint32_t d = sQh + (uint32_t)(r * QPITCH + c * 8) * 2;
            cp16(d, qh + (size_t)r * DH + c * 8);
            cp16(d + AQ_B, ql + (size_t)r * DH + c * 8);
        }
        attn_load_stage(stage0, bh, 0, tid);
        cp_commit();
    }

    for (int s = 0; s < 2; s++) {
        char* vbase = smem + (2 * AQ_B + s * ASTAGE_B + 2 * AK_B);
        for (int i = tid; i < 8 * 32; i += 256) {
            const int r = i >> 5, c = i & 31;
            *(uint32_t*)(vbase + (size_t)(64 + r) * QPITCH * 2 + c * 4) =
                (r == 0) ? 0x3C003C00u : 0u;
        }
    }

    const int a_row = lane & 15;
    const int a_ksel = (lane >> 4) * 8;
    const int b4_row = lane & 7;
    const int b4_k = ((lane >> 3) & 1) * 8;
    const int b4_n = ((lane >> 4) & 1) * 8;
    const int l2_row = lane & 7;
    const int l2_k = ((lane >> 3) & 1) * 8;

    uint32_t qfh[4][4], qfl[4][4];
    float O[8][4], Oext[4];
    float m0 = -__int_as_float(0x7f800000), m1 = m0;
#pragma unroll
    for (int d = 0; d < 8; d++)
#pragma unroll
        for (int r = 0; r < 4; r++) O[d][r] = 0.0f;
#pragma unroll
    for (int r = 0; r < 4; r++) Oext[r] = 0.0f;

    for (int kt = 0; kt < NKT; kt++) {
        const uint32_t stb = stage0 + (uint32_t)(kt & 1) * ASTAGE_B;
        if (kt + 1 < NKT) {
            attn_load_stage(stage0 + (uint32_t)((kt + 1) & 1) * ASTAGE_B,
                            bh, (kt + 1) * KT, tid);
            cp_commit();
            asm volatile("cp.async.wait_group 1;\n" ::: "memory");
        } else {
            asm volatile("cp.async.wait_group 0;\n" ::: "memory");
        }
        __syncthreads();

        if (kt == 0) {
#pragma unroll
            for (int ks = 0; ks < 4; ks++) {
                const uint32_t off =
                    (uint32_t)((wq * 16 + a_row) * QPITCH + ks * 16 + a_ksel) * 2;
                ldmatrix_x4(qfh[ks][0], qfh[ks][1], qfh[ks][2], qfh[ks][3], sQh + off);
                ldmatrix_x4(qfl[ks][0], qfl[ks][1], qfl[ks][2], qfl[ks][3], sQl + off);
            }
        }

        float S[8][4];
#pragma unroll
        for (int n = 0; n < 8; n++)
#pragma unroll
            for (int r = 0; r < 4; r++) S[n][r] = 0.0f;

        const uint32_t Kh = stb, Kl = stb + AK_B;
#pragma unroll
        for (int np = 0; np < 4; np++) {
#pragma unroll
            for (int ks = 0; ks < 4; ks++) {
                const uint32_t off =
                    (uint32_t)((np * 16 + b4_n + b4_row) * QPITCH + ks * 16 + b4_k) * 2;
                uint32_t kh0, kh1, kh2, kh3, kl0, kl1, kl2, kl3;
                ldmatrix_x4(kh0, kh1, kh2, kh3, Kh + off);
                ldmatrix_x4(kl0, kl1, kl2, kl3, Kl + off);
                mma_bf16(S[2 * np], qfh[ks][0], qfh[ks][1], qfh[ks][2], qfh[ks][3], kh0, kh1);
                mma_bf16(S[2 * np], qfh[ks][0], qfh[ks][1], qfh[ks][2], qfh[ks][3], kl0, kl1);
                mma_bf16(S[2 * np], qfl[ks][0], qfl[ks][1], qfl[ks][2], qfl[ks][3], kh0, kh1);
                mma_bf16(S[2 * np + 1], qfh[ks][0], qfh[ks][1], qfh[ks][2], qfh[ks][3], kh2, kh3);
                mma_bf16(S[2 * np + 1], qfh[ks][0], qfh[ks][1], qfh[ks][2], qfh[ks][3], kl2, kl3);
                mma_bf16(S[2 * np + 1], qfl[ks][0], qfl[ks][1], qfl[ks][2], qfl[ks][3], kh2, kh3);
            }
        }

        float mx0 = -__int_as_float(0x7f800000), mx1 = mx0;
#pragma unroll
        for (int n = 0; n < 8; n++) {
            mx0 = fmaxf(mx0, fmaxf(S[n][0], S[n][1]));
            mx1 = fmaxf(mx1, fmaxf(S[n][2], S[n][3]));
        }
        mx0 = fmaxf(mx0, __shfl_xor_sync(0xffffffffu, mx0, 1));
        mx0 = fmaxf(mx0, __shfl_xor_sync(0xffffffffu, mx0, 2));
        mx1 = fmaxf(mx1, __shfl_xor_sync(0xffffffffu, mx1, 1));
        mx1 = fmaxf(mx1, __shfl_xor_sync(0xffffffffu, mx1, 2));
        const float mn0 = fmaxf(m0, mx0), mn1 = fmaxf(m1, mx1);
        const float al0 = exp2f(m0 - mn0), al1 = exp2f(m1 - mn1);
#pragma unroll
        for (int n = 0; n < 8; n++) {
            S[n][0] = exp2f(S[n][0] - mn0);
            S[n][1] = exp2f(S[n][1] - mn0);
            S[n][2] = exp2f(S[n][2] - mn1);
            S[n][3] = exp2f(S[n][3] - mn1);
        }
        m0 = mn0;
        m1 = mn1;
#pragma unroll
        for (int d = 0; d < 8; d++) {
            O[d][0] *= al0; O[d][1] *= al0;
            O[d][2] *= al1; O[d][3] *= al1;
        }
        Oext[0] *= al0; Oext[1] *= al0;
        Oext[2] *= al1; Oext[3] *= al1;

        const uint32_t Vs = stb + 2 * AK_B;
#pragma unroll
        for (int u = 0; u < 4; u++) {
            uint32_t ph[4];
            ph[0] = cvt2h(S[2 * u][0], S[2 * u][1]);
            ph[1] = cvt2h(S[2 * u][2], S[2 * u][3]);
            ph[2] = cvt2h(S[2 * u + 1][0], S[2 * u + 1][1]);
            ph[3] = cvt2h(S[2 * u + 1][2], S[2 * u + 1][3]);
#pragma unroll
            for (int dp = 0; dp < 4; dp++) {
                const uint32_t off =
                    (uint32_t)((dp * 16 + b4_n + b4_row) * QPITCH + u * 16 + b4_k) * 2;
                uint32_t vh0, vh1, vh2, vh3;
                ldmatrix_x4(vh0, vh1, vh2, vh3, Vs + off);
                mma_f16(O[2 * dp], ph[0], ph[1], ph[2], ph[3], vh0, vh1);
                mma_f16(O[2 * dp + 1], ph[0], ph[1], ph[2], ph[3], vh2, vh3);
            }
            {
                uint32_t e0, e1;
                const uint32_t off =
                    (uint32_t)((64 + l2_row) * QPITCH + u * 16 + l2_k) * 2;
                ldmatrix_x2(e0, e1, Vs + off);
                mma_f16(Oext, ph[0], ph[1], ph[2], ph[3], e0, e1);
            }
        }
        __syncthreads();
    }

    const float l0 = __shfl_sync(0xffffffffu, Oext[0], lane & 0x1c);
    const float l1 = __shfl_sync(0xffffffffu, Oext[2], lane & 0x1c);
    const float r0 = 1.0f / l0, r1 = 1.0f / l1;
    const int row0 = q0 + wq * 16 + (lane >> 2);
    const size_t base0 = ((size_t)b * TT + row0) * CC + h * DH;
    const size_t base1 = base0 + (size_t)8 * CC;
#pragma unroll
    for (int dn = 0; dn < 8; dn++) {
        const int col = dn * 8 + 2 * (lane & 3);
        *(uint32_t*)&g_cT[base0 + col] = cvt2h(O[dn][0] * r0, O[dn][1] * r0);
        *(uint32_t*)&g_cT[base1 + col] = cvt2h(O[dn][2] * r1, O[dn][3] * r1);
    }
}

// ===========================================================================
// LayerNorm: normalize-only
// ===========================================================================
__global__ void __launch_bounds__(256) ln_kernel(
    const float* __restrict__ gamma, const float* __restrict__ beta,
    float* __restrict__ out)
{
    const int tx = threadIdx.x, ty = threadIdx.y;
    const int b = blockIdx.y;
    const int t = blockIdx.x * 16 + tx;

    const float s = g_lnsum[(size_t)b * TT + t];
    const float q = g_lnsq[(size_t)b * TT + t];
    const float mu = s * (1.0f / CC);
    const float rstd = rsqrtf(q * (1.0f / CC) - mu * mu + LN_EPS);

    const float* yb = g_y + (size_t)b * CC * TT;
    float* ob = out + (size_t)b * CC * TT;
    for (int c = ty; c < CC; c += 16) {
        const float v = yb[(size_t)c * TT + t];
        ob[(size_t)c * TT + t] = (v - mu) * rstd * gamma[c] + beta[c];
    }
}

// ===========================================================================
extern "C" void kernel_launch(void* const* d_in, const int* in_sizes, int n_in,
                              void* d_out, int out_size)
{
    const float* x     = (const float*)d_in[0];
    const float* wqkv  = (const float*)d_in[1];
    const float* wfc   = (const float*)d_in[2];
    const float* gamma = (const float*)d_in[3];
    const float* beta  = (const float*)d_in[4];
    float* out = (float*)d_out;

    float* y;
    cudaGetSymbolAddress((void**)&y, g_y);
    __nv_bfloat16 *wqkh, *wqkl, *xth, *xtl;
    __half *wvh, *wvl, *wfh, *wfl, *xt16, *ct;
    cudaGetSymbolAddress((void**)&wqkh, g_wqk_hi);
    cudaGetSymbolAddress((void**)&wqkl, g_wqk_lo);
    cudaGetSymbolAddress((void**)&wvh, g_wv_hi);
    cudaGetSymbolAddress((void**)&wvl, g_wv_lo);
    cudaGetSymbolAddress((void**)&wfh, g_wfc_hi);
    cudaGetSymbolAddress((void**)&wfl, g_wfc_lo);
    cudaGetSymbolAddress((void**)&xth, g_xT_hi);
    cudaGetSymbolAddress((void**)&xtl, g_xT_lo);
    cudaGetSymbolAddress((void**)&xt16, g_xT_h16);
    cudaGetSymbolAddress((void**)&ct, g_cT);

    cudaFuncSetAttribute((const void*)qkv_fused, cudaFuncAttributeMaxDynamicSharedMemorySize, GEMM_SMEM0);
    cudaFuncSetAttribute((const void*)proj_gemm, cudaFuncAttributeMaxDynamicSharedMemorySize, GEMM_SMEM2);
    cudaFuncSetAttribute((const void*)attn_mma, cudaFuncAttributeMaxDynamicSharedMemorySize, ATTN_SMEM);

    // 0) fused prologue: x transpose-split + weight conversions + LN zero
    prologue_kernel<<<dim3(TT / 32 + CONVX, CC / 32, BB), dim3(32, 8)>>>(
        x, wqkv, wfc);

    // 1) merged QK (bf16 3-term) + V (fp16 asym) projections
    qkv_fused<<<dim3(TT / GM_NT, 3 * CC / GM_MT, BB), 256, GEMM_SMEM0>>>(
        (const uint16_t*)wqkh, (const uint16_t*)wqkl,
        (const uint16_t*)xth, (const uint16_t*)xtl,
        (const uint16_t*)wvh, (const uint16_t*)wvl, (const uint16_t*)xt16);

    // 2) flash attention (ones-row l) -> g_cT
    attn_mma<<<dim3(TT / 128, HH, BB), 256, ATTN_SMEM>>>();

    // 3) y = w_fc @ ctx + x (fp16 asym) + fused LN stats
    proj_gemm<<<dim3(TT / GM_NT, CC / GM_MT, BB), 256, GEMM_SMEM2>>>(
        (const uint16_t*)wfh, (const uint16_t*)wfl,
        (const uint16_t*)ct, x, y, (long)CC * TT);

    // 4) LayerNorm normalize-only -> out
    ln_kernel<<<dim3(TT / 16, BB), dim3(16, 16)>>>(gamma, beta, out);
}

// round 15
// speedup vs baseline: 1.0614x; 1.0170x over previous
#include <cuda_runtime.h>
#include <cuda_bf16.h>
#include <cuda_fp16.h>
#include <cstdint>

#define BB 2
#define CC 1024
#define TT 2048
#define HH 16
#define DH 64
#define LN_EPS 1e-6f
#define LOG2E 1.44269504088896340736f

// ---- dense GEMM tiling (KC=32, 2-stage, 2 CTAs/SM) ----
#define GM_MT 128
#define GM_NT 128
#define GM_KC 32
#define NCHUNK (CC / GM_KC)            // 32
#define PITCH 40
#define A_BYTES (GM_MT * PITCH * 2)     // 10240
#define B_BYTES (GM_NT * PITCH * 2)     // 10240
#define STAGE0_BYTES (2 * A_BYTES + 2 * B_BYTES)  // 40960
#define GEMM_SMEM0 (2 * STAGE0_BYTES)             // 81920
#define STAGE2_BYTES (2 * A_BYTES + B_BYTES)      // 30720
#define GEMM_SMEM2 (2 * STAGE2_BYTES)             // 61440

// ---- attention: kt-tile 64, V rows 0..63 + ones-row block 64..71 ----
#define QPITCH 72
#define KT 64
#define NKT (TT / KT)                   // 32
#define AQ_B (128 * QPITCH * 2)         // 18432
#define AK_B (KT * QPITCH * 2)          // 9216
#define AV_ROWS 72
#define ASTAGE_B (2 * AK_B + AV_ROWS * QPITCH * 2)  // 28800
#define ATTN_SMEM (2 * AQ_B + 2 * ASTAGE_B)          // 94464 -> 2 CTAs/SM

// conv work folded into tsplit grid
#define CONV_TOTAL ((size_t)4 * CC * CC + (size_t)BB * TT)
#define CONVX 257

// ---- scratch ----
__device__ __half g_y[(size_t)BB * CC * TT];         // pre-LN, fp16
__device__ float g_lnsum[(size_t)BB * TT];
__device__ float g_lnsq[(size_t)BB * TT];
__device__ __nv_bfloat16 g_wqk_hi[2 * CC * CC], g_wqk_lo[2 * CC * CC];
__device__ __half g_wv_hi[CC * CC], g_wv_lo[CC * CC];
__device__ __half g_wfc_hi[CC * CC], g_wfc_lo[CC * CC];
__device__ __nv_bfloat16 g_xT_hi[(size_t)BB * TT * CC], g_xT_lo[(size_t)BB * TT * CC];
__device__ __half g_xT_h16[(size_t)BB * TT * CC];
__device__ __half g_cT[(size_t)BB * TT * CC];
__device__ __nv_bfloat16 g_qT_hi[(size_t)BB * HH * TT * DH], g_qT_lo[(size_t)BB * HH * TT * DH];
__device__ __nv_bfloat16 g_kT_hi[(size_t)BB * HH * TT * DH], g_kT_lo[(size_t)BB * HH * TT * DH];
__device__ __half g_v[(size_t)BB * HH * DH * TT];

// ===========================================================================
__device__ __forceinline__ uint32_t smem_u32(const void* p) {
    return (uint32_t)__cvta_generic_to_shared(p);
}
__device__ __forceinline__ void cp16(uint32_t dst, const void* src) {
    asm volatile("cp.async.cg.shared.global [%0], [%1], 16;\n" :: "r"(dst), "l"(src));
}
__device__ __forceinline__ void cp_commit() {
    asm volatile("cp.async.commit_group;\n" ::: "memory");
}
__device__ __forceinline__ void ldmatrix_x4(uint32_t& a0, uint32_t& a1, uint32_t& a2,
                                            uint32_t& a3, uint32_t addr) {
    asm volatile("ldmatrix.sync.aligned.m8n8.x4.shared.b16 {%0,%1,%2,%3}, [%4];"
                 : "=r"(a0), "=r"(a1), "=r"(a2), "=r"(a3) : "r"(addr));
}
__device__ __forceinline__ void ldmatrix_x2(uint32_t& b0, uint32_t& b1, uint32_t addr) {
    asm volatile("ldmatrix.sync.aligned.m8n8.x2.shared.b16 {%0,%1}, [%2];"
                 : "=r"(b0), "=r"(b1) : "r"(addr));
}
__device__ __forceinline__ void mma_bf16(float* c,
                                         uint32_t a0, uint32_t a1, uint32_t a2, uint32_t a3,
                                         uint32_t b0, uint32_t b1) {
    asm volatile(
        "mma.sync.aligned.m16n8k16.row.col.f32.bf16.bf16.f32 "
        "{%0,%1,%2,%3}, {%4,%5,%6,%7}, {%8,%9}, {%0,%1,%2,%3};"
        : "+f"(c[0]), "+f"(c[1]), "+f"(c[2]), "+f"(c[3])
        : "r"(a0), "r"(a1), "r"(a2), "r"(a3), "r"(b0), "r"(b1));
}
__device__ __forceinline__ void mma_f16(float* c,
                                        uint32_t a0, uint32_t a1, uint32_t a2, uint32_t a3,
                                        uint32_t b0, uint32_t b1) {
    asm volatile(
        "mma.sync.aligned.m16n8k16.row.col.f32.f16.f16.f32 "
        "{%0,%1,%2,%3}, {%4,%5,%6,%7}, {%8,%9}, {%0,%1,%2,%3};"
        : "+f"(c[0]), "+f"(c[1]), "+f"(c[2]), "+f"(c[3])
        : "r"(a0), "r"(a1), "r"(a2), "r"(a3), "r"(b0), "r"(b1));
}
__device__ __forceinline__ uint32_t cvt2(float f0, float f1) {  // bf16x2
    uint32_t r;
    asm("cvt.rn.bf16x2.f32 %0, %1, %2;" : "=r"(r) : "f"(f1), "f"(f0));
    return r;
}
__device__ __forceinline__ void split2(float f0, float f1, uint32_t& hi, uint32_t& lo) {
    hi = cvt2(f0, f1);
    const float h0 = __uint_as_float(hi << 16);
    const float h1 = __uint_as_float(hi & 0xffff0000u);
    lo = cvt2(f0 - h0, f1 - h1);
}
__device__ __forceinline__ uint32_t cvt2h(float f0, float f1) {  // f16x2
    uint32_t r;
    asm("cvt.rn.f16x2.f32 %0, %1, %2;" : "=r"(r) : "f"(f1), "f"(f0));
    return r;
}

// ===========================================================================
// fused prologue: tsplit (blocks x<64) + weight conversions + lnzero (x>=64)
// ===========================================================================
__global__ void __launch_bounds__(256) prologue_kernel(
    const float* __restrict__ x, const float* __restrict__ wqkv,
    const float* __restrict__ wfc)
{
    if (blockIdx.x < TT / 32) {
        __shared__ float tile[32][33];
        const int b = blockIdx.z;
        const int t0 = blockIdx.x * 32, c0 = blockIdx.y * 32;
        const float* ib = x + (size_t)b * CC * TT;
        for (int j = threadIdx.y; j < 32; j += 8)
            tile[j][threadIdx.x] = ib[(size_t)(c0 + j) * TT + t0 + threadIdx.x];
        __syncthreads();
        __nv_bfloat16* hb = g_xT_hi + (size_t)b * TT * CC;
        __nv_bfloat16* lb = g_xT_lo + (size_t)b * TT * CC;
        __half* sb = g_xT_h16 + (size_t)b * TT * CC;
        for (int j = threadIdx.y; j < 32; j += 8) {
            const float v = tile[threadIdx.x][j];
            const __nv_bfloat16 h = __float2bfloat16(v);
            const size_t o = (size_t)(t0 + j) * CC + c0 + threadIdx.x;
            hb[o] = h;
            lb[o] = __float2bfloat16(v - __bfloat162float(h));
            sb[o] = __float2half_rn(v);
        }
    } else {
        const int tid = threadIdx.y * 32 + threadIdx.x;
        const size_t cid = (size_t)(blockIdx.x - TT / 32) +
                           (size_t)CONVX * (blockIdx.y + 32 * blockIdx.z);
        const size_t i = cid * 256 + tid;
        const size_t N1 = (size_t)2 * CC * CC;
        const size_t N2 = (size_t)CC * CC;
        if (i < N1) {
            const float v = wqkv[i];
            const __nv_bfloat16 h = __float2bfloat16(v);
            g_wqk_hi[i] = h;
            g_wqk_lo[i] = __float2bfloat16(v - __bfloat162float(h));
        } else if (i < N1 + N2) {
            const float v = wqkv[i];
            const size_t j = i - N1;
            const __half h = __float2half_rn(v);
            g_wv_hi[j] = h;
            g_wv_lo[j] = __float2half_rn(v - __half2float(h));
        } else if (i < N1 + 2 * N2) {
            const size_t j = i - N1 - N2;
            const float v = wfc[j];
            const __half h = __float2half_rn(v);
            g_wfc_hi[j] = h;
            g_wfc_lo[j] = __float2half_rn(v - __half2float(h));
        } else if (i < CONV_TOTAL) {
            const size_t j = i - N1 - 2 * N2;
            g_lnsum[j] = 0.0f;
            g_lnsq[j] = 0.0f;
        }
    }
}

// ===========================================================================
// shared GEMM core
// ===========================================================================
template <int MODE>
__device__ __forceinline__ void g_load_stage(
    uint32_t st, int kc,
    const uint16_t* __restrict__ Ahi, const uint16_t* __restrict__ Alo,
    const uint16_t* __restrict__ Bhi, const uint16_t* __restrict__ Blo,
    int m0, int n0, int tid)
{
    for (int i = tid; i < GM_MT * 4; i += 256) {
        const int r = i >> 2, c = i & 3;
        const uint32_t dst = st + (uint32_t)(r * PITCH + c * 8) * 2;
        const size_t g = (size_t)(m0 + r) * CC + kc + c * 8;
        cp16(dst, Ahi + g);
        cp16(dst + A_BYTES, Alo + g);
    }
    for (int i = tid; i < GM_NT * 4; i += 256) {
        const int r = i >> 2, c = i & 3;
        const uint32_t dst = st + 2 * A_BYTES + (uint32_t)(r * PITCH + c * 8) * 2;
        const size_t g = (size_t)(n0 + r) * CC + kc + c * 8;
        cp16(dst, Bhi + g);
        if (MODE == 0) cp16(dst + B_BYTES, Blo + g);
    }
    cp_commit();
}

template <int EPI, int MODE>
__device__ __forceinline__ void gemm_core(
    char* smem,
    const uint16_t* __restrict__ Ahi, const uint16_t* __restrict__ Alo,
    const uint16_t* __restrict__ BhiAll, const uint16_t* __restrict__ BloAll,
    const float* __restrict__ Res, __half* __restrict__ Cout,
    long outBatchStride, int by)
{
    const uint32_t sbase = smem_u32(smem);
    const uint32_t stageB = (MODE == 0) ? STAGE0_BYTES : STAGE2_BYTES;

    const int tid = threadIdx.x;
    const int wid = tid >> 5;
    const int lane = tid & 31;
    const int b = blockIdx.z;
    const int m0 = by * GM_MT;
    const int n0 = blockIdx.x * GM_NT;
    const int wm = (wid >> 2) * 64;
    const int wn = (wid & 3) * 32;

    const uint16_t* Bhi = BhiAll + (size_t)b * TT * CC;
    const uint16_t* Blo = (MODE == 0) ? (BloAll + (size_t)b * TT * CC) : nullptr;

    float acc[4][4][4];
#pragma unroll
    for (int i = 0; i < 4; i++)
#pragma unroll
        for (int j = 0; j < 4; j++)
#pragma unroll
            for (int r = 0; r < 4; r++) acc[i][j][r] = 0.0f;

    const int a_row = lane & 15;
    const int a_ksel = (lane >> 4) * 8;
    const int b4_row = lane & 7;
    const int b4_k = ((lane >> 3) & 1) * 8;
    const int b4_n = ((lane >> 4) & 1) * 8;

    g_load_stage<MODE>(sbase, 0, Ahi, Alo, Bhi, Blo, m0, n0, tid);

    for (int c = 0; c < NCHUNK; c++) {
        const uint32_t st = sbase + (uint32_t)(c & 1) * stageB;
        if (c + 1 < NCHUNK) {
            g_load_stage<MODE>(sbase + (uint32_t)((c + 1) & 1) * stageB,
                               (c + 1) * GM_KC, Ahi, Alo, Bhi, Blo, m0, n0, tid);
            asm volatile("cp.async.wait_group 1;\n" ::: "memory");
        } else {
            asm volatile("cp.async.wait_group 0;\n" ::: "memory");
        }
        __syncthreads();

        const uint32_t sAh = st;
        const uint32_t sAl = st + A_BYTES;
        const uint32_t sBh = st + 2 * A_BYTES;
        const uint32_t sBl = sBh + B_BYTES;

#pragma unroll
        for (int kk = 0; kk < GM_KC; kk += 16) {
            uint32_t ah[4][4], al[4][4], bh[4][2], bl[4][2];
#pragma unroll
            for (int mi = 0; mi < 4; mi++) {
                const uint32_t off =
                    (uint32_t)((wm + mi * 16 + a_row) * PITCH + kk + a_ksel) * 2;
                ldmatrix_x4(ah[mi][0], ah[mi][1], ah[mi][2], ah[mi][3], sAh + off);
                ldmatrix_x4(al[mi][0], al[mi][1], al[mi][2], al[mi][3], sAl + off);
            }
#pragma unroll
            for (int p = 0; p < 2; p++) {
                const uint32_t off =
                    (uint32_t)((wn + p * 16 + b4_n + b4_row) * PITCH + kk + b4_k) * 2;
                ldmatrix_x4(bh[2 * p][0], bh[2 * p][1], bh[2 * p + 1][0],
                            bh[2 * p + 1][1], sBh + off);
                if (MODE == 0)
                    ldmatrix_x4(bl[2 * p][0], bl[2 * p][1], bl[2 * p + 1][0],
                                bl[2 * p + 1][1], sBl + off);
            }
#pragma unroll
            for (int mi = 0; mi < 4; mi++)
#pragma unroll
                for (int nj = 0; nj < 4; nj++) {
                    float* a = acc[mi][nj];
                    if (MODE == 0) {
                        mma_bf16(a, ah[mi][0], ah[mi][1], ah[mi][2], ah[mi][3],
                                 bh[nj][0], bh[nj][1]);
                        mma_bf16(a, ah[mi][0], ah[mi][1], ah[mi][2], ah[mi][3],
                                 bl[nj][0], bl[nj][1]);
                        mma_bf16(a, al[mi][0], al[mi][1], al[mi][2], al[mi][3],
                                 bh[nj][0], bh[nj][1]);
                    } else {
                        mma_f16(a, ah[mi][0], ah[mi][1], ah[mi][2], ah[mi][3],
                                bh[nj][0], bh[nj][1]);
                        mma_f16(a, al[mi][0], al[mi][1], al[mi][2], al[mi][3],
                                bh[nj][0], bh[nj][1]);
                    }
                }
        }
        __syncthreads();
    }

    const int er = lane >> 2;
    const int ec = (lane & 3) * 2;

    if (EPI == 1) {
        // residual add + fp16 store + LN stats via shfl reduction (no smem atomics)
        float cs[8], cq[8];
#pragma unroll
        for (int i = 0; i < 8; i++) { cs[i] = 0.0f; cq[i] = 0.0f; }

        __half* Cb = Cout + (size_t)b * outBatchStride;
        const float* Rb = Res + (size_t)b * CC * TT;
#pragma unroll
        for (int mi = 0; mi < 4; mi++)
#pragma unroll
            for (int nj = 0; nj < 4; nj++) {
                const int m = m0 + wm + mi * 16 + er;
                const int n = n0 + wn + nj * 8 + ec;
                float2 v0 = make_float2(acc[mi][nj][0], acc[mi][nj][1]);
                float2 v1 = make_float2(acc[mi][nj][2], acc[mi][nj][3]);
                const float2 r0 = *(const float2*)(Rb + (size_t)m * TT + n);
                const float2 r1 = *(const float2*)(Rb + (size_t)(m + 8) * TT + n);
                v0.x += r0.x; v0.y += r0.y;
                v1.x += r1.x; v1.y += r1.y;
                *(uint32_t*)(Cb + (size_t)m * TT + n) = cvt2h(v0.x, v0.y);
                *(uint32_t*)(Cb + (size_t)(m + 8) * TT + n) = cvt2h(v1.x, v1.y);
                cs[nj * 2 + 0] += v0.x + v1.x;
                cq[nj * 2 + 0] += v0.x * v0.x + v1.x * v1.x;
                cs[nj * 2 + 1] += v0.y + v1.y;
                cq[nj * 2 + 1] += v0.y * v0.y + v1.y * v1.y;
            }
        // reduce over the 8 er-lanes (xor 4, 8, 16)
#pragma unroll
        for (int ci = 0; ci < 8; ci++) {
#pragma unroll
            for (int off = 4; off <= 16; off <<= 1) {
                cs[ci] += __shfl_xor_sync(0xffffffffu, cs[ci], off);
                cq[ci] += __shfl_xor_sync(0xffffffffu, cq[ci], off);
            }
        }
        float* lns = (float*)smem;       // [2][128]
        float* lnq = lns + 256;
        if (er == 0) {                   // lanes 0..3 hold full column sums
#pragma unroll
            for (int ci = 0; ci < 8; ci++) {
                const int idx = (wid >> 2) * 128 + wn + (ci >> 1) * 8 +
                                2 * lane + (ci & 1);
                lns[idx] = cs[ci];
                lnq[idx] = cq[ci];
            }
        }
        __syncthreads();
        if (tid < 128) {
            atomicAdd(&g_lnsum[(size_t)b * TT + n0 + tid], lns[tid] + lns[128 + tid]);
            atomicAdd(&g_lnsq[(size_t)b * TT + n0 + tid], lnq[tid] + lnq[128 + tid]);
        }
    } else if (EPI == 3) {
        uint32_t* vv = (uint32_t*)g_v;
#pragma unroll
        for (int mi = 0; mi < 4; mi++)
#pragma unroll
            for (int nj = 0; nj < 4; nj++) {
                const int n = n0 + wn + nj * 8 + ec;
#pragma unroll
                for (int rr = 0; rr < 2; rr++) {
                    const int ch = m0 + wm + mi * 16 + er + rr * 8;
                    const int bh = b * HH + (ch >> 6);
                    const int d = ch & 63;
                    vv[(((size_t)bh * DH + d) * TT + n) >> 1] =
                        cvt2h(acc[mi][nj][2 * rr], acc[mi][nj][2 * rr + 1]);
                }
            }
    } else {
        const bool isK = (m0 >= CC);
        const float qscale = isK ? 1.0f : LOG2E;
        const int chBase = isK ? (m0 - CC) : m0;
        const int h0 = chBase >> 6;
        float* stg = (float*)smem;
#pragma unroll
        for (int mi = 0; mi < 4; mi++)
#pragma unroll
            for (int nj = 0; nj < 4; nj++) {
                const int m = wm + mi * 16 + er;
                const int n = wn + nj * 8 + ec;
                stg[n * 129 + m] = acc[mi][nj][0];
                stg[(n + 1) * 129 + m] = acc[mi][nj][1];
                stg[n * 129 + m + 8] = acc[mi][nj][2];
                stg[(n + 1) * 129 + m + 8] = acc[mi][nj][3];
            }
        __syncthreads();
        uint32_t* dh = (uint32_t*)(isK ? g_kT_hi : g_qT_hi);
        uint32_t* dl = (uint32_t*)(isK ? g_kT_lo : g_qT_lo);
#pragma unroll
        for (int i = 0; i < 16; i++) {
            const int t = wid * 16 + i;
            const float* row = stg + t * 129;
#pragma unroll
            for (int half = 0; half < 2; half++) {
                const float v0 = row[half * 64 + 2 * lane] * qscale;
                const float v1 = row[half * 64 + 2 * lane + 1] * qscale;
                uint32_t hi, lo;
                split2(v0, v1, hi, lo);
                const size_t idx =
                    ((size_t)(b * HH + h0 + half) * TT + n0 + t) * 32 + lane;
                dh[idx] = hi;
                dl[idx] = lo;
            }
        }
    }
}

// merged QK + V projection launch (grid.y = 24)
__global__ void __launch_bounds__(256, 2) qkv_fused(
    const uint16_t* __restrict__ wqkh, const uint16_t* __restrict__ wqkl,
    const uint16_t* __restrict__ xth, const uint16_t* __restrict__ xtl,
    const uint16_t* __restrict__ wvh, const uint16_t* __restrict__ wvl,
    const uint16_t* __restrict__ xt16)
{
    extern __shared__ char smem[];
    if (blockIdx.y < 2 * CC / GM_MT) {
        gemm_core<2, 0>(smem, wqkh, wqkl, xth, xtl, nullptr, nullptr, 0,
                        blockIdx.y);
    } else {
        gemm_core<3, 2>(smem, wvh, wvl, xt16, nullptr, nullptr, nullptr, 0,
                        blockIdx.y - 2 * CC / GM_MT);
    }
}

// projection GEMM (+residual, +LN stats, fp16 y)
__global__ void __launch_bounds__(256, 2) proj_gemm(
    const uint16_t* __restrict__ Ahi, const uint16_t* __restrict__ Alo,
    const uint16_t* __restrict__ Bhi,
    const float* __restrict__ Res, __half* __restrict__ Cout, long outBatchStride)
{
    extern __shared__ char smem[];
    gemm_core<1, 2>(smem, Ahi, Alo, Bhi, nullptr, Res, Cout, outBatchStride,
                    blockIdx.y);
}

// ===========================================================================
// Flash attention + ones-row l-accumulation (round-13, unchanged)
// ===========================================================================
__device__ __forceinline__ void attn_load_stage(uint32_t st, int bh, int k0, int tid)
{
    const __nv_bfloat16* kh = g_kT_hi + ((size_t)bh * TT + k0) * DH;
    const __nv_bfloat16* kl = g_kT_lo + ((size_t)bh * TT + k0) * DH;
    for (int i = tid; i < KT * 8; i += 256) {
        const int r = i >> 3, c = i & 7;
        const uint32_t d = st + (uint32_t)(r * QPITCH + c * 8) * 2;
        cp16(d, kh + (size_t)r * DH + c * 8);
        cp16(d + AK_B, kl + (size_t)r * DH + c * 8);
    }
    const __half* vp = g_v + (size_t)bh * DH * TT + k0;
    for (int i = tid; i < 64 * (KT / 8); i += 256) {
        const int r = i >> 3, c = i & 7;
        const uint32_t d = st + 2 * AK_B + (uint32_t)(r * QPITCH + c * 8) * 2;
        cp16(d, vp + (size_t)r * TT + c * 8);
    }
}

__global__ void __launch_bounds__(256, 2) attn_mma()
{
    extern __shared__ char smem[];
    const uint32_t sb = smem_u32(smem);
    const uint32_t sQh = sb, sQl = sb + AQ_B;
    const uint32_t stage0 = sb + 2 * AQ_B;

    const int tid = threadIdx.x;
    const int wq = tid >> 5;
    const int lane = tid & 31;
    const int b = blockIdx.z, h = blockIdx.y;
    const int bh = b * HH + h;
    const int q0 = blockIdx.x * 128;

    {
        const __nv_bfloat16* qh = g_qT_hi + ((size_t)bh * TT + q0) * DH;
        const __nv_bfloat16* ql = g_qT_lo + ((size_t)bh * TT + q0) * DH;
        for (int i = tid; i < 128 * 8; i += 256) {
            const int r = i >> 3, c = i & 7;
            const uint32_t d = sQh + (uint32_t)(r * QPITCH + c * 8) * 2;
            cp16(d, qh + (size_t)r * DH + c * 8);
            cp16(d + AQ_B, ql + (size_t)r * DH + c * 8);
        }
        attn_load_stage(stage0, bh, 0, tid);
        cp_commit();
    }

    for (int s = 0; s < 2; s++) {
        char* vbase = smem + (2 * AQ_B + s * ASTAGE_B + 2 * AK_B);
        for (int i = tid; i < 8 * 32; i += 256) {
            const int r = i >> 5, c = i & 31;
            *(uint32_t*)(vbase + (size_t)(64 + r) * QPITCH * 2 + c * 4) =
                (r == 0) ? 0x3C003C00u : 0u;
        }
    }

    const int a_row = lane & 15;
    const int a_ksel = (lane >> 4) * 8;
    const int b4_row = lane & 7;
    const int b4_k = ((lane >> 3) & 1) * 8;
    const int b4_n = ((lane >> 4) & 1) * 8;
    const int l2_row = lane & 7;
    const int l2_k = ((lane >> 3) & 1) * 8;

    uint32_t qfh[4][4], qfl[4][4];
    float O[8][4], Oext[4];
    float m0 = -__int_as_float(0x7f800000), m1 = m0;
#pragma unroll
    for (int d = 0; d < 8; d++)
#pragma unroll
        for (int r = 0; r < 4; r++) O[d][r] = 0.0f;
#pragma unroll
    for (int r = 0; r < 4; r++) Oext[r] = 0.0f;

    for (int kt = 0; kt < NKT; kt++) {
        const uint32_t stb = stage0 + (uint32_t)(kt & 1) * ASTAGE_B;
        if (kt + 1 < NKT) {
            attn_load_stage(stage0 + (uint32_t)((kt + 1) & 1) * ASTAGE_B,
                            bh, (kt + 1) * KT, tid);
            cp_commit();
            asm volatile("cp.async.wait_group 1;\n" ::: "memory");
        } else {
            asm volatile("cp.async.wait_group 0;\n" ::: "memory");
        }
        __syncthreads();

        if (kt == 0) {
#pragma unroll
            for (int ks = 0; ks < 4; ks++) {
                const uint32_t off =
                    (uint32_t)((wq * 16 + a_row) * QPITCH + ks * 16 + a_ksel) * 2;
                ldmatrix_x4(qfh[ks][0], qfh[ks][1], qfh[ks][2], qfh[ks][3], sQh + off);
                ldmatrix_x4(qfl[ks][0], qfl[ks][1], qfl[ks][2], qfl[ks][3], sQl + off);
            }
        }

        float S[8][4];
#pragma unroll
        for (int n = 0; n < 8; n++)
#pragma unroll
            for (int r = 0; r < 4; r++) S[n][r] = 0.0f;

        const uint32_t Kh = stb, Kl = stb + AK_B;
#pragma unroll
        for (int np = 0; np < 4; np++) {
#pragma unroll
            for (int ks = 0; ks < 4; ks++) {
                const uint32_t off =
                    (uint32_t)((np * 16 + b4_n + b4_row) * QPITCH + ks * 16 + b4_k) * 2;
                uint32_t kh0, kh1, kh2, kh3, kl0, kl1, kl2, kl3;
                ldmatrix_x4(kh0, kh1, kh2, kh3, Kh + off);
                ldmatrix_x4(kl0, kl1, kl2, kl3, Kl + off);
                mma_bf16(S[2 * np], qfh[ks][0], qfh[ks][1], qfh[ks][2], qfh[ks][3], kh0, kh1);
                mma_bf16(S[2 * np], qfh[ks][0], qfh[ks][1], qfh[ks][2], qfh[ks][3], kl0, kl1);
                mma_bf16(S[2 * np], qfl[ks][0], qfl[ks][1], qfl[ks][2], qfl[ks][3], kh0, kh1);
                mma_bf16(S[2 * np + 1], qfh[ks][0], qfh[ks][1], qfh[ks][2], qfh[ks][3], kh2, kh3);
                mma_bf16(S[2 * np + 1], qfh[ks][0], qfh[ks][1], qfh[ks][2], qfh[ks][3], kl2, kl3);
                mma_bf16(S[2 * np + 1], qfl[ks][0], qfl[ks][1], qfl[ks][2], qfl[ks][3], kh2, kh3);
            }
        }

        float mx0 = -__int_as_float(0x7f800000), mx1 = mx0;
#pragma unroll
        for (int n = 0; n < 8; n++) {
            mx0 = fmaxf(mx0, fmaxf(S[n][0], S[n][1]));
            mx1 = fmaxf(mx1, fmaxf(S[n][2], S[n][3]));
        }
        mx0 = fmaxf(mx0, __shfl_xor_sync(0xffffffffu, mx0, 1));
        mx0 = fmaxf(mx0, __shfl_xor_sync(0xffffffffu, mx0, 2));
        mx1 = fmaxf(mx1, __shfl_xor_sync(0xffffffffu, mx1, 1));
        mx1 = fmaxf(mx1, __shfl_xor_sync(0xffffffffu, mx1, 2));
        const float mn0 = fmaxf(m0, mx0), mn1 = fmaxf(m1, mx1);
        const float al0 = exp2f(m0 - mn0), al1 = exp2f(m1 - mn1);
#pragma unroll
        for (int n = 0; n < 8; n++) {
            S[n][0] = exp2f(S[n][0] - mn0);
            S[n][1] = exp2f(S[n][1] - mn0);
            S[n][2] = exp2f(S[n][2] - mn1);
            S[n][3] = exp2f(S[n][3] - mn1);
        }
        m0 = mn0;
        m1 = mn1;
#pragma unroll
        for (int d = 0; d < 8; d++) {
            O[d][0] *= al0; O[d][1] *= al0;
            O[d][2] *= al1; O[d][3] *= al1;
        }
        Oext[0] *= al0; Oext[1] *= al0;
        Oext[2] *= al1; Oext[3] *= al1;

        const uint32_t Vs = stb + 2 * AK_B;
#pragma unroll
        for (int u = 0; u < 4; u++) {
            uint32_t ph[4];
            ph[0] = cvt2h(S[2 * u][0], S[2 * u][1]);
            ph[1] = cvt2h(S[2 * u][2], S[2 * u][3]);
            ph[2] = cvt2h(S[2 * u + 1][0], S[2 * u + 1][1]);
            ph[3] = cvt2h(S[2 * u + 1][2], S[2 * u + 1][3]);
#pragma unroll
            for (int dp = 0; dp < 4; dp++) {
                const uint32_t off =
                    (uint32_t)((dp * 16 + b4_n + b4_row) * QPITCH + u * 16 + b4_k) * 2;
                uint32_t vh0, vh1, vh2, vh3;
                ldmatrix_x4(vh0, vh1, vh2, vh3, Vs + off);
                mma_f16(O[2 * dp], ph[0], ph[1], ph[2], ph[3], vh0, vh1);
                mma_f16(O[2 * dp + 1], ph[0], ph[1], ph[2], ph[3], vh2, vh3);
            }
            {
                uint32_t e0, e1;
                const uint32_t off =
                    (uint32_t)((64 + l2_row) * QPITCH + u * 16 + l2_k) * 2;
                ldmatrix_x2(e0, e1, Vs + off);
                mma_f16(Oext, ph[0], ph[1], ph[2], ph[3], e0, e1);
            }
        }
        __syncthreads();
    }

    const float l0 = __shfl_sync(0xffffffffu, Oext[0], lane & 0x1c);
    const float l1 = __shfl_sync(0xffffffffu, Oext[2], lane & 0x1c);
    const float r0 = 1.0f / l0, r1 = 1.0f / l1;
    const int row0 = q0 + wq * 16 + (lane >> 2);
    const size_t base0 = ((size_t)b * TT + row0) * CC + h * DH;
    const size_t base1 = base0 + (size_t)8 * CC;
#pragma unroll
    for (int dn = 0; dn < 8; dn++) {
        const int col = dn * 8 + 2 * (lane & 3);
        *(uint32_t*)&g_cT[base0 + col] = cvt2h(O[dn][0] * r0, O[dn][1] * r0);
        *(uint32_t*)&g_cT[base1 + col] = cvt2h(O[dn][2] * r1, O[dn][3] * r1);
    }
}

// ===========================================================================
// LayerNorm: normalize-only (y is fp16)
// ===========================================================================
__global__ void __launch_bounds__(256) ln_kernel(
    const float* __restrict__ gamma, const float* __restrict__ beta,
    float* __restrict__ out)
{
    const int tx = threadIdx.x, ty = threadIdx.y;
    const int b = blockIdx.y;
    const int t = blockIdx.x * 16 + tx;

    const float s = g_lnsum[(size_t)b * TT + t];
    const float q = g_lnsq[(size_t)b * TT + t];
    const float mu = s * (1.0f / CC);
    const float rstd = rsqrtf(q * (1.0f / CC) - mu * mu + LN_EPS);

    const __half* yb = g_y + (size_t)b * CC * TT;
    float* ob = out + (size_t)b * CC * TT;
    for (int c = ty; c < CC; c += 16) {
        const float v = __half2float(yb[(size_t)c * TT + t]);
        ob[(size_t)c * TT + t] = (v - mu) * rstd * gamma[c] + beta[c];
    }
}

// ===========================================================================
extern "C" void kernel_launch(void* const* d_in, const int* in_sizes, int n_in,
                              void* d_out, int out_size)
{
    const float* x     = (const float*)d_in[0];
    const float* wqkv  = (const float*)d_in[1];
    const float* wfc   = (const float*)d_in[2];
    const float* gamma = (const float*)d_in[3];
    const float* beta  = (const float*)d_in[4];
    float* out = (float*)d_out;

    __half* y;
    cudaGetSymbolAddress((void**)&y, g_y);
    __nv_bfloat16 *wqkh, *wqkl, *xth, *xtl;
    __half *wvh, *wvl, *wfh, *wfl, *xt16, *ct;
    cudaGetSymbolAddress((void**)&wqkh, g_wqk_hi);
    cudaGetSymbolAddress((void**)&wqkl, g_wqk_lo);
    cudaGetSymbolAddress((void**)&wvh, g_wv_hi);
    cudaGetSymbolAddress((void**)&wvl, g_wv_lo);
    cudaGetSymbolAddress((void**)&wfh, g_wfc_hi);
    cudaGetSymbolAddress((void**)&wfl, g_wfc_lo);
    cudaGetSymbolAddress((void**)&xth, g_xT_hi);
    cudaGetSymbolAddress((void**)&xtl, g_xT_lo);
    cudaGetSymbolAddress((void**)&xt16, g_xT_h16);
    cudaGetSymbolAddress((void**)&ct, g_cT);

    cudaFuncSetAttribute((const void*)qkv_fused, cudaFuncAttributeMaxDynamicSharedMemorySize, GEMM_SMEM0);
    cudaFuncSetAttribute((const void*)proj_gemm, cudaFuncAttributeMaxDynamicSharedMemorySize, GEMM_SMEM2);
    cudaFuncSetAttribute((const void*)attn_mma, cudaFuncAttributeMaxDynamicSharedMemorySize, ATTN_SMEM);

    // 0) fused prologue
    prologue_kernel<<<dim3(TT / 32 + CONVX, CC / 32, BB), dim3(32, 8)>>>(
        x, wqkv, wfc);

    // 1) merged QK (bf16 3-term) + V (fp16 asym) projections
    qkv_fused<<<dim3(TT / GM_NT, 3 * CC / GM_MT, BB), 256, GEMM_SMEM0>>>(
        (const uint16_t*)wqkh, (const uint16_t*)wqkl,
        (const uint16_t*)xth, (const uint16_t*)xtl,
        (const uint16_t*)wvh, (const uint16_t*)wvl, (const uint16_t*)xt16);

    // 2) flash attention (ones-row l) -> g_cT
    attn_mma<<<dim3(TT / 128, HH, BB), 256, ATTN_SMEM>>>();

    // 3) y = w_fc @ ctx + x -> fp16 y + fused LN stats (shfl-reduced)
    proj_gemm<<<dim3(TT / GM_NT, CC / GM_MT, BB), 256, GEMM_SMEM2>>>(
        (const uint16_t*)wfh, (const uint16_t*)wfl,
        (const uint16_t*)ct, x, y, (long)CC * TT);

    // 4) LayerNorm normalize-only -> out
    ln_kernel<<<dim3(TT / 16, BB), dim3(16, 16)>>>(gamma, beta, out);
}

// round 16
// speedup vs baseline: 1.0742x; 1.0121x over previous
#include <cuda_runtime.h>
#include <cuda_bf16.h>
#include <cuda_fp16.h>
#include <cstdint>

#define BB 2
#define CC 1024
#define TT 2048
#define HH 16
#define DH 64
#define LN_EPS 1e-6f
#define LOG2E 1.44269504088896340736f

// ---- dense GEMM tiling (KC=32, 2-stage, 2 CTAs/SM) ----
#define GM_MT 128
#define GM_NT 128
#define GM_KC 32
#define NCHUNK (CC / GM_KC)            // 32
#define PITCH 40
#define A_BYTES (GM_MT * PITCH * 2)     // 10240
#define B_BYTES (GM_NT * PITCH * 2)     // 10240
#define STAGE0_BYTES (2 * A_BYTES + 2 * B_BYTES)  // 40960 (A hi/lo + B hi/lo)
#define GEMM_SMEM0 (2 * STAGE0_BYTES)             // 81920
#define STAGE2_BYTES (2 * A_BYTES + B_BYTES)      // 30720 (A hi/lo + B single)
#define GEMM_SMEM2 (2 * STAGE2_BYTES)             // 61440
#define STAGE3_BYTES (A_BYTES + 2 * B_BYTES)      // 30720 (A single + B hi/lo)
#define GEMM_SMEM3 (2 * STAGE3_BYTES)             // 61440

// ---- attention: kt-tile 64, V rows 0..63 + ones-row block 64..71 ----
#define QPITCH 72
#define KT 64
#define NKT (TT / KT)                   // 32
#define AQ_B (128 * QPITCH * 2)         // 18432
#define AK_B (KT * QPITCH * 2)          // 9216
#define AV_ROWS 72
#define ASTAGE_B (2 * AK_B + AV_ROWS * QPITCH * 2)  // 28800
#define ATTN_SMEM (2 * AQ_B + 2 * ASTAGE_B)          // 94464 -> 2 CTAs/SM

// conv work folded into tsplit grid
#define CONV_TOTAL ((size_t)4 * CC * CC + (size_t)BB * TT)
#define CONVX 257

// ---- scratch ----
__device__ __half g_y[(size_t)BB * TT * CC];         // pre-LN, fp16, [b][t][c]
__device__ float g_lnsum[(size_t)BB * TT];
__device__ float g_lnsq[(size_t)BB * TT];
__device__ __nv_bfloat16 g_wqk_hi[2 * CC * CC], g_wqk_lo[2 * CC * CC];
__device__ __half g_wv_hi[CC * CC], g_wv_lo[CC * CC];
__device__ __half g_wfc_hi[CC * CC], g_wfc_lo[CC * CC];
__device__ __nv_bfloat16 g_xT_hi[(size_t)BB * TT * CC], g_xT_lo[(size_t)BB * TT * CC];
__device__ __half g_xT_h16[(size_t)BB * TT * CC];
__device__ __half g_cT[(size_t)BB * TT * CC];
__device__ __nv_bfloat16 g_qT_hi[(size_t)BB * HH * TT * DH], g_qT_lo[(size_t)BB * HH * TT * DH];
__device__ __nv_bfloat16 g_kT_hi[(size_t)BB * HH * TT * DH], g_kT_lo[(size_t)BB * HH * TT * DH];
__device__ __half g_v[(size_t)BB * HH * DH * TT];

// ===========================================================================
__device__ __forceinline__ uint32_t smem_u32(const void* p) {
    return (uint32_t)__cvta_generic_to_shared(p);
}
__device__ __forceinline__ void cp16(uint32_t dst, const void* src) {
    asm volatile("cp.async.cg.shared.global [%0], [%1], 16;\n" :: "r"(dst), "l"(src));
}
__device__ __forceinline__ void cp_commit() {
    asm volatile("cp.async.commit_group;\n" ::: "memory");
}
__device__ __forceinline__ void ldmatrix_x4(uint32_t& a0, uint32_t& a1, uint32_t& a2,
                                            uint32_t& a3, uint32_t addr) {
    asm volatile("ldmatrix.sync.aligned.m8n8.x4.shared.b16 {%0,%1,%2,%3}, [%4];"
                 : "=r"(a0), "=r"(a1), "=r"(a2), "=r"(a3) : "r"(addr));
}
__device__ __forceinline__ void ldmatrix_x2(uint32_t& b0, uint32_t& b1, uint32_t addr) {
    asm volatile("ldmatrix.sync.aligned.m8n8.x2.shared.b16 {%0,%1}, [%2];"
                 : "=r"(b0), "=r"(b1) : "r"(addr));
}
__device__ __forceinline__ void mma_bf16(float* c,
                                         uint32_t a0, uint32_t a1, uint32_t a2, uint32_t a3,
                                         uint32_t b0, uint32_t b1) {
    asm volatile(
        "mma.sync.aligned.m16n8k16.row.col.f32.bf16.bf16.f32 "
        "{%0,%1,%2,%3}, {%4,%5,%6,%7}, {%8,%9}, {%0,%1,%2,%3};"
        : "+f"(c[0]), "+f"(c[1]), "+f"(c[2]), "+f"(c[3])
        : "r"(a0), "r"(a1), "r"(a2), "r"(a3), "r"(b0), "r"(b1));
}
__device__ __forceinline__ void mma_f16(float* c,
                                        uint32_t a0, uint32_t a1, uint32_t a2, uint32_t a3,
                                        uint32_t b0, uint32_t b1) {
    asm volatile(
        "mma.sync.aligned.m16n8k16.row.col.f32.f16.f16.f32 "
        "{%0,%1,%2,%3}, {%4,%5,%6,%7}, {%8,%9}, {%0,%1,%2,%3};"
        : "+f"(c[0]), "+f"(c[1]), "+f"(c[2]), "+f"(c[3])
        : "r"(a0), "r"(a1), "r"(a2), "r"(a3), "r"(b0), "r"(b1));
}
__device__ __forceinline__ uint32_t cvt2(float f0, float f1) {  // bf16x2
    uint32_t r;
    asm("cvt.rn.bf16x2.f32 %0, %1, %2;" : "=r"(r) : "f"(f1), "f"(f0));
    return r;
}
__device__ __forceinline__ void split2(float f0, float f1, uint32_t& hi, uint32_t& lo) {
    hi = cvt2(f0, f1);
    const float h0 = __uint_as_float(hi << 16);
    const float h1 = __uint_as_float(hi & 0xffff0000u);
    lo = cvt2(f0 - h0, f1 - h1);
}
__device__ __forceinline__ uint32_t cvt2h(float f0, float f1) {  // f16x2
    uint32_t r;
    asm("cvt.rn.f16x2.f32 %0, %1, %2;" : "=r"(r) : "f"(f1), "f"(f0));
    return r;
}

// ===========================================================================
// fused prologue
// ===========================================================================
__global__ void __launch_bounds__(256) prologue_kernel(
    const float* __restrict__ x, const float* __restrict__ wqkv,
    const float* __restrict__ wfc)
{
    if (blockIdx.x < TT / 32) {
        __shared__ float tile[32][33];
        const int b = blockIdx.z;
        const int t0 = blockIdx.x * 32, c0 = blockIdx.y * 32;
        const float* ib = x + (size_t)b * CC * TT;
        for (int j = threadIdx.y; j < 32; j += 8)
            tile[j][threadIdx.x] = ib[(size_t)(c0 + j) * TT + t0 + threadIdx.x];
        __syncthreads();
        __nv_bfloat16* hb = g_xT_hi + (size_t)b * TT * CC;
        __nv_bfloat16* lb = g_xT_lo + (size_t)b * TT * CC;
        __half* sb = g_xT_h16 + (size_t)b * TT * CC;
        for (int j = threadIdx.y; j < 32; j += 8) {
            const float v = tile[threadIdx.x][j];
            const __nv_bfloat16 h = __float2bfloat16(v);
            const size_t o = (size_t)(t0 + j) * CC + c0 + threadIdx.x;
            hb[o] = h;
            lb[o] = __float2bfloat16(v - __bfloat162float(h));
            sb[o] = __float2half_rn(v);
        }
    } else {
        const int tid = threadIdx.y * 32 + threadIdx.x;
        const size_t cid = (size_t)(blockIdx.x - TT / 32) +
                           (size_t)CONVX * (blockIdx.y + 32 * blockIdx.z);
        const size_t i = cid * 256 + tid;
        const size_t N1 = (size_t)2 * CC * CC;
        const size_t N2 = (size_t)CC * CC;
        if (i < N1) {
            const float v = wqkv[i];
            const __nv_bfloat16 h = __float2bfloat16(v);
            g_wqk_hi[i] = h;
            g_wqk_lo[i] = __float2bfloat16(v - __bfloat162float(h));
        } else if (i < N1 + N2) {
            const float v = wqkv[i];
            const size_t j = i - N1;
            const __half h = __float2half_rn(v);
            g_wv_hi[j] = h;
            g_wv_lo[j] = __float2half_rn(v - __half2float(h));
        } else if (i < N1 + 2 * N2) {
            const size_t j = i - N1 - N2;
            const float v = wfc[j];
            const __half h = __float2half_rn(v);
            g_wfc_hi[j] = h;
            g_wfc_lo[j] = __float2half_rn(v - __half2float(h));
        } else if (i < CONV_TOTAL) {
            const size_t j = i - N1 - 2 * N2;
            g_lnsum[j] = 0.0f;
            g_lnsq[j] = 0.0f;
        }
    }
}

// ===========================================================================
// shared GEMM core.
// MODE 0: A hi/lo + B hi/lo (bf16, 3 mma)
// MODE 2: A hi/lo + B single (fp16, 2 mma)
// MODE 3: A single + B hi/lo (fp16, 2 mma)  [A batched, B not]
// EPI 2 = Q/K attention epi; EPI 3 = V epi; EPI 4 = transposed proj epi
// ===========================================================================
template <int MODE>
__device__ __forceinline__ void g_load_stage(
    uint32_t st, int kc,
    const uint16_t* __restrict__ Ahi, const uint16_t* __restrict__ Alo,
    const uint16_t* __restrict__ Bhi, const uint16_t* __restrict__ Blo,
    int m0, int n0, int tid)
{
    const uint32_t bOff = (MODE == 3) ? A_BYTES : 2 * A_BYTES;
    for (int i = tid; i < GM_MT * 4; i += 256) {
        const int r = i >> 2, c = i & 3;
        const uint32_t dst = st + (uint32_t)(r * PITCH + c * 8) * 2;
        const size_t g = (size_t)(m0 + r) * CC + kc + c * 8;
        cp16(dst, Ahi + g);
        if (MODE != 3) cp16(dst + A_BYTES, Alo + g);
    }
    for (int i = tid; i < GM_NT * 4; i += 256) {
        const int r = i >> 2, c = i & 3;
        const uint32_t dst = st + bOff + (uint32_t)(r * PITCH + c * 8) * 2;
        const size_t g = (size_t)(n0 + r) * CC + kc + c * 8;
        cp16(dst, Bhi + g);
        if (MODE == 0 || MODE == 3) cp16(dst + B_BYTES, Blo + g);
    }
    cp_commit();
}

template <int EPI, int MODE>
__device__ __forceinline__ void gemm_core(
    char* smem,
    const uint16_t* __restrict__ AhiIn, const uint16_t* __restrict__ AloIn,
    const uint16_t* __restrict__ BhiIn, const uint16_t* __restrict__ BloIn,
    __half* __restrict__ Cout, long outBatchStride, int by)
{
    const uint32_t sbase = smem_u32(smem);
    const uint32_t stageB = (MODE == 0) ? STAGE0_BYTES
                          : (MODE == 2) ? STAGE2_BYTES : STAGE3_BYTES;

    const int tid = threadIdx.x;
    const int wid = tid >> 5;
    const int lane = tid & 31;
    const int b = blockIdx.z;
    const int m0 = by * GM_MT;
    const int n0 = blockIdx.x * GM_NT;
    const int wm = (wid >> 2) * 64;
    const int wn = (wid & 3) * 32;

    // MODE 3: A batched, B not; otherwise the reverse.
    const uint16_t* Ahi = AhiIn + ((MODE == 3) ? (size_t)b * TT * CC : 0);
    const uint16_t* Alo = (MODE != 3)
        ? AloIn : nullptr;
    const uint16_t* Bhi = BhiIn + ((MODE == 3) ? 0 : (size_t)b * TT * CC);
    const uint16_t* Blo = (MODE == 0) ? (BloIn + (size_t)b * TT * CC)
                        : (MODE == 3) ? BloIn : nullptr;

    float acc[4][4][4];
#pragma unroll
    for (int i = 0; i < 4; i++)
#pragma unroll
        for (int j = 0; j < 4; j++)
#pragma unroll
            for (int r = 0; r < 4; r++) acc[i][j][r] = 0.0f;

    const int a_row = lane & 15;
    const int a_ksel = (lane >> 4) * 8;
    const int b4_row = lane & 7;
    const int b4_k = ((lane >> 3) & 1) * 8;
    const int b4_n = ((lane >> 4) & 1) * 8;

    g_load_stage<MODE>(sbase, 0, Ahi, Alo, Bhi, Blo, m0, n0, tid);

    for (int c = 0; c < NCHUNK; c++) {
        const uint32_t st = sbase + (uint32_t)(c & 1) * stageB;
        if (c + 1 < NCHUNK) {
            g_load_stage<MODE>(sbase + (uint32_t)((c + 1) & 1) * stageB,
                               (c + 1) * GM_KC, Ahi, Alo, Bhi, Blo, m0, n0, tid);
            asm volatile("cp.async.wait_group 1;\n" ::: "memory");
        } else {
            asm volatile("cp.async.wait_group 0;\n" ::: "memory");
        }
        __syncthreads();

        const uint32_t sAh = st;
        const uint32_t sAl = st + A_BYTES;
        const uint32_t sBh = st + ((MODE == 3) ? A_BYTES : 2 * A_BYTES);
        const uint32_t sBl = sBh + B_BYTES;

#pragma unroll
        for (int kk = 0; kk < GM_KC; kk += 16) {
            uint32_t ah[4][4], al[4][4], bh[4][2], bl[4][2];
#pragma unroll
            for (int mi = 0; mi < 4; mi++) {
                const uint32_t off =
                    (uint32_t)((wm + mi * 16 + a_row) * PITCH + kk + a_ksel) * 2;
                ldmatrix_x4(ah[mi][0], ah[mi][1], ah[mi][2], ah[mi][3], sAh + off);
                if (MODE != 3)
                    ldmatrix_x4(al[mi][0], al[mi][1], al[mi][2], al[mi][3], sAl + off);
            }
#pragma unroll
            for (int p = 0; p < 2; p++) {
                const uint32_t off =
                    (uint32_t)((wn + p * 16 + b4_n + b4_row) * PITCH + kk + b4_k) * 2;
                ldmatrix_x4(bh[2 * p][0], bh[2 * p][1], bh[2 * p + 1][0],
                            bh[2 * p + 1][1], sBh + off);
                if (MODE == 0 || MODE == 3)
                    ldmatrix_x4(bl[2 * p][0], bl[2 * p][1], bl[2 * p + 1][0],
                                bl[2 * p + 1][1], sBl + off);
            }
#pragma unroll
            for (int mi = 0; mi < 4; mi++)
#pragma unroll
                for (int nj = 0; nj < 4; nj++) {
                    float* a = acc[mi][nj];
                    if (MODE == 0) {
                        mma_bf16(a, ah[mi][0], ah[mi][1], ah[mi][2], ah[mi][3],
                                 bh[nj][0], bh[nj][1]);
                        mma_bf16(a, ah[mi][0], ah[mi][1], ah[mi][2], ah[mi][3],
                                 bl[nj][0], bl[nj][1]);
                        mma_bf16(a, al[mi][0], al[mi][1], al[mi][2], al[mi][3],
                                 bh[nj][0], bh[nj][1]);
                    } else if (MODE == 2) {
                        mma_f16(a, ah[mi][0], ah[mi][1], ah[mi][2], ah[mi][3],
                                bh[nj][0], bh[nj][1]);
                        mma_f16(a, al[mi][0], al[mi][1], al[mi][2], al[mi][3],
                                bh[nj][0], bh[nj][1]);
                    } else {
                        mma_f16(a, ah[mi][0], ah[mi][1], ah[mi][2], ah[mi][3],
                                bh[nj][0], bh[nj][1]);
                        mma_f16(a, ah[mi][0], ah[mi][1], ah[mi][2], ah[mi][3],
                                bl[nj][0], bl[nj][1]);
                    }
                }
        }
        __syncthreads();
    }

    const int er = lane >> 2;
    const int ec = (lane & 3) * 2;

    if (EPI == 4) {
        // transposed proj: m = t rows, n = c cols; residual from xT fp16;
        // y^T fp16 + per-row LN stats (quad-shfl reduced, 1 atomic per row)
        float rs[4][2], rq[4][2];
#pragma unroll
        for (int mi = 0; mi < 4; mi++) {
            rs[mi][0] = rs[mi][1] = 0.0f;
            rq[mi][0] = rq[mi][1] = 0.0f;
        }
        __half* Cb = Cout + (size_t)b * outBatchStride;
        const __half* Rb = g_xT_h16 + (size_t)b * TT * CC;
#pragma unroll
        for (int mi = 0; mi < 4; mi++)
#pragma unroll
            for (int nj = 0; nj < 4; nj++) {
                const int m = m0 + wm + mi * 16 + er;
                const int n = n0 + wn + nj * 8 + ec;
                const __half2 rA = *(const __half2*)(Rb + (size_t)m * CC + n);
                const __half2 rB = *(const __half2*)(Rb + (size_t)(m + 8) * CC + n);
                const float v0x = acc[mi][nj][0] + __half2float(rA.x);
                const float v0y = acc[mi][nj][1] + __half2float(rA.y);
                const float v1x = acc[mi][nj][2] + __half2float(rB.x);
                const float v1y = acc[mi][nj][3] + __half2float(rB.y);
                *(uint32_t*)(Cb + (size_t)m * CC + n) = cvt2h(v0x, v0y);
                *(uint32_t*)(Cb + (size_t)(m + 8) * CC + n) = cvt2h(v1x, v1y);
                rs[mi][0] += v0x + v0y;
                rq[mi][0] += v0x * v0x + v0y * v0y;
                rs[mi][1] += v1x + v1y;
                rq[mi][1] += v1x * v1x + v1y * v1y;
            }
#pragma unroll
        for (int mi = 0; mi < 4; mi++)
#pragma unroll
            for (int r2 = 0; r2 < 2; r2++) {
                rs[mi][r2] += __shfl_xor_sync(0xffffffffu, rs[mi][r2], 1);
                rs[mi][r2] += __shfl_xor_sync(0xffffffffu, rs[mi][r2], 2);
                rq[mi][r2] += __shfl_xor_sync(0xffffffffu, rq[mi][r2], 1);
                rq[mi][r2] += __shfl_xor_sync(0xffffffffu, rq[mi][r2], 2);
            }
        float* rows_s = (float*)smem;       // [128][4]
        float* rowq_s = rows_s + 512;       // [128][4]
        if ((lane & 3) == 0) {
#pragma unroll
            for (int mi = 0; mi < 4; mi++)
#pragma unroll
                for (int r2 = 0; r2 < 2; r2++) {
                    const int rl = (wid >> 2) * 64 + mi * 16 + er + r2 * 8;
                    rows_s[rl * 4 + (wid & 3)] = rs[mi][r2];
                    rowq_s[rl * 4 + (wid & 3)] = rq[mi][r2];
                }
        }
        __syncthreads();
        if (tid < 128) {
            const float s = rows_s[tid * 4] + rows_s[tid * 4 + 1] +
                            rows_s[tid * 4 + 2] + rows_s[tid * 4 + 3];
            const float q = rowq_s[tid * 4] + rowq_s[tid * 4 + 1] +
                            rowq_s[tid * 4 + 2] + rowq_s[tid * 4 + 3];
            atomicAdd(&g_lnsum[(size_t)b * TT + m0 + tid], s);
            atomicAdd(&g_lnsq[(size_t)b * TT + m0 + tid], q);
        }
    } else if (EPI == 3) {
        uint32_t* vv = (uint32_t*)g_v;
#pragma unroll
        for (int mi = 0; mi < 4; mi++)
#pragma unroll
            for (int nj = 0; nj < 4; nj++) {
                const int n = n0 + wn + nj * 8 + ec;
#pragma unroll
                for (int rr = 0; rr < 2; rr++) {
                    const int ch = m0 + wm + mi * 16 + er + rr * 8;
                    const int bh2 = b * HH + (ch >> 6);
                    const int d = ch & 63;
                    vv[(((size_t)bh2 * DH + d) * TT + n) >> 1] =
                        cvt2h(acc[mi][nj][2 * rr], acc[mi][nj][2 * rr + 1]);
                }
            }
    } else {
        const bool isK = (m0 >= CC);
        const float qscale = isK ? 1.0f : LOG2E;
        const int chBase = isK ? (m0 - CC) : m0;
        const int h0 = chBase >> 6;
        float* stg = (float*)smem;
#pragma unroll
        for (int mi = 0; mi < 4; mi++)
#pragma unroll
            for (int nj = 0; nj < 4; nj++) {
                const int m = wm + mi * 16 + er;
                const int n = wn + nj * 8 + ec;
                stg[n * 129 + m] = acc[mi][nj][0];
                stg[(n + 1) * 129 + m] = acc[mi][nj][1];
                stg[n * 129 + m + 8] = acc[mi][nj][2];
                stg[(n + 1) * 129 + m + 8] = acc[mi][nj][3];
            }
        __syncthreads();
        uint32_t* dh = (uint32_t*)(isK ? g_kT_hi : g_qT_hi);
        uint32_t* dl = (uint32_t*)(isK ? g_kT_lo : g_qT_lo);
#pragma unroll
        for (int i = 0; i < 16; i++) {
            const int t = wid * 16 + i;
            const float* row = stg + t * 129;
#pragma unroll
            for (int half = 0; half < 2; half++) {
                const float v0 = row[half * 64 + 2 * lane] * qscale;
                const float v1 = row[half * 64 + 2 * lane + 1] * qscale;
                uint32_t hi, lo;
                split2(v0, v1, hi, lo);
                const size_t idx =
                    ((size_t)(b * HH + h0 + half) * TT + n0 + t) * 32 + lane;
                dh[idx] = hi;
                dl[idx] = lo;
            }
        }
    }
}

// merged QK + V projection launch (grid.y = 24)
__global__ void __launch_bounds__(256, 2) qkv_fused(
    const uint16_t* __restrict__ wqkh, const uint16_t* __restrict__ wqkl,
    const uint16_t* __restrict__ xth, const uint16_t* __restrict__ xtl,
    const uint16_t* __restrict__ wvh, const uint16_t* __restrict__ wvl,
    const uint16_t* __restrict__ xt16)
{
    extern __shared__ char smem[];
    if (blockIdx.y < 2 * CC / GM_MT) {
        gemm_core<2, 0>(smem, wqkh, wqkl, xth, xtl, nullptr, 0, blockIdx.y);
    } else {
        gemm_core<3, 2>(smem, wvh, wvl, xt16, nullptr, nullptr, 0,
                        blockIdx.y - 2 * CC / GM_MT);
    }
}

// transposed projection GEMM: y^T = ct @ wfc^T (+x^T residual, +LN row stats)
__global__ void __launch_bounds__(256, 2) proj_gemm(
    const uint16_t* __restrict__ ct,
    const uint16_t* __restrict__ wfh, const uint16_t* __restrict__ wfl,
    __half* __restrict__ Cout, long outBatchStride)
{
    extern __shared__ char smem[];
    gemm_core<4, 3>(smem, ct, nullptr, wfh, wfl, Cout, outBatchStride,
                    blockIdx.y);
}

// ===========================================================================
// Flash attention + ones-row l-accumulation (unchanged)
// ===========================================================================
__device__ __forceinline__ void attn_load_stage(uint32_t st, int bh, int k0, int tid)
{
    const __nv_bfloat16* kh = g_kT_hi + ((size_t)bh * TT + k0) * DH;
    const __nv_bfloat16* kl = g_kT_lo + ((size_t)bh * TT + k0) * DH;
    for (int i = tid; i < KT * 8; i += 256) {
        const int r = i >> 3, c = i & 7;
        const uint32_t d = st + (uint32_t)(r * QPITCH + c * 8) * 2;
        cp16(d, kh + (size_t)r * DH + c * 8);
        cp16(d + AK_B, kl + (size_t)r * DH + c * 8);
    }
    const __half* vp = g_v + (size_t)bh * DH * TT + k0;
    for (int i = tid; i < 64 * (KT / 8); i += 256) {
        const int r = i >> 3, c = i & 7;
        const uint32_t d = st + 2 * AK_B + (uint32_t)(r * QPITCH + c * 8) * 2;
        cp16(d, vp + (size_t)r * TT + c * 8);
    }
}

__global__ void __launch_bounds__(256, 2) attn_mma()
{
    extern __shared__ char smem[];
    const uint32_t sb = smem_u32(smem);
    const uint32_t sQh = sb, sQl = sb + AQ_B;
    const uint32_t stage0 = sb + 2 * AQ_B;

    const int tid = threadIdx.x;
    const int wq = tid >> 5;
    const int lane = tid & 31;
    const int b = blockIdx.z, h = blockIdx.y;
    const int bh = b * HH + h;
    const int q0 = blockIdx.x * 128;

    {
        const __nv_bfloat16* qh = g_qT_hi + ((size_t)bh * TT + q0) * DH;
        const __nv_bfloat16* ql = g_qT_lo + ((size_t)bh * TT + q0) * DH;
        for (int i = tid; i < 128 * 8; i += 256) {
            const int r = i >> 3, c = i & 7;
            const uint32_t d = sQh + (uint32_t)(r * QPITCH + c * 8) * 2;
            cp16(d, qh + (size_t)r * DH + c * 8);
            cp16(d + AQ_B, ql + (size_t)r * DH + c * 8);
        }
        attn_load_stage(stage0, bh, 0, tid);
        cp_commit();
    }

    for (int s = 0; s < 2; s++) {
        char* vbase = smem + (2 * AQ_B + s * ASTAGE_B + 2 * AK_B);
        for (int i = tid; i < 8 * 32; i += 256) {
            const int r = i >> 5, c = i & 31;
            *(uint32_t*)(vbase + (size_t)(64 + r) * QPITCH * 2 + c * 4) =
                (r == 0) ? 0x3C003C00u : 0u;
        }
    }

    const int a_row = lane & 15;
    const int a_ksel = (lane >> 4) * 8;
    const int b4_row = lane & 7;
    const int b4_k = ((lane >> 3) & 1) * 8;
    const int b4_n = ((lane >> 4) & 1) * 8;
    const int l2_row = lane & 7;
    const int l2_k = ((lane >> 3) & 1) * 8;

    uint32_t qfh[4][4], qfl[4][4];
    float O[8][4], Oext[4];
    float m0 = -__int_as_float(0x7f800000), m1 = m0;
#pragma unroll
    for (int d = 0; d < 8; d++)
#pragma unroll
        for (int r = 0; r < 4; r++) O[d][r] = 0.0f;
#pragma unroll
    for (int r = 0; r < 4; r++) Oext[r] = 0.0f;

    for (int kt = 0; kt < NKT; kt++) {
        const uint32_t stb = stage0 + (uint32_t)(kt & 1) * ASTAGE_B;
        if (kt + 1 < NKT) {
            attn_load_stage(stage0 + (uint32_t)((kt + 1) & 1) * ASTAGE_B,
                            bh, (kt + 1) * KT, tid);
            cp_commit();
            asm volatile("cp.async.wait_group 1;\n" ::: "memory");
        } else {
            asm volatile("cp.async.wait_group 0;\n" ::: "memory");
        }
        __syncthreads();

        if (kt == 0) {
#pragma unroll
            for (int ks = 0; ks < 4; ks++) {
                const uint32_t off =
                    (uint32_t)((wq * 16 + a_row) * QPITCH + ks * 16 + a_ksel) * 2;
                ldmatrix_x4(qfh[ks][0], qfh[ks][1], qfh[ks][2], qfh[ks][3], sQh + off);
                ldmatrix_x4(qfl[ks][0], qfl[ks][1], qfl[ks][2], qfl[ks][3], sQl + off);
            }
        }

        float S[8][4];
#pragma unroll
        for (int n = 0; n < 8; n++)
#pragma unroll
            for (int r = 0; r < 4; r++) S[n][r] = 0.0f;

        const uint32_t Kh = stb, Kl = stb + AK_B;
#pragma unroll
        for (int np = 0; np < 4; np++) {
#pragma unroll
            for (int ks = 0; ks < 4; ks++) {
                const uint32_t off =
                    (uint32_t)((np * 16 + b4_n + b4_row) * QPITCH + ks * 16 + b4_k) * 2;
                uint32_t kh0, kh1, kh2, kh3, kl0, kl1, kl2, kl3;
                ldmatrix_x4(kh0, kh1, kh2, kh3, Kh + off);
                ldmatrix_x4(kl0, kl1, kl2, kl3, Kl + off);
                mma_bf16(S[2 * np], qfh[ks][0], qfh[ks][1], qfh[ks][2], qfh[ks][3], kh0, kh1);
                mma_bf16(S[2 * np], qfh[ks][0], qfh[ks][1], qfh[ks][2], qfh[ks][3], kl0, kl1);
                mma_bf16(S[2 * np], qfl[ks][0], qfl[ks][1], qfl[ks][2], qfl[ks][3], kh0, kh1);
                mma_bf16(S[2 * np + 1], qfh[ks][0], qfh[ks][1], qfh[ks][2], qfh[ks][3], kh2, kh3);
                mma_bf16(S[2 * np + 1], qfh[ks][0], qfh[ks][1], qfh[ks][2], qfh[ks][3], kl2, kl3);
                mma_bf16(S[2 * np + 1], qfl[ks][0], qfl[ks][1], qfl[ks][2], qfl[ks][3], kh2, kh3);
            }
        }

        float mx0 = -__int_as_float(0x7f800000), mx1 = mx0;
#pragma unroll
        for (int n = 0; n < 8; n++) {
            mx0 = fmaxf(mx0, fmaxf(S[n][0], S[n][1]));
            mx1 = fmaxf(mx1, fmaxf(S[n][2], S[n][3]));
        }
        mx0 = fmaxf(mx0, __shfl_xor_sync(0xffffffffu, mx0, 1));
        mx0 = fmaxf(mx0, __shfl_xor_sync(0xffffffffu, mx0, 2));
        mx1 = fmaxf(mx1, __shfl_xor_sync(0xffffffffu, mx1, 1));
        mx1 = fmaxf(mx1, __shfl_xor_sync(0xffffffffu, mx1, 2));
        const float mn0 = fmaxf(m0, mx0), mn1 = fmaxf(m1, mx1);
        const float al0 = exp2f(m0 - mn0), al1 = exp2f(m1 - mn1);
#pragma unroll
        for (int n = 0; n < 8; n++) {
            S[n][0] = exp2f(S[n][0] - mn0);
            S[n][1] = exp2f(S[n][1] - mn0);
            S[n][2] = exp2f(S[n][2] - mn1);
            S[n][3] = exp2f(S[n][3] - mn1);
        }
        m0 = mn0;
        m1 = mn1;
#pragma unroll
        for (int d = 0; d < 8; d++) {
            O[d][0] *= al0; O[d][1] *= al0;
            O[d][2] *= al1; O[d][3] *= al1;
        }
        Oext[0] *= al0; Oext[1] *= al0;
        Oext[2] *= al1; Oext[3] *= al1;

        const uint32_t Vs = stb + 2 * AK_B;
#pragma unroll
        for (int u = 0; u < 4; u++) {
            uint32_t ph[4];
            ph[0] = cvt2h(S[2 * u][0], S[2 * u][1]);
            ph[1] = cvt2h(S[2 * u][2], S[2 * u][3]);
            ph[2] = cvt2h(S[2 * u + 1][0], S[2 * u + 1][1]);
            ph[3] = cvt2h(S[2 * u + 1][2], S[2 * u + 1][3]);
#pragma unroll
            for (int dp = 0; dp < 4; dp++) {
                const uint32_t off =
                    (uint32_t)((dp * 16 + b4_n + b4_row) * QPITCH + u * 16 + b4_k) * 2;
                uint32_t vh0, vh1, vh2, vh3;
                ldmatrix_x4(vh0, vh1, vh2, vh3, Vs + off);
                mma_f16(O[2 * dp], ph[0], ph[1], ph[2], ph[3], vh0, vh1);
                mma_f16(O[2 * dp + 1], ph[0], ph[1], ph[2], ph[3], vh2, vh3);
            }
            {
                uint32_t e0, e1;
                const uint32_t off =
                    (uint32_t)((64 + l2_row) * QPITCH + u * 16 + l2_k) * 2;
                ldmatrix_x2(e0, e1, Vs + off);
                mma_f16(Oext, ph[0], ph[1], ph[2], ph[3], e0, e1);
            }
        }
        __syncthreads();
    }

    const float l0 = __shfl_sync(0xffffffffu, Oext[0], lane & 0x1c);
    const float l1 = __shfl_sync(0xffffffffu, Oext[2], lane & 0x1c);
    const float r0 = 1.0f / l0, r1 = 1.0f / l1;
    const int row0 = q0 + wq * 16 + (lane >> 2);
    const size_t base0 = ((size_t)b * TT + row0) * CC + h * DH;
    const size_t base1 = base0 + (size_t)8 * CC;
#pragma unroll
    for (int dn = 0; dn < 8; dn++) {
        const int col = dn * 8 + 2 * (lane & 3);
        *(uint32_t*)&g_cT[base0 + col] = cvt2h(O[dn][0] * r0, O[dn][1] * r0);
        *(uint32_t*)&g_cT[base1 + col] = cvt2h(O[dn][2] * r1, O[dn][3] * r1);
    }
}

// ===========================================================================
// LayerNorm: normalize-only on y^T [t][c] + transpose to out [c][t]
// ===========================================================================
__global__ void __launch_bounds__(256) ln_kernel(
    const float* __restrict__ gamma, const float* __restrict__ beta,
    float* __restrict__ out)
{
    __shared__ float tile[32][33];
    const int tx = threadIdx.x, ty = threadIdx.y;
    const int b = blockIdx.z;
    const int t0 = blockIdx.x * 32, c0 = blockIdx.y * 32;

    const float gm = gamma[c0 + tx];
    const float bt = beta[c0 + tx];
    const __half* yb = g_y + (size_t)b * TT * CC;
    for (int j = ty; j < 32; j += 8) {
        const int t = t0 + j;
        const float s = g_lnsum[(size_t)b * TT + t];
        const float q = g_lnsq[(size_t)b * TT + t];
        const float mu = s * (1.0f / CC);
        const float rstd = rsqrtf(q * (1.0f / CC) - mu * mu + LN_EPS);
        const float v = __half2float(yb[(size_t)t * CC + c0 + tx]);
        tile[j][tx] = (v - mu) * rstd * gm + bt;
    }
    __syncthreads();
    float* ob = out + (size_t)b * CC * TT;
    for (int j = ty; j < 32; j += 8)
        ob[(size_t)(c0 + j) * TT + t0 + tx] = tile[tx][j];
}

// ===========================================================================
extern "C" void kernel_launch(void* const* d_in, const int* in_sizes, int n_in,
                              void* d_out, int out_size)
{
    const float* x     = (const float*)d_in[0];
    const float* wqkv  = (const float*)d_in[1];
    const float* wfc   = (const float*)d_in[2];
    const float* gamma = (const float*)d_in[3];
    const float* beta  = (const float*)d_in[4];
    float* out = (float*)d_out;

    __half* y;
    cudaGetSymbolAddress((void**)&y, g_y);
    __nv_bfloat16 *wqkh, *wqkl, *xth, *xtl;
    __half *wvh, *wvl, *wfh, *wfl, *xt16, *ct;
    cudaGetSymbolAddress((void**)&wqkh, g_wqk_hi);
    cudaGetSymbolAddress((void**)&wqkl, g_wqk_lo);
    cudaGetSymbolAddress((void**)&wvh, g_wv_hi);
    cudaGetSymbolAddress((void**)&wvl, g_wv_lo);
    cudaGetSymbolAddress((void**)&wfh, g_wfc_hi);
    cudaGetSymbolAddress((void**)&wfl, g_wfc_lo);
    cudaGetSymbolAddress((void**)&xth, g_xT_hi);
    cudaGetSymbolAddress((void**)&xtl, g_xT_lo);
    cudaGetSymbolAddress((void**)&xt16, g_xT_h16);
    cudaGetSymbolAddress((void**)&ct, g_cT);

    cudaFuncSetAttribute((const void*)qkv_fused, cudaFuncAttributeMaxDynamicSharedMemorySize, GEMM_SMEM0);
    cudaFuncSetAttribute((const void*)proj_gemm, cudaFuncAttributeMaxDynamicSharedMemorySize, GEMM_SMEM3);
    cudaFuncSetAttribute((const void*)attn_mma, cudaFuncAttributeMaxDynamicSharedMemorySize, ATTN_SMEM);

    // 0) fused prologue
    prologue_kernel<<<dim3(TT / 32 + CONVX, CC / 32, BB), dim3(32, 8)>>>(
        x, wqkv, wfc);

    // 1) merged QK (bf16 3-term) + V (fp16 asym) projections
    qkv_fused<<<dim3(TT / GM_NT, 3 * CC / GM_MT, BB), 256, GEMM_SMEM0>>>(
        (const uint16_t*)wqkh, (const uint16_t*)wqkl,
        (const uint16_t*)xth, (const uint16_t*)xtl,
        (const uint16_t*)wvh, (const uint16_t*)wvl, (const uint16_t*)xt16);

    // 2) flash attention (ones-row l) -> g_cT
    attn_mma<<<dim3(TT / 128, HH, BB), 256, ATTN_SMEM>>>();

    // 3) y^T = ct @ wfc^T + x^T (fp16, LN row stats fused)
    proj_gemm<<<dim3(CC / GM_NT, TT / GM_MT, BB), 256, GEMM_SMEM3>>>(
        (const uint16_t*)ct, (const uint16_t*)wfh, (const uint16_t*)wfl,
        y, (long)TT * CC);

    // 4) LayerNorm normalize + transpose -> out [c][t]
    ln_kernel<<<dim3(TT / 32, CC / 32, BB), dim3(32, 8)>>>(gamma, beta, out);
}

// round 17
// speedup vs baseline: 1.1035x; 1.0272x over previous
#include <cuda_runtime.h>
#include <cuda_bf16.h>
#include <cuda_fp16.h>
#include <cstdint>

#define BB 2
#define CC 1024
#define TT 2048
#define HH 16
#define DH 64
#define LN_EPS 1e-6f
#define LOG2E 1.44269504088896340736f

// ---- dense GEMM tiling (KC=32, 2-stage, 2 CTAs/SM) ----
#define GM_MT 128
#define GM_NT 128
#define GM_KC 32
#define NCHUNK (CC / GM_KC)            // 32
#define PITCH 40
#define A_BYTES (GM_MT * PITCH * 2)     // 10240
#define B_BYTES (GM_NT * PITCH * 2)     // 10240
#define STAGE0_BYTES (2 * A_BYTES + 2 * B_BYTES)  // 40960
#define GEMM_SMEM0 (2 * STAGE0_BYTES)             // 81920
#define STAGE3_BYTES (A_BYTES + 2 * B_BYTES)      // 30720 (A single + B hi/lo)
#define GEMM_SMEM3 (2 * STAGE3_BYTES)             // 61440

// ---- attention ----
#define QPITCH 72
#define KT 64
#define NKT (TT / KT)
#define AQ_B (128 * QPITCH * 2)
#define AK_B (KT * QPITCH * 2)
#define AV_ROWS 72
#define ASTAGE_B (2 * AK_B + AV_ROWS * QPITCH * 2)
#define ATTN_SMEM (2 * AQ_B + 2 * ASTAGE_B)      // 94464

#define CONV_TOTAL ((size_t)4 * CC * CC + (size_t)BB * TT)
#define CONVX 257

// ---- scratch ----
__device__ __half g_y[(size_t)BB * TT * CC];
__device__ float g_lnsum[(size_t)BB * TT];
__device__ float g_lnsq[(size_t)BB * TT];
__device__ __nv_bfloat16 g_wqk_hi[2 * CC * CC], g_wqk_lo[2 * CC * CC];
__device__ __half g_wv_hi[CC * CC], g_wv_lo[CC * CC];
__device__ __half g_wfc_hi[CC * CC], g_wfc_lo[CC * CC];
__device__ __nv_bfloat16 g_xT_hi[(size_t)BB * TT * CC], g_xT_lo[(size_t)BB * TT * CC];
__device__ __half g_xT_h16[(size_t)BB * TT * CC];
__device__ __half g_cT[(size_t)BB * TT * CC];
__device__ __nv_bfloat16 g_qT_hi[(size_t)BB * HH * TT * DH], g_qT_lo[(size_t)BB * HH * TT * DH];
__device__ __nv_bfloat16 g_kT_hi[(size_t)BB * HH * TT * DH], g_kT_lo[(size_t)BB * HH * TT * DH];
__device__ __half g_v[(size_t)BB * HH * DH * TT];

// ===========================================================================
__device__ __forceinline__ uint32_t smem_u32(const void* p) {
    return (uint32_t)__cvta_generic_to_shared(p);
}
__device__ __forceinline__ void cp16(uint32_t dst, const void* src) {
    asm volatile("cp.async.cg.shared.global [%0], [%1], 16;\n" :: "r"(dst), "l"(src));
}
__device__ __forceinline__ void cp_commit() {
    asm volatile("cp.async.commit_group;\n" ::: "memory");
}
__device__ __forceinline__ void ldmatrix_x4(uint32_t& a0, uint32_t& a1, uint32_t& a2,
                                            uint32_t& a3, uint32_t addr) {
    asm volatile("ldmatrix.sync.aligned.m8n8.x4.shared.b16 {%0,%1,%2,%3}, [%4];"
                 : "=r"(a0), "=r"(a1), "=r"(a2), "=r"(a3) : "r"(addr));
}
__device__ __forceinline__ void ldmatrix_x2(uint32_t& b0, uint32_t& b1, uint32_t addr) {
    asm volatile("ldmatrix.sync.aligned.m8n8.x2.shared.b16 {%0,%1}, [%2];"
                 : "=r"(b0), "=r"(b1) : "r"(addr));
}
__device__ __forceinline__ void mma_bf16(float* c,
                                         uint32_t a0, uint32_t a1, uint32_t a2, uint32_t a3,
                                         uint32_t b0, uint32_t b1) {
    asm volatile(
        "mma.sync.aligned.m16n8k16.row.col.f32.bf16.bf16.f32 "
        "{%0,%1,%2,%3}, {%4,%5,%6,%7}, {%8,%9}, {%0,%1,%2,%3};"
        : "+f"(c[0]), "+f"(c[1]), "+f"(c[2]), "+f"(c[3])
        : "r"(a0), "r"(a1), "r"(a2), "r"(a3), "r"(b0), "r"(b1));
}
__device__ __forceinline__ void mma_f16(float* c,
                                        uint32_t a0, uint32_t a1, uint32_t a2, uint32_t a3,
                                        uint32_t b0, uint32_t b1) {
    asm volatile(
        "mma.sync.aligned.m16n8k16.row.col.f32.f16.f16.f32 "
        "{%0,%1,%2,%3}, {%4,%5,%6,%7}, {%8,%9}, {%0,%1,%2,%3};"
        : "+f"(c[0]), "+f"(c[1]), "+f"(c[2]), "+f"(c[3])
        : "r"(a0), "r"(a1), "r"(a2), "r"(a3), "r"(b0), "r"(b1));
}
__device__ __forceinline__ uint32_t cvt2(float f0, float f1) {  // bf16x2
    uint32_t r;
    asm("cvt.rn.bf16x2.f32 %0, %1, %2;" : "=r"(r) : "f"(f1), "f"(f0));
    return r;
}
__device__ __forceinline__ void split2(float f0, float f1, uint32_t& hi, uint32_t& lo) {
    hi = cvt2(f0, f1);
    const float h0 = __uint_as_float(hi << 16);
    const float h1 = __uint_as_float(hi & 0xffff0000u);
    lo = cvt2(f0 - h0, f1 - h1);
}
__device__ __forceinline__ uint32_t cvt2h(float f0, float f1) {  // f16x2
    uint32_t r;
    asm("cvt.rn.f16x2.f32 %0, %1, %2;" : "=r"(r) : "f"(f1), "f"(f0));
    return r;
}
__device__ __forceinline__ float ex2f(float x) {  // guaranteed single MUFU
    float r;
    asm("ex2.approx.f32 %0, %1;" : "=f"(r) : "f"(x));
    return r;
}

// ===========================================================================
// fused prologue
// ===========================================================================
__global__ void __launch_bounds__(256) prologue_kernel(
    const float* __restrict__ x, const float* __restrict__ wqkv,
    const float* __restrict__ wfc)
{
    if (blockIdx.x < TT / 32) {
        __shared__ float tile[32][33];
        const int b = blockIdx.z;
        const int t0 = blockIdx.x * 32, c0 = blockIdx.y * 32;
        const float* ib = x + (size_t)b * CC * TT;
        for (int j = threadIdx.y; j < 32; j += 8)
            tile[j][threadIdx.x] = ib[(size_t)(c0 + j) * TT + t0 + threadIdx.x];
        __syncthreads();
        __nv_bfloat16* hb = g_xT_hi + (size_t)b * TT * CC;
        __nv_bfloat16* lb = g_xT_lo + (size_t)b * TT * CC;
        __half* sb = g_xT_h16 + (size_t)b * TT * CC;
        for (int j = threadIdx.y; j < 32; j += 8) {
            const float v = tile[threadIdx.x][j];
            const __nv_bfloat16 h = __float2bfloat16(v);
            const size_t o = (size_t)(t0 + j) * CC + c0 + threadIdx.x;
            hb[o] = h;
            lb[o] = __float2bfloat16(v - __bfloat162float(h));
            sb[o] = __float2half_rn(v);
        }
    } else {
        const int tid = threadIdx.y * 32 + threadIdx.x;
        const size_t cid = (size_t)(blockIdx.x - TT / 32) +
                           (size_t)CONVX * (blockIdx.y + 32 * blockIdx.z);
        const size_t i = cid * 256 + tid;
        const size_t N1 = (size_t)2 * CC * CC;
        const size_t N2 = (size_t)CC * CC;
        if (i < N1) {
            const float v = wqkv[i];
            const __nv_bfloat16 h = __float2bfloat16(v);
            g_wqk_hi[i] = h;
            g_wqk_lo[i] = __float2bfloat16(v - __bfloat162float(h));
        } else if (i < N1 + N2) {
            const float v = wqkv[i];
            const size_t j = i - N1;
            const __half h = __float2half_rn(v);
            g_wv_hi[j] = h;
            g_wv_lo[j] = __float2half_rn(v - __half2float(h));
        } else if (i < N1 + 2 * N2) {
            const size_t j = i - N1 - N2;
            const float v = wfc[j];
            const __half h = __float2half_rn(v);
            g_wfc_hi[j] = h;
            g_wfc_lo[j] = __float2half_rn(v - __half2float(h));
        } else if (i < CONV_TOTAL) {
            const size_t j = i - N1 - 2 * N2;
            g_lnsum[j] = 0.0f;
            g_lnsq[j] = 0.0f;
        }
    }
}

// ===========================================================================
// shared GEMM core.
// MODE 0: A hi/lo + B hi/lo (bf16, 3 mma)
// MODE 3: A single (batched) + B hi/lo (fp16, 2 mma)
// EPI 2 = Q/K epi; EPI 4 = transposed proj epi; EPI 5 = transposed V epi
// ===========================================================================
template <int MODE>
__device__ __forceinline__ void g_load_stage(
    uint32_t st, int kc,
    const uint16_t* __restrict__ Ahi, const uint16_t* __restrict__ Alo,
    const uint16_t* __restrict__ Bhi, const uint16_t* __restrict__ Blo,
    int m0, int n0, int tid)
{
    const uint32_t bOff = (MODE == 3) ? A_BYTES : 2 * A_BYTES;
    for (int i = tid; i < GM_MT * 4; i += 256) {
        const int r = i >> 2, c = i & 3;
        const uint32_t dst = st + (uint32_t)(r * PITCH + c * 8) * 2;
        const size_t g = (size_t)(m0 + r) * CC + kc + c * 8;
        cp16(dst, Ahi + g);
        if (MODE != 3) cp16(dst + A_BYTES, Alo + g);
    }
    for (int i = tid; i < GM_NT * 4; i += 256) {
        const int r = i >> 2, c = i & 3;
        const uint32_t dst = st + bOff + (uint32_t)(r * PITCH + c * 8) * 2;
        const size_t g = (size_t)(n0 + r) * CC + kc + c * 8;
        cp16(dst, Bhi + g);
        cp16(dst + B_BYTES, Blo + g);
    }
    cp_commit();
}

template <int EPI, int MODE>
__device__ __forceinline__ void gemm_core(
    char* smem,
    const uint16_t* __restrict__ AhiIn, const uint16_t* __restrict__ AloIn,
    const uint16_t* __restrict__ BhiIn, const uint16_t* __restrict__ BloIn,
    __half* __restrict__ Cout, long outBatchStride, int bx, int by)
{
    const uint32_t sbase = smem_u32(smem);
    const uint32_t stageB = (MODE == 0) ? STAGE0_BYTES : STAGE3_BYTES;

    const int tid = threadIdx.x;
    const int wid = tid >> 5;
    const int lane = tid & 31;
    const int b = blockIdx.z;
    const int m0 = by * GM_MT;
    const int n0 = bx * GM_NT;
    const int wm = (wid >> 2) * 64;
    const int wn = (wid & 3) * 32;

    // MODE 3: A batched (x/ct), B shared weights; MODE 0: A weights, B batched.
    const uint16_t* Ahi = AhiIn + ((MODE == 3) ? (size_t)b * TT * CC : 0);
    const uint16_t* Alo = (MODE == 0) ? AloIn : nullptr;
    const uint16_t* Bhi = BhiIn + ((MODE == 3) ? 0 : (size_t)b * TT * CC);
    const uint16_t* Blo = BloIn + ((MODE == 3) ? 0 : (size_t)b * TT * CC);

    float acc[4][4][4];
#pragma unroll
    for (int i = 0; i < 4; i++)
#pragma unroll
        for (int j = 0; j < 4; j++)
#pragma unroll
            for (int r = 0; r < 4; r++) acc[i][j][r] = 0.0f;

    const int a_row = lane & 15;
    const int a_ksel = (lane >> 4) * 8;
    const int b4_row = lane & 7;
    const int b4_k = ((lane >> 3) & 1) * 8;
    const int b4_n = ((lane >> 4) & 1) * 8;

    g_load_stage<MODE>(sbase, 0, Ahi, Alo, Bhi, Blo, m0, n0, tid);

    for (int c = 0; c < NCHUNK; c++) {
        const uint32_t st = sbase + (uint32_t)(c & 1) * stageB;
        if (c + 1 < NCHUNK) {
            g_load_stage<MODE>(sbase + (uint32_t)((c + 1) & 1) * stageB,
                               (c + 1) * GM_KC, Ahi, Alo, Bhi, Blo, m0, n0, tid);
            asm volatile("cp.async.wait_group 1;\n" ::: "memory");
        } else {
            asm volatile("cp.async.wait_group 0;\n" ::: "memory");
        }
        __syncthreads();

        const uint32_t sAh = st;
        const uint32_t sAl = st + A_BYTES;
        const uint32_t sBh = st + ((MODE == 3) ? A_BYTES : 2 * A_BYTES);
        const uint32_t sBl = sBh + B_BYTES;

#pragma unroll
        for (int kk = 0; kk < GM_KC; kk += 16) {
            uint32_t ah[4][4], al[4][4], bh[4][2], bl[4][2];
#pragma unroll
            for (int mi = 0; mi < 4; mi++) {
                const uint32_t off =
                    (uint32_t)((wm + mi * 16 + a_row) * PITCH + kk + a_ksel) * 2;
                ldmatrix_x4(ah[mi][0], ah[mi][1], ah[mi][2], ah[mi][3], sAh + off);
                if (MODE == 0)
                    ldmatrix_x4(al[mi][0], al[mi][1], al[mi][2], al[mi][3], sAl + off);
            }
#pragma unroll
            for (int p = 0; p < 2; p++) {
                const uint32_t off =
                    (uint32_t)((wn + p * 16 + b4_n + b4_row) * PITCH + kk + b4_k) * 2;
                ldmatrix_x4(bh[2 * p][0], bh[2 * p][1], bh[2 * p + 1][0],
                            bh[2 * p + 1][1], sBh + off);
                ldmatrix_x4(bl[2 * p][0], bl[2 * p][1], bl[2 * p + 1][0],
                            bl[2 * p + 1][1], sBl + off);
            }
#pragma unroll
            for (int mi = 0; mi < 4; mi++)
#pragma unroll
                for (int nj = 0; nj < 4; nj++) {
                    float* a = acc[mi][nj];
                    if (MODE == 0) {
                        mma_bf16(a, ah[mi][0], ah[mi][1], ah[mi][2], ah[mi][3],
                                 bh[nj][0], bh[nj][1]);
                        mma_bf16(a, ah[mi][0], ah[mi][1], ah[mi][2], ah[mi][3],
                                 bl[nj][0], bl[nj][1]);
                        mma_bf16(a, al[mi][0], al[mi][1], al[mi][2], al[mi][3],
                                 bh[nj][0], bh[nj][1]);
                    } else {
                        mma_f16(a, ah[mi][0], ah[mi][1], ah[mi][2], ah[mi][3],
                                bh[nj][0], bh[nj][1]);
                        mma_f16(a, ah[mi][0], ah[mi][1], ah[mi][2], ah[mi][3],
                                bl[nj][0], bl[nj][1]);
                    }
                }
        }
        __syncthreads();
    }

    const int er = lane >> 2;
    const int ec = (lane & 3) * 2;

    if (EPI == 4) {
        // transposed proj: m=t, n=c; residual from xT fp16; y^T + LN row stats
        float rs[4][2], rq[4][2];
#pragma unroll
        for (int mi = 0; mi < 4; mi++) {
            rs[mi][0] = rs[mi][1] = 0.0f;
            rq[mi][0] = rq[mi][1] = 0.0f;
        }
        __half* Cb = Cout + (size_t)b * outBatchStride;
        const __half* Rb = g_xT_h16 + (size_t)b * TT * CC;
#pragma unroll
        for (int mi = 0; mi < 4; mi++)
#pragma unroll
            for (int nj = 0; nj < 4; nj++) {
                const int m = m0 + wm + mi * 16 + er;
                const int n = n0 + wn + nj * 8 + ec;
                const __half2 rA = *(const __half2*)(Rb + (size_t)m * CC + n);
                const __half2 rB = *(const __half2*)(Rb + (size_t)(m + 8) * CC + n);
                const float v0x = acc[mi][nj][0] + __half2float(rA.x);
                const float v0y = acc[mi][nj][1] + __half2float(rA.y);
                const float v1x = acc[mi][nj][2] + __half2float(rB.x);
                const float v1y = acc[mi][nj][3] + __half2float(rB.y);
                *(uint32_t*)(Cb + (size_t)m * CC + n) = cvt2h(v0x, v0y);
                *(uint32_t*)(Cb + (size_t)(m + 8) * CC + n) = cvt2h(v1x, v1y);
                rs[mi][0] += v0x + v0y;
                rq[mi][0] += v0x * v0x + v0y * v0y;
                rs[mi][1] += v1x + v1y;
                rq[mi][1] += v1x * v1x + v1y * v1y;
            }
#pragma unroll
        for (int mi = 0; mi < 4; mi++)
#pragma unroll
            for (int r2 = 0; r2 < 2; r2++) {
                rs[mi][r2] += __shfl_xor_sync(0xffffffffu, rs[mi][r2], 1);
                rs[mi][r2] += __shfl_xor_sync(0xffffffffu, rs[mi][r2], 2);
                rq[mi][r2] += __shfl_xor_sync(0xffffffffu, rq[mi][r2], 1);
                rq[mi][r2] += __shfl_xor_sync(0xffffffffu, rq[mi][r2], 2);
            }
        float* rows_s = (float*)smem;
        float* rowq_s = rows_s + 512;
        if ((lane & 3) == 0) {
#pragma unroll
            for (int mi = 0; mi < 4; mi++)
#pragma unroll
                for (int r2 = 0; r2 < 2; r2++) {
                    const int rl = (wid >> 2) * 64 + mi * 16 + er + r2 * 8;
                    rows_s[rl * 4 + (wid & 3)] = rs[mi][r2];
                    rowq_s[rl * 4 + (wid & 3)] = rq[mi][r2];
                }
        }
        __syncthreads();
        if (tid < 128) {
            const float s = rows_s[tid * 4] + rows_s[tid * 4 + 1] +
                            rows_s[tid * 4 + 2] + rows_s[tid * 4 + 3];
            const float q = rowq_s[tid * 4] + rowq_s[tid * 4 + 1] +
                            rowq_s[tid * 4 + 2] + rowq_s[tid * 4 + 3];
            atomicAdd(&g_lnsum[(size_t)b * TT + m0 + tid], s);
            atomicAdd(&g_lnsq[(size_t)b * TT + m0 + tid], q);
        }
    } else if (EPI == 5) {
        // transposed V epilogue: m=t, n=channel; stage transposed, write V[d][t]
        float* stg = (float*)smem;  // [n(128)][m(128)] pitch 129
#pragma unroll
        for (int mi = 0; mi < 4; mi++)
#pragma unroll
            for (int nj = 0; nj < 4; nj++) {
                const int m = wm + mi * 16 + er;
                const int n = wn + nj * 8 + ec;
                stg[n * 129 + m] = acc[mi][nj][0];
                stg[(n + 1) * 129 + m] = acc[mi][nj][1];
                stg[n * 129 + m + 8] = acc[mi][nj][2];
                stg[(n + 1) * 129 + m + 8] = acc[mi][nj][3];
            }
        __syncthreads();
        uint32_t* vv = (uint32_t*)g_v;
#pragma unroll
        for (int i = 0; i < 16; i++) {
            const int chl = wid * 16 + i;
            const int ch = n0 + chl;
            const int bh2 = b * HH + (ch >> 6);
            const int d = ch & 63;
            const float* row = stg + chl * 129;
            const size_t basev = (((size_t)bh2 * DH + d) * TT + m0) >> 1;
#pragma unroll
            for (int half = 0; half < 2; half++) {
                const float v0 = row[half * 64 + 2 * lane];
                const float v1 = row[half * 64 + 2 * lane + 1];
                vv[basev + half * 32 + lane] = cvt2h(v0, v1);
            }
        }
    } else {
        // EPI 2: Q/K epilogue
        const bool isK = (m0 >= CC);
        const float qscale = isK ? 1.0f : LOG2E;
        const int chBase = isK ? (m0 - CC) : m0;
        const int h0 = chBase >> 6;
        float* stg = (float*)smem;
#pragma unroll
        for (int mi = 0; mi < 4; mi++)
#pragma unroll
            for (int nj = 0; nj < 4; nj++) {
                const int m = wm + mi * 16 + er;
                const int n = wn + nj * 8 + ec;
                stg[n * 129 + m] = acc[mi][nj][0];
                stg[(n + 1) * 129 + m] = acc[mi][nj][1];
                stg[n * 129 + m + 8] = acc[mi][nj][2];
                stg[(n + 1) * 129 + m + 8] = acc[mi][nj][3];
            }
        __syncthreads();
        uint32_t* dh = (uint32_t*)(isK ? g_kT_hi : g_qT_hi);
        uint32_t* dl = (uint32_t*)(isK ? g_kT_lo : g_qT_lo);
#pragma unroll
        for (int i = 0; i < 16; i++) {
            const int t = wid * 16 + i;
            const float* row = stg + t * 129;
#pragma unroll
            for (int half = 0; half < 2; half++) {
                const float v0 = row[half * 64 + 2 * lane] * qscale;
                const float v1 = row[half * 64 + 2 * lane + 1] * qscale;
                uint32_t hi, lo;
                split2(v0, v1, hi, lo);
                const size_t idx =
                    ((size_t)(b * HH + h0 + half) * TT + n0 + t) * 32 + lane;
                dh[idx] = hi;
                dl[idx] = lo;
            }
        }
    }
}

// merged QK + transposed-V launch (grid = (16, 24, 2))
__global__ void __launch_bounds__(256, 2) qkv_fused(
    const uint16_t* __restrict__ wqkh, const uint16_t* __restrict__ wqkl,
    const uint16_t* __restrict__ xth, const uint16_t* __restrict__ xtl,
    const uint16_t* __restrict__ xt16,
    const uint16_t* __restrict__ wvh, const uint16_t* __restrict__ wvl)
{
    extern __shared__ char smem[];
    if (blockIdx.y < 2 * CC / GM_MT) {
        gemm_core<2, 0>(smem, wqkh, wqkl, xth, xtl, nullptr, 0,
                        blockIdx.x, blockIdx.y);
    } else {
        // V^T: A = x^T single (t rows), B = w_v hi/lo (channel rows)
        gemm_core<5, 3>(smem, xt16, nullptr, wvh, wvl, nullptr, 0,
                        blockIdx.y - 2 * CC / GM_MT, blockIdx.x);
    }
}

// transposed projection GEMM
__global__ void __launch_bounds__(256, 2) proj_gemm(
    const uint16_t* __restrict__ ct,
    const uint16_t* __restrict__ wfh, const uint16_t* __restrict__ wfl,
    __half* __restrict__ Cout, long outBatchStride)
{
    extern __shared__ char smem[];
    gemm_core<4, 3>(smem, ct, nullptr, wfh, wfl, Cout, outBatchStride,
                    blockIdx.x, blockIdx.y);
}

// ===========================================================================
// Flash attention + ones-row l (ex2 asm, vote-gated rescale)
// ===========================================================================
__device__ __forceinline__ void attn_load_stage(uint32_t st, int bh, int k0, int tid)
{
    const __nv_bfloat16* kh = g_kT_hi + ((size_t)bh * TT + k0) * DH;
    const __nv_bfloat16* kl = g_kT_lo + ((size_t)bh * TT + k0) * DH;
    for (int i = tid; i < KT * 8; i += 256) {
        const int r = i >> 3, c = i & 7;
        const uint32_t d = st + (uint32_t)(r * QPITCH + c * 8) * 2;
        cp16(d, kh + (size_t)r * DH + c * 8);
        cp16(d + AK_B, kl + (size_t)r * DH + c * 8);
    }
    const __half* vp = g_v + (size_t)bh * DH * TT + k0;
    for (int i = tid; i < 64 * (KT / 8); i += 256) {
        const int r = i >> 3, c = i & 7;
        const uint32_t d = st + 2 * AK_B + (uint32_t)(r * QPITCH + c * 8) * 2;
        cp16(d, vp + (size_t)r * TT + c * 8);
    }
}

__global__ void __launch_bounds__(256, 2) attn_mma()
{
    extern __shared__ char smem[];
    const uint32_t sb = smem_u32(smem);
    const uint32_t sQh = sb, sQl = sb + AQ_B;
    const uint32_t stage0 = sb + 2 * AQ_B;

    const int tid = threadIdx.x;
    const int wq = tid >> 5;
    const int lane = tid & 31;
    const int b = blockIdx.z, h = blockIdx.y;
    const int bh = b * HH + h;
    const int q0 = blockIdx.x * 128;

    {
        const __nv_bfloat16* qh = g_qT_hi + ((size_t)bh * TT + q0) * DH;
        const __nv_bfloat16* ql = g_qT_lo + ((size_t)bh * TT + q0) * DH;
        for (int i = tid; i < 128 * 8; i += 256) {
            const int r = i >> 3, c = i & 7;
            const uint32_t d = sQh + (uint32_t)(r * QPITCH + c * 8) * 2;
            cp16(d, qh + (size_t)r * DH + c * 8);
            cp16(d + AQ_B, ql + (size_t)r * DH + c * 8);
        }
        attn_load_stage(stage0, bh, 0, tid);
        cp_commit();
    }

    for (int s = 0; s < 2; s++) {
        char* vbase = smem + (2 * AQ_B + s * ASTAGE_B + 2 * AK_B);
        for (int i = tid; i < 8 * 32; i += 256) {
            const int r = i >> 5, c = i & 31;
            *(uint32_t*)(vbase + (size_t)(64 + r) * QPITCH * 2 + c * 4) =
                (r == 0) ? 0x3C003C00u : 0u;
        }
    }

    const int a_row = lane & 15;
    const int a_ksel = (lane >> 4) * 8;
    const int b4_row = lane & 7;
    const int b4_k = ((lane >> 3) & 1) * 8;
    const int b4_n = ((lane >> 4) & 1) * 8;
    const int l2_row = lane & 7;
    const int l2_k = ((lane >> 3) & 1) * 8;

    uint32_t qfh[4][4], qfl[4][4];
    float O[8][4], Oext[4];
    float m0 = -__int_as_float(0x7f800000), m1 = m0;
#pragma unroll
    for (int d = 0; d < 8; d++)
#pragma unroll
        for (int r = 0; r < 4; r++) O[d][r] = 0.0f;
#pragma unroll
    for (int r = 0; r < 4; r++) Oext[r] = 0.0f;

    for (int kt = 0; kt < NKT; kt++) {
        const uint32_t stb = stage0 + (uint32_t)(kt & 1) * ASTAGE_B;
        if (kt + 1 < NKT) {
            attn_load_stage(stage0 + (uint32_t)((kt + 1) & 1) * ASTAGE_B,
                            bh, (kt + 1) * KT, tid);
            cp_commit();
            asm volatile("cp.async.wait_group 1;\n" ::: "memory");
        } else {
            asm volatile("cp.async.wait_group 0;\n" ::: "memory");
        }
        __syncthreads();

        if (kt == 0) {
#pragma unroll
            for (int ks = 0; ks < 4; ks++) {
                const uint32_t off =
                    (uint32_t)((wq * 16 + a_row) * QPITCH + ks * 16 + a_ksel) * 2;
                ldmatrix_x4(qfh[ks][0], qfh[ks][1], qfh[ks][2], qfh[ks][3], sQh + off);
                ldmatrix_x4(qfl[ks][0], qfl[ks][1], qfl[ks][2], qfl[ks][3], sQl + off);
            }
        }

        float S[8][4];
#pragma unroll
        for (int n = 0; n < 8; n++)
#pragma unroll
            for (int r = 0; r < 4; r++) S[n][r] = 0.0f;

        const uint32_t Kh = stb, Kl = stb + AK_B;
#pragma unroll
        for (int np = 0; np < 4; np++) {
#pragma unroll
            for (int ks = 0; ks < 4; ks++) {
                const uint32_t off =
                    (uint32_t)((np * 16 + b4_n + b4_row) * QPITCH + ks * 16 + b4_k) * 2;
                uint32_t kh0, kh1, kh2, kh3, kl0, kl1, kl2, kl3;
                ldmatrix_x4(kh0, kh1, kh2, kh3, Kh + off);
                ldmatrix_x4(kl0, kl1, kl2, kl3, Kl + off);
                mma_bf16(S[2 * np], qfh[ks][0], qfh[ks][1], qfh[ks][2], qfh[ks][3], kh0, kh1);
                mma_bf16(S[2 * np], qfh[ks][0], qfh[ks][1], qfh[ks][2], qfh[ks][3], kl0, kl1);
                mma_bf16(S[2 * np], qfl[ks][0], qfl[ks][1], qfl[ks][2], qfl[ks][3], kh0, kh1);
                mma_bf16(S[2 * np + 1], qfh[ks][0], qfh[ks][1], qfh[ks][2], qfh[ks][3], kh2, kh3);
                mma_bf16(S[2 * np + 1], qfh[ks][0], qfh[ks][1], qfh[ks][2], qfh[ks][3], kl2, kl3);
                mma_bf16(S[2 * np + 1], qfl[ks][0], qfl[ks][1], qfl[ks][2], qfl[ks][3], kh2, kh3);
            }
        }

        float mx0 = -__int_as_float(0x7f800000), mx1 = mx0;
#pragma unroll
        for (int n = 0; n < 8; n++) {
            mx0 = fmaxf(mx0, fmaxf(S[n][0], S[n][1]));
            mx1 = fmaxf(mx1, fmaxf(S[n][2], S[n][3]));
        }
        mx0 = fmaxf(mx0, __shfl_xor_sync(0xffffffffu, mx0, 1));
        mx0 = fmaxf(mx0, __shfl_xor_sync(0xffffffffu, mx0, 2));
        mx1 = fmaxf(mx1, __shfl_xor_sync(0xffffffffu, mx1, 1));
        mx1 = fmaxf(mx1, __shfl_xor_sync(0xffffffffu, mx1, 2));
        const float mn0 = fmaxf(m0, mx0), mn1 = fmaxf(m1, mx1);
        const float al0 = ex2f(m0 - mn0), al1 = ex2f(m1 - mn1);
#pragma unroll
        for (int n = 0; n < 8; n++) {
            S[n][0] = ex2f(S[n][0] - mn0);
            S[n][1] = ex2f(S[n][1] - mn0);
            S[n][2] = ex2f(S[n][2] - mn1);
            S[n][3] = ex2f(S[n][3] - mn1);
        }
        m0 = mn0;
        m1 = mn1;
        // vote-gated rescale: skip when al==1.0 exactly for all lanes
        if (__any_sync(0xffffffffu, (al0 != 1.0f) || (al1 != 1.0f))) {
#pragma unroll
            for (int d = 0; d < 8; d++) {
                O[d][0] *= al0; O[d][1] *= al0;
                O[d][2] *= al1; O[d][3] *= al1;
            }
            Oext[0] *= al0; Oext[1] *= al0;
            Oext[2] *= al1; Oext[3] *= al1;
        }

        const uint32_t Vs = stb + 2 * AK_B;
#pragma unroll
        for (int u = 0; u < 4; u++) {
            uint32_t ph[4];
            ph[0] = cvt2h(S[2 * u][0], S[2 * u][1]);
            ph[1] = cvt2h(S[2 * u][2], S[2 * u][3]);
            ph[2] = cvt2h(S[2 * u + 1][0], S[2 * u + 1][1]);
            ph[3] = cvt2h(S[2 * u + 1][2], S[2 * u + 1][3]);
#pragma unroll
            for (int dp = 0; dp < 4; dp++) {
                const uint32_t off =
                    (uint32_t)((dp * 16 + b4_n + b4_row) * QPITCH + u * 16 + b4_k) * 2;
                uint32_t vh0, vh1, vh2, vh3;
                ldmatrix_x4(vh0, vh1, vh2, vh3, Vs + off);
                mma_f16(O[2 * dp], ph[0], ph[1], ph[2], ph[3], vh0, vh1);
                mma_f16(O[2 * dp + 1], ph[0], ph[1], ph[2], ph[3], vh2, vh3);
            }
            {
                uint32_t e0, e1;
                const uint32_t off =
                    (uint32_t)((64 + l2_row) * QPITCH + u * 16 + l2_k) * 2;
                ldmatrix_x2(e0, e1, Vs + off);
                mma_f16(Oext, ph[0], ph[1], ph[2], ph[3], e0, e1);
            }
        }
        __syncthreads();
    }

    const float l0 = __shfl_sync(0xffffffffu, Oext[0], lane & 0x1c);
    const float l1 = __shfl_sync(0xffffffffu, Oext[2], lane & 0x1c);
    const float r0 = 1.0f / l0, r1 = 1.0f / l1;
    const int row0 = q0 + wq * 16 + (lane >> 2);
    const size_t base0 = ((size_t)b * TT + row0) * CC + h * DH;
    const size_t base1 = base0 + (size_t)8 * CC;
#pragma unroll
    for (int dn = 0; dn < 8; dn++) {
        const int col = dn * 8 + 2 * (lane & 3);
        *(uint32_t*)&g_cT[base0 + col] = cvt2h(O[dn][0] * r0, O[dn][1] * r0);
        *(uint32_t*)&g_cT[base1 + col] = cvt2h(O[dn][2] * r1, O[dn][3] * r1);
    }
}

// ===========================================================================
// LayerNorm: normalize y^T + transpose to out [c][t]
// ===========================================================================
__global__ void __launch_bounds__(256) ln_kernel(
    const float* __restrict__ gamma, const float* __restrict__ beta,
    float* __restrict__ out)
{
    __shared__ float tile[32][33];
    const int tx = threadIdx.x, ty = threadIdx.y;
    const int b = blockIdx.z;
    const int t0 = blockIdx.x * 32, c0 = blockIdx.y * 32;

    const float gm = gamma[c0 + tx];
    const float bt = beta[c0 + tx];
    const __half* yb = g_y + (size_t)b * TT * CC;
    for (int j = ty; j < 32; j += 8) {
        const int t = t0 + j;
        const float s = g_lnsum[(size_t)b * TT + t];
        const float q = g_lnsq[(size_t)b * TT + t];
        const float mu = s * (1.0f / CC);
        const float rstd = rsqrtf(q * (1.0f / CC) - mu * mu + LN_EPS);
        const float v = __half2float(yb[(size_t)t * CC + c0 + tx]);
        tile[j][tx] = (v - mu) * rstd * gm + bt;
    }
    __syncthreads();
    float* ob = out + (size_t)b * CC * TT;
    for (int j = ty; j < 32; j += 8)
        ob[(size_t)(c0 + j) * TT + t0 + tx] = tile[tx][j];
}

// ===========================================================================
extern "C" void kernel_launch(void* const* d_in, const int* in_sizes, int n_in,
                              void* d_out, int out_size)
{
    const float* x     = (const float*)d_in[0];
    const float* wqkv  = (const float*)d_in[1];
    const float* wfc   = (const float*)d_in[2];
    const float* gamma = (const float*)d_in[3];
    const float* beta  = (const float*)d_in[4];
    float* out = (float*)d_out;

    __half* y;
    cudaGetSymbolAddress((void**)&y, g_y);
    __nv_bfloat16 *wqkh, *wqkl, *xth, *xtl;
    __half *wvh, *wvl, *wfh, *wfl, *xt16, *ct;
    cudaGetSymbolAddress((void**)&wqkh, g_wqk_hi);
    cudaGetSymbolAddress((void**)&wqkl, g_wqk_lo);
    cudaGetSymbolAddress((void**)&wvh, g_wv_hi);
    cudaGetSymbolAddress((void**)&wvl, g_wv_lo);
    cudaGetSymbolAddress((void**)&wfh, g_wfc_hi);
    cudaGetSymbolAddress((void**)&wfl, g_wfc_lo);
    cudaGetSymbolAddress((void**)&xth, g_xT_hi);
    cudaGetSymbolAddress((void**)&xtl, g_xT_lo);
    cudaGetSymbolAddress((void**)&xt16, g_xT_h16);
    cudaGetSymbolAddress((void**)&ct, g_cT);

    cudaFuncSetAttribute((const void*)qkv_fused, cudaFuncAttributeMaxDynamicSharedMemorySize, GEMM_SMEM0);
    cudaFuncSetAttribute((const void*)proj_gemm, cudaFuncAttributeMaxDynamicSharedMemorySize, GEMM_SMEM3);
    cudaFuncSetAttribute((const void*)attn_mma, cudaFuncAttributeMaxDynamicSharedMemorySize, ATTN_SMEM);

    // 0) fused prologue
    prologue_kernel<<<dim3(TT / 32 + CONVX, CC / 32, BB), dim3(32, 8)>>>(
        x, wqkv, wfc);

    // 1) merged QK (bf16 3-term) + transposed V (fp16 asym) projections
    qkv_fused<<<dim3(TT / GM_NT, 3 * CC / GM_MT, BB), 256, GEMM_SMEM0>>>(
        (const uint16_t*)wqkh, (const uint16_t*)wqkl,
        (const uint16_t*)xth, (const uint16_t*)xtl,
        (const uint16_t*)xt16, (const uint16_t*)wvh, (const uint16_t*)wvl);

    // 2) flash attention (ones-row l) -> g_cT
    attn_mma<<<dim3(TT / 128, HH, BB), 256, ATTN_SMEM>>>();

    // 3) y^T = ct @ wfc^T + x^T (fp16, LN row stats fused)
    proj_gemm<<<dim3(CC / GM_NT, TT / GM_MT, BB), 256, GEMM_SMEM3>>>(
        (const uint16_t*)ct, (const uint16_t*)wfh, (const uint16_t*)wfl,
        y, (long)TT * CC);

    // 4) LayerNorm normalize + transpose -> out [c][t]
    ln_kernel<<<dim3(TT / 32, CC / 32, BB), dim3(32, 8)>>>(gamma, beta, out);
}